// round 2
// baseline (speedup 1.0000x reference)
#include <cuda_runtime.h>

#define BATCH 2
#define SEQ   2048
#define EMB   1024
#define HEADS 16
#define DKH   64
#define NEGV  (-1.0e9f)
#define SCALE 0.125f

// Scratch (64 MB total) — __device__ globals per allocation rules.
__device__ float g_q [BATCH*SEQ*EMB];
__device__ float g_k [BATCH*SEQ*EMB];
__device__ float g_v [BATCH*SEQ*EMB];
__device__ float g_ao[BATCH*SEQ*EMB];
__device__ int   g_mask_is_i32;

// ---------------------------------------------------------------------------
// Mask representation detection: if the bool mask was materialized as int32
// (values 0/1), every byte at offset % 4 != 0 is zero. With 1-byte bools of
// random 0/1, 3072 such bytes being all zero has probability ~2^-3072.
// ---------------------------------------------------------------------------
__global__ void mha_detect_mask_kernel(const unsigned char* __restrict__ m)
{
    if (threadIdx.x == 0 && blockIdx.x == 0) {
        int s = 0;
        for (int i = 0; i < 4096; i++)
            if ((i & 3) != 0) s += m[i];
        g_mask_is_i32 = (s == 0) ? 1 : 0;
    }
}

// ---------------------------------------------------------------------------
// SGEMM: C[M,N] = A[M,K] @ W[K,N], fp32, 128x128x16 tiles, 256 threads,
// 8x8 per thread in split 4+4 fragment layout (conflict-free smem reads).
// ---------------------------------------------------------------------------
#define GBM 128
#define GBN 128
#define GBK 16

__global__ __launch_bounds__(256)
void mha_sgemm_kernel(const float* __restrict__ A, const float* __restrict__ W,
                      float* __restrict__ C, int M, int N, int K)
{
    __shared__ float As[GBK][GBM + 4];   // A tile stored transposed [k][m]
    __shared__ float Bs[GBK][GBN + 4];   // B tile natural [k][n]

    const int tid = threadIdx.x;
    const int tx  = tid & 15;            // 0..15 -> n fragment
    const int ty  = tid >> 4;            // 0..15 -> m fragment
    const int m0  = blockIdx.y * GBM;
    const int n0  = blockIdx.x * GBN;

    float acc[8][8];
    #pragma unroll
    for (int i = 0; i < 8; i++)
        #pragma unroll
        for (int j = 0; j < 8; j++) acc[i][j] = 0.0f;

    float4 pa[2], pb[2];

    // ---- prologue: load tile 0 into smem ----
    {
        const int k0 = 0;
        #pragma unroll
        for (int p = 0; p < 2; p++) {
            int f  = tid + p * 256;                 // 0..511 float4 slots
            int am = f >> 2, ak = (f & 3) << 2;     // A: [128m][16k]
            pa[p] = *(const float4*)(A + (size_t)(m0 + am) * K + k0 + ak);
            int br = f >> 5, bc = (f & 31) << 2;    // B: [16k][128n]
            pb[p] = *(const float4*)(W + (size_t)(k0 + br) * N + n0 + bc);
        }
        #pragma unroll
        for (int p = 0; p < 2; p++) {
            int f  = tid + p * 256;
            int am = f >> 2, ak = (f & 3) << 2;
            As[ak + 0][am] = pa[p].x;
            As[ak + 1][am] = pa[p].y;
            As[ak + 2][am] = pa[p].z;
            As[ak + 3][am] = pa[p].w;
            int br = f >> 5, bc = (f & 31) << 2;
            *(float4*)&Bs[br][bc] = pb[p];
        }
    }
    __syncthreads();

    const int ntiles = K / GBK;
    for (int t = 0; t < ntiles; t++) {
        // register prefetch of next tile
        if (t + 1 < ntiles) {
            const int k0 = (t + 1) * GBK;
            #pragma unroll
            for (int p = 0; p < 2; p++) {
                int f  = tid + p * 256;
                int am = f >> 2, ak = (f & 3) << 2;
                pa[p] = *(const float4*)(A + (size_t)(m0 + am) * K + k0 + ak);
                int br = f >> 5, bc = (f & 31) << 2;
                pb[p] = *(const float4*)(W + (size_t)(k0 + br) * N + n0 + bc);
            }
        }
        // compute current tile
        #pragma unroll
        for (int kk = 0; kk < GBK; kk++) {
            float a[8], b[8];
            *(float4*)&a[0] = *(const float4*)&As[kk][ty * 4];
            *(float4*)&a[4] = *(const float4*)&As[kk][64 + ty * 4];
            *(float4*)&b[0] = *(const float4*)&Bs[kk][tx * 4];
            *(float4*)&b[4] = *(const float4*)&Bs[kk][64 + tx * 4];
            #pragma unroll
            for (int i = 0; i < 8; i++)
                #pragma unroll
                for (int j = 0; j < 8; j++)
                    acc[i][j] = fmaf(a[i], b[j], acc[i][j]);
        }
        __syncthreads();
        if (t + 1 < ntiles) {
            #pragma unroll
            for (int p = 0; p < 2; p++) {
                int f  = tid + p * 256;
                int am = f >> 2, ak = (f & 3) << 2;
                As[ak + 0][am] = pa[p].x;
                As[ak + 1][am] = pa[p].y;
                As[ak + 2][am] = pa[p].z;
                As[ak + 3][am] = pa[p].w;
                int br = f >> 5, bc = (f & 31) << 2;
                *(float4*)&Bs[br][bc] = pb[p];
            }
            __syncthreads();
        }
    }

    // write back: rows {ty*4+i, 64+ty*4+i}, cols {tx*4.., 64+tx*4..}
    #pragma unroll
    for (int ih = 0; ih < 2; ih++) {
        #pragma unroll
        for (int i = 0; i < 4; i++) {
            const int r = m0 + ih * 64 + ty * 4 + i;
            #pragma unroll
            for (int jh = 0; jh < 2; jh++) {
                float4 v;
                v.x = acc[ih * 4 + i][jh * 4 + 0];
                v.y = acc[ih * 4 + i][jh * 4 + 1];
                v.z = acc[ih * 4 + i][jh * 4 + 2];
                v.w = acc[ih * 4 + i][jh * 4 + 3];
                *(float4*)(C + (size_t)r * N + n0 + jh * 64 + tx * 4) = v;
            }
        }
    }
}

// ---------------------------------------------------------------------------
// Flash attention, fp32. One CTA = 64 query rows of one (b,h).
// Loops over 32 key tiles of 64. Online softmax, stats in registers.
// smem: Qt (transposed, swizzled) + KP (K transposed/swizzled, reused for P
// transposed/swizzled) + Vs (natural) = exactly 48 KB.
// Thread map: ty=tid/16 owns q rows 4ty..4ty+3; tx=tid%16 owns cols 4tx..4tx+3
// (k-cols in phase 1, dk-cols in phase 2).
// ---------------------------------------------------------------------------
__global__ __launch_bounds__(256)
void mha_attn_kernel(const float* __restrict__ gq, const float* __restrict__ gk,
                     const float* __restrict__ gv,
                     const unsigned char* __restrict__ mask,
                     float* __restrict__ out)
{
    __shared__ float Qt[64 * 64];   // [d][q], xor-swizzled cols
    __shared__ float KP[64 * 64];   // Kt [d][k] then Pt [k][q], xor-swizzled
    __shared__ float Vs[64 * 64];   // [k][d], natural

    const int tid = threadIdx.x;
    const int tx  = tid & 15;
    const int ty  = tid >> 4;
    const int q0  = blockIdx.x * 64;
    const int bh  = blockIdx.y;
    const int b   = bh / HEADS;
    const int h   = bh % HEADS;
    const int mask_i32 = g_mask_is_i32;

    const size_t base_q  = ((size_t)b * SEQ + q0) * EMB + h * DKH;
    const size_t base_kv = ((size_t)b * SEQ) * EMB + h * DKH;

    // ---- load Q tile transposed+swizzled: element (q,d) at row d,
    //      col ((q>>2)^(d&15))*4 + (q&3) ----
    #pragma unroll
    for (int p = 0; p < 4; p++) {
        int f  = tid + p * 256;
        int qq = f >> 4;            // 0..63
        int d4 = f & 15;
        float4 v = *(const float4*)(gq + base_q + (size_t)qq * EMB + d4 * 4);
        int qg = qq >> 2, qr = qq & 3;
        { int r = 4 * d4 + 0; Qt[r * 64 + (((qg ^ (r & 15)) << 2) | qr)] = v.x; }
        { int r = 4 * d4 + 1; Qt[r * 64 + (((qg ^ (r & 15)) << 2) | qr)] = v.y; }
        { int r = 4 * d4 + 2; Qt[r * 64 + (((qg ^ (r & 15)) << 2) | qr)] = v.z; }
        { int r = 4 * d4 + 3; Qt[r * 64 + (((qg ^ (r & 15)) << 2) | qr)] = v.w; }
    }

    float o[4][4];
    #pragma unroll
    for (int i = 0; i < 4; i++)
        #pragma unroll
        for (int j = 0; j < 4; j++) o[i][j] = 0.0f;

    float mrow[4], lrow[4];
    #pragma unroll
    for (int i = 0; i < 4; i++) { mrow[i] = __int_as_float(0xff800000); lrow[i] = 0.0f; }

    for (int kt = 0; kt < SEQ / 64; kt++) {
        const int k0 = kt * 64;
        __syncthreads();   // (A) prev PV done (and Qt ready on first iter)

        // ---- load K (transposed+swizzled) and V (natural) tiles ----
        float4 kvr[4], vvr[4];
        #pragma unroll
        for (int p = 0; p < 4; p++) {
            int f  = tid + p * 256;
            int kk = f >> 4;
            int d4 = f & 15;
            const size_t go = base_kv + (size_t)(k0 + kk) * EMB + d4 * 4;
            kvr[p] = *(const float4*)(gk + go);
            vvr[p] = *(const float4*)(gv + go);
        }
        #pragma unroll
        for (int p = 0; p < 4; p++) {
            int f  = tid + p * 256;
            int kk = f >> 4;
            int d4 = f & 15;
            *(float4*)&Vs[kk * 64 + d4 * 4] = vvr[p];
            int kg = kk >> 2, kr = kk & 3;
            { int r = 4 * d4 + 0; KP[r * 64 + (((kg ^ (r & 15)) << 2) | kr)] = kvr[p].x; }
            { int r = 4 * d4 + 1; KP[r * 64 + (((kg ^ (r & 15)) << 2) | kr)] = kvr[p].y; }
            { int r = 4 * d4 + 2; KP[r * 64 + (((kg ^ (r & 15)) << 2) | kr)] = kvr[p].z; }
            { int r = 4 * d4 + 3; KP[r * 64 + (((kg ^ (r & 15)) << 2) | kr)] = kvr[p].w; }
        }

        // ---- prefetch mask values (overlaps with compute below) ----
        // Element (q,k) of a [B,S,S] array; representation per g_mask_is_i32.
        unsigned char mkv[4][4];
        if (mask_i32) {
            const int* mi = (const int*)mask;
            const size_t rowb = ((size_t)b * SEQ + q0) * SEQ + k0;
            #pragma unroll
            for (int i = 0; i < 4; i++) {
                int4 w = *(const int4*)(mi + rowb + (size_t)(4 * ty + i) * SEQ + 4 * tx);
                mkv[i][0] = (unsigned char)w.x;
                mkv[i][1] = (unsigned char)w.y;
                mkv[i][2] = (unsigned char)w.z;
                mkv[i][3] = (unsigned char)w.w;
            }
        } else {
            const unsigned char* mb = mask + ((size_t)b * SEQ + q0) * SEQ + k0;
            #pragma unroll
            for (int i = 0; i < 4; i++) {
                uchar4 w = *(const uchar4*)(mb + (size_t)(4 * ty + i) * SEQ + 4 * tx);
                mkv[i][0] = w.x; mkv[i][1] = w.y; mkv[i][2] = w.z; mkv[i][3] = w.w;
            }
        }

        __syncthreads();   // (B) tiles in smem

        // ---- S = Q K^T (thread: q=4ty+i, k=4tx+j) ----
        float s[4][4];
        #pragma unroll
        for (int i = 0; i < 4; i++)
            #pragma unroll
            for (int j = 0; j < 4; j++) s[i][j] = 0.0f;

        #pragma unroll 16
        for (int d = 0; d < 64; d++) {
            const float4 qv = *(const float4*)&Qt[d * 64 + ((ty ^ (d & 15)) << 2)];
            const float4 kv = *(const float4*)&KP[d * 64 + ((tx ^ (d & 15)) << 2)];
            const float qa[4] = {qv.x, qv.y, qv.z, qv.w};
            const float ka[4] = {kv.x, kv.y, kv.z, kv.w};
            #pragma unroll
            for (int i = 0; i < 4; i++)
                #pragma unroll
                for (int j = 0; j < 4; j++)
                    s[i][j] = fmaf(qa[i], ka[j], s[i][j]);
        }

        // ---- scale + mask ----
        #pragma unroll
        for (int i = 0; i < 4; i++) {
            #pragma unroll
            for (int j = 0; j < 4; j++)
                s[i][j] = mkv[i][j] ? NEGV : s[i][j] * SCALE;
        }

        // ---- online softmax stats (per q row, replicated across 16 lanes) ----
        float alpha[4];
        #pragma unroll
        for (int i = 0; i < 4; i++) {
            float rmax = fmaxf(fmaxf(s[i][0], s[i][1]), fmaxf(s[i][2], s[i][3]));
            #pragma unroll
            for (int off = 1; off < 16; off <<= 1)
                rmax = fmaxf(rmax, __shfl_xor_sync(0xffffffffu, rmax, off));
            const float mn = fmaxf(mrow[i], rmax);
            alpha[i] = __expf(mrow[i] - mn);
            float rs = 0.0f;
            #pragma unroll
            for (int j = 0; j < 4; j++) {
                const float p = __expf(s[i][j] - mn);
                s[i][j] = p;
                rs += p;
            }
            #pragma unroll
            for (int off = 1; off < 16; off <<= 1)
                rs += __shfl_xor_sync(0xffffffffu, rs, off);
            lrow[i] = lrow[i] * alpha[i] + rs;
            mrow[i] = mn;
        }
        // rescale accumulator
        #pragma unroll
        for (int i = 0; i < 4; i++)
            #pragma unroll
            for (int j = 0; j < 4; j++) o[i][j] *= alpha[i];

        __syncthreads();   // (C) all Kt reads done before P overwrites KP

        // ---- store P transposed+swizzled: element (k,q) at row k,
        //      col ((q>>2)^(k&15))*4 + (q&3) ----
        #pragma unroll
        for (int i = 0; i < 4; i++)
            #pragma unroll
            for (int j = 0; j < 4; j++) {
                const int kcol = 4 * tx + j;
                KP[kcol * 64 + (((ty ^ (kcol & 15)) << 2) | i)] = s[i][j];
            }

        __syncthreads();   // (D) P visible

        // ---- O += P @ V (thread: q=4ty+i, d=4tx+j) ----
        #pragma unroll 16
        for (int k = 0; k < 64; k++) {
            const float4 pv = *(const float4*)&KP[k * 64 + ((ty ^ (k & 15)) << 2)];
            const float4 vv = *(const float4*)&Vs[k * 64 + tx * 4];
            const float pa[4] = {pv.x, pv.y, pv.z, pv.w};
            const float va[4] = {vv.x, vv.y, vv.z, vv.w};
            #pragma unroll
            for (int i = 0; i < 4; i++)
                #pragma unroll
                for (int j = 0; j < 4; j++)
                    o[i][j] = fmaf(pa[i], va[j], o[i][j]);
        }
    }

    // ---- normalize and write [B,S,E] so Wo GEMM consumes directly ----
    #pragma unroll
    for (int i = 0; i < 4; i++) {
        const float inv = 1.0f / lrow[i];
        float4 r;
        r.x = o[i][0] * inv;
        r.y = o[i][1] * inv;
        r.z = o[i][2] * inv;
        r.w = o[i][3] * inv;
        const size_t row = (size_t)b * SEQ + q0 + 4 * ty + i;
        *(float4*)(out + row * EMB + h * DKH + 4 * tx) = r;
    }
}

// ---------------------------------------------------------------------------
extern "C" void kernel_launch(void* const* d_in, const int* in_sizes, int n_in,
                              void* d_out, int out_size)
{
    (void)in_sizes; (void)n_in; (void)out_size;
    const float*         query  = (const float*)d_in[0];
    const float*         key    = (const float*)d_in[1];
    const float*         value  = (const float*)d_in[2];
    const unsigned char* masked = (const unsigned char*)d_in[3];
    const float*         Wq     = (const float*)d_in[4];
    const float*         Wk     = (const float*)d_in[5];
    const float*         Wv     = (const float*)d_in[6];
    const float*         Wo     = (const float*)d_in[7];
    float*               out    = (float*)d_out;

    float *gq, *gk, *gv, *gao;
    cudaGetSymbolAddress((void**)&gq,  g_q);
    cudaGetSymbolAddress((void**)&gk,  g_k);
    cudaGetSymbolAddress((void**)&gv,  g_v);
    cudaGetSymbolAddress((void**)&gao, g_ao);

    const int M = BATCH * SEQ;                 // 4096
    dim3 gemm_grid(EMB / GBN, M / GBM);        // (8, 32)
    dim3 gemm_blk(256);

    mha_detect_mask_kernel<<<1, 32>>>(masked);

    mha_sgemm_kernel<<<gemm_grid, gemm_blk>>>(query, Wq, gq, M, EMB, EMB);
    mha_sgemm_kernel<<<gemm_grid, gemm_blk>>>(key,   Wk, gk, M, EMB, EMB);
    mha_sgemm_kernel<<<gemm_grid, gemm_blk>>>(value, Wv, gv, M, EMB, EMB);

    dim3 attn_grid(SEQ / 64, BATCH * HEADS);   // (32, 32)
    mha_attn_kernel<<<attn_grid, 256>>>(gq, gk, gv, masked, gao);

    mha_sgemm_kernel<<<gemm_grid, gemm_blk>>>(gao, Wo, out, M, EMB, EMB);
}

// round 4
// speedup vs baseline: 1.4176x; 1.4176x over previous
#include <cuda_runtime.h>
#include <cuda_bf16.h>
#include <cstdint>

#define BATCH 2
#define SEQ   2048
#define EMB   1024
#define HEADS 16
#define DKH   64
#define NEGV  (-1.0e9f)
#define SCALE 0.125f
#define MROWS (BATCH*SEQ)     // 4096

// ---------------------------------------------------------------------------
// Scratch — __device__ globals per allocation rules.
// ---------------------------------------------------------------------------
__device__ float g_q [BATCH*SEQ*EMB];
__device__ float g_k [BATCH*SEQ*EMB];
__device__ float g_v [BATCH*SEQ*EMB];
__device__ float g_ao[BATCH*SEQ*EMB];
__device__ __nv_bfloat16 g_ah [MROWS*EMB];   // activation split hi
__device__ __nv_bfloat16 g_al [MROWS*EMB];   // activation split lo
__device__ __nv_bfloat16 g_wth[EMB*EMB];     // weight^T split hi  [N][K]
__device__ __nv_bfloat16 g_wtl[EMB*EMB];     // weight^T split lo  [N][K]
__device__ int   g_mask_is_i32;

// ---------------------------------------------------------------------------
// PTX helpers: baseline ISA only (compute_100-safe): mma.sync / ldmatrix /
// cp.async. NO tcgen05 (requires compute_100a virtual arch, which the
// harness does not use).
// ---------------------------------------------------------------------------
__device__ __forceinline__ uint32_t smem_u32(const void* p) {
    uint32_t a;
    asm("{ .reg .u64 t; cvta.to.shared.u64 t, %1; cvt.u32.u64 %0, t; }"
        : "=r"(a) : "l"(p));
    return a;
}

#define LDSM4(r, addr) \
    asm volatile("ldmatrix.sync.aligned.m8n8.x4.shared.b16 {%0,%1,%2,%3}, [%4];" \
        : "=r"((r)[0]), "=r"((r)[1]), "=r"((r)[2]), "=r"((r)[3]) : "r"(addr))

#define MMA_BF16(d, a, b) \
    asm volatile("mma.sync.aligned.m16n8k16.row.col.f32.bf16.bf16.f32 " \
        "{%0,%1,%2,%3}, {%4,%5,%6,%7}, {%8,%9}, {%0,%1,%2,%3};" \
        : "+f"((d)[0]), "+f"((d)[1]), "+f"((d)[2]), "+f"((d)[3]) \
        : "r"((a)[0]), "r"((a)[1]), "r"((a)[2]), "r"((a)[3]), \
          "r"((b)[0]), "r"((b)[1]))

#define CP_ASYNC16(sa, gp) \
    asm volatile("{\n\t.reg .u64 gpt;\n\tcvta.to.global.u64 gpt, %1;\n\t" \
        "cp.async.cg.shared.global [%0], [gpt], 16;\n\t}" \
        :: "r"(sa), "l"(gp))
#define CP_COMMIT()  asm volatile("cp.async.commit_group;" ::: "memory")
#define CP_WAIT0()   asm volatile("cp.async.wait_group 0;" ::: "memory")

// ---------------------------------------------------------------------------
// Mask representation detection (int32-bool vs uint8-bool).
// ---------------------------------------------------------------------------
__global__ void mha_detect_mask_kernel(const unsigned char* __restrict__ m)
{
    if (threadIdx.x == 0 && blockIdx.x == 0) {
        int s = 0;
        for (int i = 0; i < 4096; i++)
            if ((i & 3) != 0) s += m[i];
        g_mask_is_i32 = (s == 0) ? 1 : 0;
    }
}

// ---------------------------------------------------------------------------
// fp32 -> (bf16 hi, bf16 lo) split, elementwise, float4-vectorized.
// ---------------------------------------------------------------------------
__global__ __launch_bounds__(256)
void mha_split_kernel(const float4* __restrict__ x,
                      __nv_bfloat162* __restrict__ hi,
                      __nv_bfloat162* __restrict__ lo, int n4)
{
    int i = blockIdx.x * 256 + threadIdx.x;
    if (i >= n4) return;
    float4 v = x[i];
    __nv_bfloat16 hx = __float2bfloat16(v.x);
    __nv_bfloat16 hy = __float2bfloat16(v.y);
    __nv_bfloat16 hz = __float2bfloat16(v.z);
    __nv_bfloat16 hw = __float2bfloat16(v.w);
    __nv_bfloat16 lx = __float2bfloat16(v.x - __bfloat162float(hx));
    __nv_bfloat16 ly = __float2bfloat16(v.y - __bfloat162float(hy));
    __nv_bfloat16 lz = __float2bfloat16(v.z - __bfloat162float(hz));
    __nv_bfloat16 lw = __float2bfloat16(v.w - __bfloat162float(hw));
    hi[2 * i + 0] = __nv_bfloat162(hx, hy);
    hi[2 * i + 1] = __nv_bfloat162(hz, hw);
    lo[2 * i + 0] = __nv_bfloat162(lx, ly);
    lo[2 * i + 1] = __nv_bfloat162(lz, lw);
}

// ---------------------------------------------------------------------------
// Weight transpose + split: W[K,N] fp32 -> Wt hi/lo [N,K] bf16.
// ---------------------------------------------------------------------------
__global__ __launch_bounds__(256)
void mha_wsplit_kernel(const float* __restrict__ W,
                       __nv_bfloat16* __restrict__ th,
                       __nv_bfloat16* __restrict__ tl)
{
    __shared__ float t[32][33];
    const int n  = blockIdx.x * 32 + threadIdx.x;
    const int k0 = blockIdx.y * 32;
    #pragma unroll
    for (int r = 0; r < 32; r += 8)
        t[threadIdx.y + r][threadIdx.x] = W[(size_t)(k0 + threadIdx.y + r) * EMB + n];
    __syncthreads();
    #pragma unroll
    for (int r = 0; r < 32; r += 8) {
        float v = t[threadIdx.x][threadIdx.y + r];
        int on = blockIdx.x * 32 + threadIdx.y + r;
        int ok = k0 + threadIdx.x;
        __nv_bfloat16 h = __float2bfloat16(v);
        th[(size_t)on * EMB + ok] = h;
        tl[(size_t)on * EMB + ok] = __float2bfloat16(v - __bfloat162float(h));
    }
}

// ---------------------------------------------------------------------------
// Tensor-core GEMM via mma.sync bf16 split:
//   C[MROWS,EMB] = A @ W  with  A@W ~= Ah@Bh + Ah@Bl + Al@Bh  (fp32 accum).
// A hi/lo: [M,K] bf16 row-major.  B hi/lo: [N,K] bf16 row-major (weightT).
// CTA tile 128x128, K-chunk 32, double-buffered cp.async pipeline.
// 8 warps = 2(m) x 4(n); warp tile 64x32 -> 4x4 m16n8 accumulators.
// smem row stride 80B: rows 0..7 hit 8 distinct 16B bank columns
// (r*80 mod 128 all distinct) -> conflict-free ldmatrix without XOR swizzle.
// ---------------------------------------------------------------------------
#define KC        32
#define ROWB      80
#define TILE_SB   (128 * ROWB)        // 10240
#define STAGE_SB  (4 * TILE_SB)       // 40960: Ah, Al, Bh, Bl
#define GSM_TOTAL (2 * STAGE_SB)      // 81920

__device__ __forceinline__ void cp_tile(const __nv_bfloat16* __restrict__ g,
                                        int row0, int kb, uint32_t sdst, int tid)
{
    #pragma unroll
    for (int p = 0; p < 2; p++) {
        int f = tid + p * 256;                 // 0..511 16B-chunks
        int r = f >> 2, ch = f & 3;
        const __nv_bfloat16* gp = g + (size_t)(row0 + r) * EMB + kb + ch * 8;
        uint32_t sa = sdst + r * ROWB + ch * 16;
        CP_ASYNC16(sa, gp);
    }
}

__global__ __launch_bounds__(256)
void mha_mma_gemm(const __nv_bfloat16* __restrict__ Ah,
                  const __nv_bfloat16* __restrict__ Al,
                  const __nv_bfloat16* __restrict__ Bh,
                  const __nv_bfloat16* __restrict__ Bl,
                  float* __restrict__ C)
{
    extern __shared__ char smem[];
    const uint32_t sb = smem_u32(smem);
    const int tid  = threadIdx.x;
    const int wid  = tid >> 5;
    const int lane = tid & 31;
    const int wm   = wid & 1;           // 0..1
    const int wn   = wid >> 1;          // 0..3
    const int m0   = blockIdx.y * 128;
    const int n0   = blockIdx.x * 128;

    float acc[4][4][4];
    #pragma unroll
    for (int mt = 0; mt < 4; mt++)
        #pragma unroll
        for (int nt = 0; nt < 4; nt++)
            #pragma unroll
            for (int e = 0; e < 4; e++) acc[mt][nt][e] = 0.0f;

    // prologue: stage 0
    cp_tile(Ah, m0, 0, sb + 0 * TILE_SB, tid);
    cp_tile(Al, m0, 0, sb + 1 * TILE_SB, tid);
    cp_tile(Bh, n0, 0, sb + 2 * TILE_SB, tid);
    cp_tile(Bl, n0, 0, sb + 3 * TILE_SB, tid);
    CP_COMMIT();

    const int NS = EMB / KC;            // 32
    for (int s = 0; s < NS; s++) {
        CP_WAIT0();
        __syncthreads();

        if (s + 1 < NS) {
            const uint32_t nb = sb + ((s + 1) & 1) * STAGE_SB;
            const int kb = (s + 1) * KC;
            cp_tile(Ah, m0, kb, nb + 0 * TILE_SB, tid);
            cp_tile(Al, m0, kb, nb + 1 * TILE_SB, tid);
            cp_tile(Bh, n0, kb, nb + 2 * TILE_SB, tid);
            cp_tile(Bl, n0, kb, nb + 3 * TILE_SB, tid);
            CP_COMMIT();
        }

        const uint32_t abase = sb + (s & 1) * STAGE_SB;          // Ah
        const uint32_t bbase = abase + 2 * TILE_SB;              // Bh

        #pragma unroll
        for (int ks = 0; ks < 2; ks++) {                         // two k16 steps
            uint32_t ah[4][4], al[4][4];
            #pragma unroll
            for (int mt = 0; mt < 4; mt++) {
                const int row = wm * 64 + mt * 16 + (lane & 15);
                const int ch  = ks * 2 + (lane >> 4);
                const uint32_t ad = abase + row * ROWB + ch * 16;
                LDSM4(ah[mt], ad);
                LDSM4(al[mt], ad + TILE_SB);
            }
            uint32_t bh[4][2], bl[4][2];
            #pragma unroll
            for (int g = 0; g < 2; g++) {                        // two n16 groups
                const int row = wn * 32 + g * 16 + (lane & 7) + ((lane >> 4) << 3);
                const int ch  = ks * 2 + ((lane >> 3) & 1);
                const uint32_t bd = bbase + row * ROWB + ch * 16;
                uint32_t t[4];
                LDSM4(t, bd);
                bh[2*g][0] = t[0]; bh[2*g][1] = t[1];
                bh[2*g+1][0] = t[2]; bh[2*g+1][1] = t[3];
                LDSM4(t, bd + TILE_SB);
                bl[2*g][0] = t[0]; bl[2*g][1] = t[1];
                bl[2*g+1][0] = t[2]; bl[2*g+1][1] = t[3];
            }
            #pragma unroll
            for (int mt = 0; mt < 4; mt++)
                #pragma unroll
                for (int nt = 0; nt < 4; nt++) {
                    MMA_BF16(acc[mt][nt], ah[mt], bh[nt]);
                    MMA_BF16(acc[mt][nt], ah[mt], bl[nt]);
                    MMA_BF16(acc[mt][nt], al[mt], bh[nt]);
                }
        }
        __syncthreads();
    }

    // epilogue: fp32 accumulators -> C
    #pragma unroll
    for (int mt = 0; mt < 4; mt++) {
        const int r0 = m0 + wm * 64 + mt * 16 + (lane >> 2);
        #pragma unroll
        for (int nt = 0; nt < 4; nt++) {
            const int c0 = n0 + wn * 32 + nt * 8 + 2 * (lane & 3);
            *(float2*)(C + (size_t)r0 * EMB + c0)       = make_float2(acc[mt][nt][0], acc[mt][nt][1]);
            *(float2*)(C + (size_t)(r0 + 8) * EMB + c0) = make_float2(acc[mt][nt][2], acc[mt][nt][3]);
        }
    }
}

// ---------------------------------------------------------------------------
// Flash attention, fp32 SIMT (unchanged verified path).
// ---------------------------------------------------------------------------
__global__ __launch_bounds__(256)
void mha_attn_kernel(const float* __restrict__ gq, const float* __restrict__ gk,
                     const float* __restrict__ gv,
                     const unsigned char* __restrict__ mask,
                     float* __restrict__ out)
{
    __shared__ float Qt[64 * 64];
    __shared__ float KP[64 * 64];
    __shared__ float Vs[64 * 64];

    const int tid = threadIdx.x;
    const int tx  = tid & 15;
    const int ty  = tid >> 4;
    const int q0  = blockIdx.x * 64;
    const int bh  = blockIdx.y;
    const int b   = bh / HEADS;
    const int h   = bh % HEADS;
    const int mask_i32 = g_mask_is_i32;

    const size_t base_q  = ((size_t)b * SEQ + q0) * EMB + h * DKH;
    const size_t base_kv = ((size_t)b * SEQ) * EMB + h * DKH;

    #pragma unroll
    for (int p = 0; p < 4; p++) {
        int f  = tid + p * 256;
        int qq = f >> 4;
        int d4 = f & 15;
        float4 v = *(const float4*)(gq + base_q + (size_t)qq * EMB + d4 * 4);
        int qg = qq >> 2, qr = qq & 3;
        { int r = 4 * d4 + 0; Qt[r * 64 + (((qg ^ (r & 15)) << 2) | qr)] = v.x; }
        { int r = 4 * d4 + 1; Qt[r * 64 + (((qg ^ (r & 15)) << 2) | qr)] = v.y; }
        { int r = 4 * d4 + 2; Qt[r * 64 + (((qg ^ (r & 15)) << 2) | qr)] = v.z; }
        { int r = 4 * d4 + 3; Qt[r * 64 + (((qg ^ (r & 15)) << 2) | qr)] = v.w; }
    }

    float o[4][4];
    #pragma unroll
    for (int i = 0; i < 4; i++)
        #pragma unroll
        for (int j = 0; j < 4; j++) o[i][j] = 0.0f;

    float mrow[4], lrow[4];
    #pragma unroll
    for (int i = 0; i < 4; i++) { mrow[i] = __int_as_float(0xff800000); lrow[i] = 0.0f; }

    for (int kt = 0; kt < SEQ / 64; kt++) {
        const int k0 = kt * 64;
        __syncthreads();

        float4 kvr[4], vvr[4];
        #pragma unroll
        for (int p = 0; p < 4; p++) {
            int f  = tid + p * 256;
            int kk = f >> 4;
            int d4 = f & 15;
            const size_t go = base_kv + (size_t)(k0 + kk) * EMB + d4 * 4;
            kvr[p] = *(const float4*)(gk + go);
            vvr[p] = *(const float4*)(gv + go);
        }
        #pragma unroll
        for (int p = 0; p < 4; p++) {
            int f  = tid + p * 256;
            int kk = f >> 4;
            int d4 = f & 15;
            *(float4*)&Vs[kk * 64 + d4 * 4] = vvr[p];
            int kg = kk >> 2, kr = kk & 3;
            { int r = 4 * d4 + 0; KP[r * 64 + (((kg ^ (r & 15)) << 2) | kr)] = kvr[p].x; }
            { int r = 4 * d4 + 1; KP[r * 64 + (((kg ^ (r & 15)) << 2) | kr)] = kvr[p].y; }
            { int r = 4 * d4 + 2; KP[r * 64 + (((kg ^ (r & 15)) << 2) | kr)] = kvr[p].z; }
            { int r = 4 * d4 + 3; KP[r * 64 + (((kg ^ (r & 15)) << 2) | kr)] = kvr[p].w; }
        }

        unsigned char mkv[4][4];
        if (mask_i32) {
            const int* mi = (const int*)mask;
            const size_t rowb = ((size_t)b * SEQ + q0) * SEQ + k0;
            #pragma unroll
            for (int i = 0; i < 4; i++) {
                int4 w = *(const int4*)(mi + rowb + (size_t)(4 * ty + i) * SEQ + 4 * tx);
                mkv[i][0] = (unsigned char)w.x;
                mkv[i][1] = (unsigned char)w.y;
                mkv[i][2] = (unsigned char)w.z;
                mkv[i][3] = (unsigned char)w.w;
            }
        } else {
            const unsigned char* mb = mask + ((size_t)b * SEQ + q0) * SEQ + k0;
            #pragma unroll
            for (int i = 0; i < 4; i++) {
                uchar4 w = *(const uchar4*)(mb + (size_t)(4 * ty + i) * SEQ + 4 * tx);
                mkv[i][0] = w.x; mkv[i][1] = w.y; mkv[i][2] = w.z; mkv[i][3] = w.w;
            }
        }

        __syncthreads();

        float s[4][4];
        #pragma unroll
        for (int i = 0; i < 4; i++)
            #pragma unroll
            for (int j = 0; j < 4; j++) s[i][j] = 0.0f;

        #pragma unroll 16
        for (int d = 0; d < 64; d++) {
            const float4 qv = *(const float4*)&Qt[d * 64 + ((ty ^ (d & 15)) << 2)];
            const float4 kv = *(const float4*)&KP[d * 64 + ((tx ^ (d & 15)) << 2)];
            const float qa[4] = {qv.x, qv.y, qv.z, qv.w};
            const float ka[4] = {kv.x, kv.y, kv.z, kv.w};
            #pragma unroll
            for (int i = 0; i < 4; i++)
                #pragma unroll
                for (int j = 0; j < 4; j++)
                    s[i][j] = fmaf(qa[i], ka[j], s[i][j]);
        }

        #pragma unroll
        for (int i = 0; i < 4; i++) {
            #pragma unroll
            for (int j = 0; j < 4; j++)
                s[i][j] = mkv[i][j] ? NEGV : s[i][j] * SCALE;
        }

        float alpha[4];
        #pragma unroll
        for (int i = 0; i < 4; i++) {
            float rmax = fmaxf(fmaxf(s[i][0], s[i][1]), fmaxf(s[i][2], s[i][3]));
            #pragma unroll
            for (int off = 1; off < 16; off <<= 1)
                rmax = fmaxf(rmax, __shfl_xor_sync(0xffffffffu, rmax, off));
            const float mn = fmaxf(mrow[i], rmax);
            alpha[i] = __expf(mrow[i] - mn);
            float rs = 0.0f;
            #pragma unroll
            for (int j = 0; j < 4; j++) {
                const float p = __expf(s[i][j] - mn);
                s[i][j] = p;
                rs += p;
            }
            #pragma unroll
            for (int off = 1; off < 16; off <<= 1)
                rs += __shfl_xor_sync(0xffffffffu, rs, off);
            lrow[i] = lrow[i] * alpha[i] + rs;
            mrow[i] = mn;
        }
        #pragma unroll
        for (int i = 0; i < 4; i++)
            #pragma unroll
            for (int j = 0; j < 4; j++) o[i][j] *= alpha[i];

        __syncthreads();

        #pragma unroll
        for (int i = 0; i < 4; i++)
            #pragma unroll
            for (int j = 0; j < 4; j++) {
                const int kcol = 4 * tx + j;
                KP[kcol * 64 + (((ty ^ (kcol & 15)) << 2) | i)] = s[i][j];
            }

        __syncthreads();

        #pragma unroll 16
        for (int k = 0; k < 64; k++) {
            const float4 pv = *(const float4*)&KP[k * 64 + ((ty ^ (k & 15)) << 2)];
            const float4 vv = *(const float4*)&Vs[k * 64 + tx * 4];
            const float pa[4] = {pv.x, pv.y, pv.z, pv.w};
            const float va[4] = {vv.x, vv.y, vv.z, vv.w};
            #pragma unroll
            for (int i = 0; i < 4; i++)
                #pragma unroll
                for (int j = 0; j < 4; j++)
                    o[i][j] = fmaf(pa[i], va[j], o[i][j]);
        }
    }

    #pragma unroll
    for (int i = 0; i < 4; i++) {
        const float inv = 1.0f / lrow[i];
        float4 r;
        r.x = o[i][0] * inv;
        r.y = o[i][1] * inv;
        r.z = o[i][2] * inv;
        r.w = o[i][3] * inv;
        const size_t row = (size_t)b * SEQ + q0 + 4 * ty + i;
        *(float4*)(out + row * EMB + h * DKH + 4 * tx) = r;
    }
}

// ---------------------------------------------------------------------------
extern "C" void kernel_launch(void* const* d_in, const int* in_sizes, int n_in,
                              void* d_out, int out_size)
{
    (void)in_sizes; (void)n_in; (void)out_size;
    const float*         query  = (const float*)d_in[0];
    const float*         key    = (const float*)d_in[1];
    const float*         value  = (const float*)d_in[2];
    const unsigned char* masked = (const unsigned char*)d_in[3];
    const float*         Wq     = (const float*)d_in[4];
    const float*         Wk     = (const float*)d_in[5];
    const float*         Wv     = (const float*)d_in[6];
    const float*         Wo     = (const float*)d_in[7];
    float*               out    = (float*)d_out;

    float *gq, *gk, *gv, *gao;
    __nv_bfloat16 *gah, *gal, *gwth, *gwtl;
    cudaGetSymbolAddress((void**)&gq,   g_q);
    cudaGetSymbolAddress((void**)&gk,   g_k);
    cudaGetSymbolAddress((void**)&gv,   g_v);
    cudaGetSymbolAddress((void**)&gao,  g_ao);
    cudaGetSymbolAddress((void**)&gah,  g_ah);
    cudaGetSymbolAddress((void**)&gal,  g_al);
    cudaGetSymbolAddress((void**)&gwth, g_wth);
    cudaGetSymbolAddress((void**)&gwtl, g_wtl);

    cudaFuncSetAttribute(mha_mma_gemm,
                         cudaFuncAttributeMaxDynamicSharedMemorySize, GSM_TOTAL);

    const int n4 = MROWS * EMB / 4;            // 1048576
    dim3 split_grid((n4 + 255) / 256);
    dim3 w_grid(EMB / 32, EMB / 32), w_blk(32, 8);
    dim3 gemm_grid(EMB / 128, MROWS / 128);    // (8, 32)

    mha_detect_mask_kernel<<<1, 32>>>(masked);

    // Q projection
    mha_wsplit_kernel<<<w_grid, w_blk>>>(Wq, gwth, gwtl);
    mha_split_kernel<<<split_grid, 256>>>((const float4*)query,
                                          (__nv_bfloat162*)gah, (__nv_bfloat162*)gal, n4);
    mha_mma_gemm<<<gemm_grid, 256, GSM_TOTAL>>>(gah, gal, gwth, gwtl, gq);

    // K projection
    mha_wsplit_kernel<<<w_grid, w_blk>>>(Wk, gwth, gwtl);
    mha_split_kernel<<<split_grid, 256>>>((const float4*)key,
                                          (__nv_bfloat162*)gah, (__nv_bfloat162*)gal, n4);
    mha_mma_gemm<<<gemm_grid, 256, GSM_TOTAL>>>(gah, gal, gwth, gwtl, gk);

    // V projection
    mha_wsplit_kernel<<<w_grid, w_blk>>>(Wv, gwth, gwtl);
    mha_split_kernel<<<split_grid, 256>>>((const float4*)value,
                                          (__nv_bfloat162*)gah, (__nv_bfloat162*)gal, n4);
    mha_mma_gemm<<<gemm_grid, 256, GSM_TOTAL>>>(gah, gal, gwth, gwtl, gv);

    // attention
    dim3 attn_grid(SEQ / 64, BATCH * HEADS);
    mha_attn_kernel<<<attn_grid, 256>>>(gq, gk, gv, masked, gao);

    // output projection
    mha_wsplit_kernel<<<w_grid, w_blk>>>(Wo, gwth, gwtl);
    mha_split_kernel<<<split_grid, 256>>>((const float4*)gao,
                                          (__nv_bfloat162*)gah, (__nv_bfloat162*)gal, n4);
    mha_mma_gemm<<<gemm_grid, 256, GSM_TOTAL>>>(gah, gal, gwth, gwtl, out);
}

// round 5
// speedup vs baseline: 2.6914x; 1.8986x over previous
#include <cuda_runtime.h>
#include <cuda_bf16.h>
#include <cstdint>

#define BATCH 2
#define SEQ   2048
#define EMB   1024
#define HEADS 16
#define DKH   64
#define NEGV  (-1.0e9f)
#define SCALE 0.125f
#define MROWS (BATCH*SEQ)     // 4096

// ---------------------------------------------------------------------------
// Scratch — __device__ globals per allocation rules.
// ---------------------------------------------------------------------------
__device__ __nv_bfloat16 g_qh [MROWS*EMB];
__device__ __nv_bfloat16 g_ql [MROWS*EMB];
__device__ __nv_bfloat16 g_kh [MROWS*EMB];
__device__ __nv_bfloat16 g_kl [MROWS*EMB];
__device__ __nv_bfloat16 g_vh [MROWS*EMB];
__device__ __nv_bfloat16 g_vl [MROWS*EMB];
__device__ __nv_bfloat16 g_ah [MROWS*EMB];   // GEMM A hi / attention out hi
__device__ __nv_bfloat16 g_al [MROWS*EMB];   // GEMM A lo / attention out lo
__device__ __nv_bfloat16 g_wth[EMB*EMB];     // weight^T split hi  [N][K]
__device__ __nv_bfloat16 g_wtl[EMB*EMB];     // weight^T split lo  [N][K]
__device__ unsigned char g_m8 [BATCH*SEQ*SEQ];
__device__ int   g_mask_is_i32;

// ---------------------------------------------------------------------------
// PTX helpers (compute_100-safe baseline ISA: mma.sync / ldmatrix / cp.async)
// ---------------------------------------------------------------------------
__device__ __forceinline__ uint32_t smem_u32(const void* p) {
    uint32_t a;
    asm("{ .reg .u64 t; cvta.to.shared.u64 t, %1; cvt.u32.u64 %0, t; }"
        : "=r"(a) : "l"(p));
    return a;
}

#define LDSM4(r, addr) \
    asm volatile("ldmatrix.sync.aligned.m8n8.x4.shared.b16 {%0,%1,%2,%3}, [%4];" \
        : "=r"((r)[0]), "=r"((r)[1]), "=r"((r)[2]), "=r"((r)[3]) : "r"(addr))
#define LDSM4T(r, addr) \
    asm volatile("ldmatrix.sync.aligned.m8n8.x4.trans.shared.b16 {%0,%1,%2,%3}, [%4];" \
        : "=r"((r)[0]), "=r"((r)[1]), "=r"((r)[2]), "=r"((r)[3]) : "r"(addr))

#define MMA_BF16(d, a, b) \
    asm volatile("mma.sync.aligned.m16n8k16.row.col.f32.bf16.bf16.f32 " \
        "{%0,%1,%2,%3}, {%4,%5,%6,%7}, {%8,%9}, {%0,%1,%2,%3};" \
        : "+f"((d)[0]), "+f"((d)[1]), "+f"((d)[2]), "+f"((d)[3]) \
        : "r"((a)[0]), "r"((a)[1]), "r"((a)[2]), "r"((a)[3]), \
          "r"((b)[0]), "r"((b)[1]))

#define CP_ASYNC16(sa, gp) \
    asm volatile("{\n\t.reg .u64 gpt;\n\tcvta.to.global.u64 gpt, %1;\n\t" \
        "cp.async.cg.shared.global [%0], [gpt], 16;\n\t}" \
        :: "r"(sa), "l"(gp))
#define CP_COMMIT()  asm volatile("cp.async.commit_group;" ::: "memory")
#define CP_WAIT0()   asm volatile("cp.async.wait_group 0;" ::: "memory")
#define CP_WAIT1()   asm volatile("cp.async.wait_group 1;" ::: "memory")

// fp32 pair -> packed bf16x2 hi and lo (2-term split)
__device__ __forceinline__ void split2(float x, float y, uint32_t& hi, uint32_t& lo)
{
    __nv_bfloat16 hx = __float2bfloat16(x), hy = __float2bfloat16(y);
    __nv_bfloat16 lx = __float2bfloat16(x - __bfloat162float(hx));
    __nv_bfloat16 ly = __float2bfloat16(y - __bfloat162float(hy));
    __nv_bfloat162 H(hx, hy), L(lx, ly);
    hi = *reinterpret_cast<uint32_t*>(&H);
    lo = *reinterpret_cast<uint32_t*>(&L);
}

// ---------------------------------------------------------------------------
// Mask representation detection (int32-bool vs uint8-bool).
// ---------------------------------------------------------------------------
__global__ void mha_detect_mask_kernel(const unsigned char* __restrict__ m)
{
    if (threadIdx.x == 0 && blockIdx.x == 0) {
        int s = 0;
        for (int i = 0; i < 4096; i++)
            if ((i & 3) != 0) s += m[i];
        g_mask_is_i32 = (s == 0) ? 1 : 0;
    }
}

// mask -> uint8 (avoids 16x-redundant int32 reads in attention)
__global__ __launch_bounds__(256)
void mha_mask8_kernel(const unsigned char* __restrict__ m,
                      unsigned char* __restrict__ o, int n4)
{
    int i = blockIdx.x * 256 + threadIdx.x;
    if (i >= n4) return;
    if (g_mask_is_i32) {
        int4 w = ((const int4*)m)[i];
        uchar4 u;
        u.x = (unsigned char)w.x; u.y = (unsigned char)w.y;
        u.z = (unsigned char)w.z; u.w = (unsigned char)w.w;
        ((uchar4*)o)[i] = u;
    } else {
        ((uchar4*)o)[i] = ((const uchar4*)m)[i];
    }
}

// ---------------------------------------------------------------------------
// fp32 -> (bf16 hi, bf16 lo) split, elementwise.
// ---------------------------------------------------------------------------
__global__ __launch_bounds__(256)
void mha_split_kernel(const float4* __restrict__ x,
                      __nv_bfloat162* __restrict__ hi,
                      __nv_bfloat162* __restrict__ lo, int n4)
{
    int i = blockIdx.x * 256 + threadIdx.x;
    if (i >= n4) return;
    float4 v = x[i];
    uint32_t h0, l0, h1, l1;
    split2(v.x, v.y, h0, l0);
    split2(v.z, v.w, h1, l1);
    ((uint32_t*)hi)[2 * i + 0] = h0;
    ((uint32_t*)hi)[2 * i + 1] = h1;
    ((uint32_t*)lo)[2 * i + 0] = l0;
    ((uint32_t*)lo)[2 * i + 1] = l1;
}

// ---------------------------------------------------------------------------
// Weight transpose + split: W[K,N] fp32 -> Wt hi/lo [N,K] bf16.
// ---------------------------------------------------------------------------
__global__ __launch_bounds__(256)
void mha_wsplit_kernel(const float* __restrict__ W,
                       __nv_bfloat16* __restrict__ th,
                       __nv_bfloat16* __restrict__ tl)
{
    __shared__ float t[32][33];
    const int n  = blockIdx.x * 32 + threadIdx.x;
    const int k0 = blockIdx.y * 32;
    #pragma unroll
    for (int r = 0; r < 32; r += 8)
        t[threadIdx.y + r][threadIdx.x] = W[(size_t)(k0 + threadIdx.y + r) * EMB + n];
    __syncthreads();
    #pragma unroll
    for (int r = 0; r < 32; r += 8) {
        float v = t[threadIdx.x][threadIdx.y + r];
        int on = blockIdx.x * 32 + threadIdx.y + r;
        int ok = k0 + threadIdx.x;
        __nv_bfloat16 h = __float2bfloat16(v);
        th[(size_t)on * EMB + ok] = h;
        tl[(size_t)on * EMB + ok] = __float2bfloat16(v - __bfloat162float(h));
    }
}

// ---------------------------------------------------------------------------
// Tensor-core GEMM (mma.sync bf16 3-term split), CTA 128x128, K-chunk 32,
// double-buffered cp.async. Epilogue: if Ch != null, write split bf16 hi/lo
// (for Q/K/V projections); else write fp32 C (final Wo projection).
// ---------------------------------------------------------------------------
#define KC        32
#define ROWB      80
#define TILE_SB   (128 * ROWB)
#define STAGE_SB  (4 * TILE_SB)
#define GSM_TOTAL (2 * STAGE_SB)      // 81920

__device__ __forceinline__ void cp_tile(const __nv_bfloat16* __restrict__ g,
                                        int row0, int kb, uint32_t sdst, int tid)
{
    #pragma unroll
    for (int p = 0; p < 2; p++) {
        int f = tid + p * 256;
        int r = f >> 2, ch = f & 3;
        const __nv_bfloat16* gp = g + (size_t)(row0 + r) * EMB + kb + ch * 8;
        uint32_t sa = sdst + r * ROWB + ch * 16;
        CP_ASYNC16(sa, gp);
    }
}

__global__ __launch_bounds__(256)
void mha_mma_gemm(const __nv_bfloat16* __restrict__ Ah,
                  const __nv_bfloat16* __restrict__ Al,
                  const __nv_bfloat16* __restrict__ Bh,
                  const __nv_bfloat16* __restrict__ Bl,
                  float* __restrict__ C,
                  __nv_bfloat16* __restrict__ Ch,
                  __nv_bfloat16* __restrict__ Cl)
{
    extern __shared__ char smem[];
    const uint32_t sb = smem_u32(smem);
    const int tid  = threadIdx.x;
    const int wid  = tid >> 5;
    const int lane = tid & 31;
    const int wm   = wid & 1;
    const int wn   = wid >> 1;
    const int m0   = blockIdx.y * 128;
    const int n0   = blockIdx.x * 128;

    float acc[4][4][4];
    #pragma unroll
    for (int mt = 0; mt < 4; mt++)
        #pragma unroll
        for (int nt = 0; nt < 4; nt++)
            #pragma unroll
            for (int e = 0; e < 4; e++) acc[mt][nt][e] = 0.0f;

    cp_tile(Ah, m0, 0, sb + 0 * TILE_SB, tid);
    cp_tile(Al, m0, 0, sb + 1 * TILE_SB, tid);
    cp_tile(Bh, n0, 0, sb + 2 * TILE_SB, tid);
    cp_tile(Bl, n0, 0, sb + 3 * TILE_SB, tid);
    CP_COMMIT();

    const int NS = EMB / KC;
    for (int s = 0; s < NS; s++) {
        CP_WAIT0();
        __syncthreads();

        if (s + 1 < NS) {
            const uint32_t nb = sb + ((s + 1) & 1) * STAGE_SB;
            const int kb = (s + 1) * KC;
            cp_tile(Ah, m0, kb, nb + 0 * TILE_SB, tid);
            cp_tile(Al, m0, kb, nb + 1 * TILE_SB, tid);
            cp_tile(Bh, n0, kb, nb + 2 * TILE_SB, tid);
            cp_tile(Bl, n0, kb, nb + 3 * TILE_SB, tid);
            CP_COMMIT();
        }

        const uint32_t abase = sb + (s & 1) * STAGE_SB;
        const uint32_t bbase = abase + 2 * TILE_SB;

        #pragma unroll
        for (int ks = 0; ks < 2; ks++) {
            uint32_t ah[4][4], al[4][4];
            #pragma unroll
            for (int mt = 0; mt < 4; mt++) {
                const int row = wm * 64 + mt * 16 + (lane & 15);
                const int ch  = ks * 2 + (lane >> 4);
                const uint32_t ad = abase + row * ROWB + ch * 16;
                LDSM4(ah[mt], ad);
                LDSM4(al[mt], ad + TILE_SB);
            }
            uint32_t bh[4][2], bl[4][2];
            #pragma unroll
            for (int g = 0; g < 2; g++) {
                const int row = wn * 32 + g * 16 + (lane & 7) + ((lane >> 4) << 3);
                const int ch  = ks * 2 + ((lane >> 3) & 1);
                const uint32_t bd = bbase + row * ROWB + ch * 16;
                uint32_t t[4];
                LDSM4(t, bd);
                bh[2*g][0] = t[0]; bh[2*g][1] = t[1];
                bh[2*g+1][0] = t[2]; bh[2*g+1][1] = t[3];
                LDSM4(t, bd + TILE_SB);
                bl[2*g][0] = t[0]; bl[2*g][1] = t[1];
                bl[2*g+1][0] = t[2]; bl[2*g+1][1] = t[3];
            }
            #pragma unroll
            for (int mt = 0; mt < 4; mt++)
                #pragma unroll
                for (int nt = 0; nt < 4; nt++) {
                    MMA_BF16(acc[mt][nt], ah[mt], bh[nt]);
                    MMA_BF16(acc[mt][nt], ah[mt], bl[nt]);
                    MMA_BF16(acc[mt][nt], al[mt], bh[nt]);
                }
        }
        __syncthreads();
    }

    if (Ch) {
        #pragma unroll
        for (int mt = 0; mt < 4; mt++) {
            const int r0 = m0 + wm * 64 + mt * 16 + (lane >> 2);
            #pragma unroll
            for (int nt = 0; nt < 4; nt++) {
                const int c0 = n0 + wn * 32 + nt * 8 + 2 * (lane & 3);
                uint32_t hu, lu;
                split2(acc[mt][nt][0], acc[mt][nt][1], hu, lu);
                *(uint32_t*)(Ch + (size_t)r0 * EMB + c0) = hu;
                *(uint32_t*)(Cl + (size_t)r0 * EMB + c0) = lu;
                split2(acc[mt][nt][2], acc[mt][nt][3], hu, lu);
                *(uint32_t*)(Ch + (size_t)(r0 + 8) * EMB + c0) = hu;
                *(uint32_t*)(Cl + (size_t)(r0 + 8) * EMB + c0) = lu;
            }
        }
    } else {
        #pragma unroll
        for (int mt = 0; mt < 4; mt++) {
            const int r0 = m0 + wm * 64 + mt * 16 + (lane >> 2);
            #pragma unroll
            for (int nt = 0; nt < 4; nt++) {
                const int c0 = n0 + wn * 32 + nt * 8 + 2 * (lane & 3);
                *(float2*)(C + (size_t)r0 * EMB + c0)       = make_float2(acc[mt][nt][0], acc[mt][nt][1]);
                *(float2*)(C + (size_t)(r0 + 8) * EMB + c0) = make_float2(acc[mt][nt][2], acc[mt][nt][3]);
            }
        }
    }
}

// ---------------------------------------------------------------------------
// Flash attention on mma.sync bf16 (3-term split for both QK^T and PV).
// CTA = 128 q-rows of one (b,h); 16 k-tiles of 128. 8 warps, warp w owns
// q rows 16w..16w+15 x all 128 k-cols (row stats stay in-warp).
// smem: Qh,Ql (16KB each) + 2 stages x (Kh,Kl,Vh,Vl 16KB each) = 160 KB.
// Swizzle: 16B chunk column ch -> ch ^ (row & 7) (conflict-free STS + LDSM).
// ---------------------------------------------------------------------------
#define BR  128
#define BC  128
#define NKT (SEQ / BC)        // 16
#define AQH 0
#define AQL 16384
#define AST 32768
#define ASTAGE 65536
#define ASM_TOTAL (AST + 2 * ASTAGE)   // 163840

__device__ __forceinline__ void att_cp_tile(const __nv_bfloat16* __restrict__ g,
                                            uint32_t sbase, int tid)
{
    #pragma unroll
    for (int p = 0; p < 4; p++) {
        int f = tid + p * 256;
        int r = f >> 3, ch = f & 7;
        const __nv_bfloat16* gp = g + (size_t)r * EMB + ch * 8;
        uint32_t sa = sbase + r * 128 + ((ch ^ (r & 7)) << 4);
        CP_ASYNC16(sa, gp);
    }
}

__global__ __launch_bounds__(256, 1)
void mha_attn_mma(const __nv_bfloat16* __restrict__ Qh, const __nv_bfloat16* __restrict__ Ql,
                  const __nv_bfloat16* __restrict__ Kh, const __nv_bfloat16* __restrict__ Kl,
                  const __nv_bfloat16* __restrict__ Vh, const __nv_bfloat16* __restrict__ Vl,
                  const unsigned char* __restrict__ mask8,
                  __nv_bfloat16* __restrict__ Oh, __nv_bfloat16* __restrict__ Ol)
{
    extern __shared__ char smem[];
    const uint32_t sb = smem_u32(smem);
    const int tid = threadIdx.x, wid = tid >> 5, lane = tid & 31;
    const int q0 = blockIdx.x * BR;
    const int b  = blockIdx.y >> 4, h = blockIdx.y & 15;

    const size_t qoff   = ((size_t)(b * SEQ + q0)) * EMB + h * DKH;
    const size_t kvbase = ((size_t)b * SEQ) * EMB + h * DKH;

    // prologue: Q + K/V stage 0
    att_cp_tile(Qh + qoff, sb + AQH, tid);
    att_cp_tile(Ql + qoff, sb + AQL, tid);
    att_cp_tile(Kh + kvbase, sb + AST + 0 * 16384, tid);
    att_cp_tile(Kl + kvbase, sb + AST + 1 * 16384, tid);
    att_cp_tile(Vh + kvbase, sb + AST + 2 * 16384, tid);
    att_cp_tile(Vl + kvbase, sb + AST + 3 * 16384, tid);
    CP_COMMIT();
    CP_WAIT0();
    __syncthreads();

    // preload Q A-fragments (constant across k-tiles)
    uint32_t qfh[4][4], qfl[4][4];
    {
        const int row = 16 * wid + (lane & 15);
        #pragma unroll
        for (int kc = 0; kc < 4; kc++) {
            const int ch = 2 * kc + (lane >> 4);
            const uint32_t off = row * 128 + ((ch ^ (row & 7)) << 4);
            LDSM4(qfh[kc], sb + AQH + off);
            LDSM4(qfl[kc], sb + AQL + off);
        }
    }

    const int sx    = lane & 7;                              // swizzle xor (row&7)
    const int krow  = (lane & 7) + ((lane & 16) ? 8 : 0);    // K ldsm row-in-16
    const int kchh  = (lane >> 3) & 1;                       // K ldsm chunk half
    const int vrowb = (lane & 7) + ((lane & 8) ? 8 : 0);     // V ldsm row-in-16
    const int vchh  = (lane & 16) ? 1 : 0;                   // V ldsm chunk half

    float o[8][4];
    #pragma unroll
    for (int g = 0; g < 8; g++)
        #pragma unroll
        for (int e = 0; e < 4; e++) o[g][e] = 0.0f;
    float m0 = -__int_as_float(0x7f800000) * 0.0f;           // placeholder
    m0 = __int_as_float(0xff800000);
    float m1 = __int_as_float(0xff800000);
    float l0 = 0.0f, l1 = 0.0f;

    const unsigned char* mb0 = mask8 +
        ((size_t)(b * SEQ + q0 + 16 * wid + (lane >> 2))) * SEQ + 2 * (lane & 3);
    const unsigned char* mb1 = mb0 + 8 * SEQ;

    for (int kt = 0; kt < NKT; kt++) {
        // issue next stage
        if (kt + 1 < NKT) {
            const size_t kv = kvbase + (size_t)(kt + 1) * BC * EMB;
            const uint32_t nb = sb + AST + ((kt + 1) & 1) * ASTAGE;
            att_cp_tile(Kh + kv, nb + 0 * 16384, tid);
            att_cp_tile(Kl + kv, nb + 1 * 16384, tid);
            att_cp_tile(Vh + kv, nb + 2 * 16384, tid);
            att_cp_tile(Vl + kv, nb + 3 * 16384, tid);
            CP_COMMIT();
            CP_WAIT1();
        } else {
            CP_WAIT0();
        }
        __syncthreads();

        const uint32_t bKh = sb + AST + (kt & 1) * ASTAGE;
        const uint32_t bKl = bKh + 16384;
        const uint32_t bVh = bKh + 32768;
        const uint32_t bVl = bKh + 49152;

        // ---- S = Q K^T (3-term split), s[g] = n8-group g of 16 ----
        float s[16][4];
        #pragma unroll
        for (int g = 0; g < 16; g++)
            #pragma unroll
            for (int e = 0; e < 4; e++) s[g][e] = 0.0f;

        #pragma unroll
        for (int kc = 0; kc < 4; kc++) {
            #pragma unroll
            for (int jp = 0; jp < 4; jp++) {
                uint32_t kh0[4], kl0[4], kh1[4], kl1[4];
                const int ch = 2 * kc + kchh;
                const uint32_t pc = (uint32_t)((ch ^ sx) << 4);
                const uint32_t o0 = (uint32_t)((32 * jp + krow) * 128) + pc;
                const uint32_t o1 = o0 + 16 * 128;
                LDSM4(kh0, bKh + o0);
                LDSM4(kl0, bKl + o0);
                LDSM4(kh1, bKh + o1);
                LDSM4(kl1, bKl + o1);
                MMA_BF16(s[4*jp+0], qfh[kc], kh0);
                MMA_BF16(s[4*jp+1], qfh[kc], kh0 + 2);
                MMA_BF16(s[4*jp+2], qfh[kc], kh1);
                MMA_BF16(s[4*jp+3], qfh[kc], kh1 + 2);
                MMA_BF16(s[4*jp+0], qfh[kc], kl0);
                MMA_BF16(s[4*jp+1], qfh[kc], kl0 + 2);
                MMA_BF16(s[4*jp+2], qfh[kc], kl1);
                MMA_BF16(s[4*jp+3], qfh[kc], kl1 + 2);
                MMA_BF16(s[4*jp+0], qfl[kc], kh0);
                MMA_BF16(s[4*jp+1], qfl[kc], kh0 + 2);
                MMA_BF16(s[4*jp+2], qfl[kc], kh1);
                MMA_BF16(s[4*jp+3], qfl[kc], kh1 + 2);
            }
        }

        // ---- scale + mask ----
        const unsigned char* mr0 = mb0 + (size_t)kt * BC;
        const unsigned char* mr1 = mb1 + (size_t)kt * BC;
        #pragma unroll
        for (int g = 0; g < 16; g++) {
            uchar2 u0 = *(const uchar2*)(mr0 + 8 * g);
            uchar2 u1 = *(const uchar2*)(mr1 + 8 * g);
            s[g][0] = u0.x ? NEGV : s[g][0] * SCALE;
            s[g][1] = u0.y ? NEGV : s[g][1] * SCALE;
            s[g][2] = u1.x ? NEGV : s[g][2] * SCALE;
            s[g][3] = u1.y ? NEGV : s[g][3] * SCALE;
        }

        // ---- online softmax (rows r=lane>>2 and r+8; 4-lane groups) ----
        float mx0 = NEGV * 2.0f, mx1 = NEGV * 2.0f;
        #pragma unroll
        for (int g = 0; g < 16; g++) {
            mx0 = fmaxf(mx0, fmaxf(s[g][0], s[g][1]));
            mx1 = fmaxf(mx1, fmaxf(s[g][2], s[g][3]));
        }
        mx0 = fmaxf(mx0, __shfl_xor_sync(0xffffffffu, mx0, 1));
        mx0 = fmaxf(mx0, __shfl_xor_sync(0xffffffffu, mx0, 2));
        mx1 = fmaxf(mx1, __shfl_xor_sync(0xffffffffu, mx1, 1));
        mx1 = fmaxf(mx1, __shfl_xor_sync(0xffffffffu, mx1, 2));
        const float mn0 = fmaxf(m0, mx0), mn1 = fmaxf(m1, mx1);
        const float a0 = __expf(m0 - mn0), a1 = __expf(m1 - mn1);
        float sum0 = 0.0f, sum1 = 0.0f;
        #pragma unroll
        for (int g = 0; g < 16; g++) {
            s[g][0] = __expf(s[g][0] - mn0);
            s[g][1] = __expf(s[g][1] - mn0);
            s[g][2] = __expf(s[g][2] - mn1);
            s[g][3] = __expf(s[g][3] - mn1);
            sum0 += s[g][0] + s[g][1];
            sum1 += s[g][2] + s[g][3];
        }
        sum0 += __shfl_xor_sync(0xffffffffu, sum0, 1);
        sum0 += __shfl_xor_sync(0xffffffffu, sum0, 2);
        sum1 += __shfl_xor_sync(0xffffffffu, sum1, 1);
        sum1 += __shfl_xor_sync(0xffffffffu, sum1, 2);
        l0 = l0 * a0 + sum0;  m0 = mn0;
        l1 = l1 * a1 + sum1;  m1 = mn1;
        #pragma unroll
        for (int g = 0; g < 8; g++) {
            o[g][0] *= a0; o[g][1] *= a0;
            o[g][2] *= a1; o[g][3] *= a1;
        }

        // ---- P -> bf16 hi/lo A-fragments (register-only) ----
        uint32_t pha[8][4], pla[8][4];
        #pragma unroll
        for (int c = 0; c < 8; c++) {
            split2(s[2*c][0],   s[2*c][1],   pha[c][0], pla[c][0]);
            split2(s[2*c][2],   s[2*c][3],   pha[c][1], pla[c][1]);
            split2(s[2*c+1][0], s[2*c+1][1], pha[c][2], pla[c][2]);
            split2(s[2*c+1][2], s[2*c+1][3], pha[c][3], pla[c][3]);
        }

        // ---- O += P V (3-term split), V via ldmatrix.trans ----
        #pragma unroll
        for (int c = 0; c < 8; c++) {
            uint32_t vh[4][4], vl[4][4];
            const uint32_t rbase = (uint32_t)((16 * c + vrowb) * 128);
            #pragma unroll
            for (int jd = 0; jd < 4; jd++) {
                const int ch = 2 * jd + vchh;
                const uint32_t off = rbase + ((ch ^ sx) << 4);
                LDSM4T(vh[jd], bVh + off);
                LDSM4T(vl[jd], bVl + off);
            }
            #pragma unroll
            for (int jd = 0; jd < 4; jd++) {
                MMA_BF16(o[2*jd],   pha[c], vh[jd]);
                MMA_BF16(o[2*jd+1], pha[c], vh[jd] + 2);
            }
            #pragma unroll
            for (int jd = 0; jd < 4; jd++) {
                MMA_BF16(o[2*jd],   pha[c], vl[jd]);
                MMA_BF16(o[2*jd+1], pha[c], vl[jd] + 2);
            }
            #pragma unroll
            for (int jd = 0; jd < 4; jd++) {
                MMA_BF16(o[2*jd],   pla[c], vh[jd]);
                MMA_BF16(o[2*jd+1], pla[c], vh[jd] + 2);
            }
        }

        __syncthreads();   // all warps done with stage (kt&1) before overwrite
    }

    // ---- epilogue: normalize, split, store hi/lo for the Wo GEMM ----
    const float i0 = 1.0f / l0, i1 = 1.0f / l1;
    const int qr = q0 + 16 * wid + (lane >> 2);
    const size_t ob = ((size_t)(b * SEQ + qr)) * EMB + h * DKH + 2 * (lane & 3);
    #pragma unroll
    for (int g = 0; g < 8; g++) {
        uint32_t hu, lu;
        split2(o[g][0] * i0, o[g][1] * i0, hu, lu);
        *(uint32_t*)(Oh + ob + 8 * g) = hu;
        *(uint32_t*)(Ol + ob + 8 * g) = lu;
        split2(o[g][2] * i1, o[g][3] * i1, hu, lu);
        *(uint32_t*)(Oh + ob + 8 * (size_t)EMB + 8 * g) = hu;
        *(uint32_t*)(Ol + ob + 8 * (size_t)EMB + 8 * g) = lu;
    }
}

// ---------------------------------------------------------------------------
extern "C" void kernel_launch(void* const* d_in, const int* in_sizes, int n_in,
                              void* d_out, int out_size)
{
    (void)in_sizes; (void)n_in; (void)out_size;
    const float*         query  = (const float*)d_in[0];
    const float*         key    = (const float*)d_in[1];
    const float*         value  = (const float*)d_in[2];
    const unsigned char* masked = (const unsigned char*)d_in[3];
    const float*         Wq     = (const float*)d_in[4];
    const float*         Wk     = (const float*)d_in[5];
    const float*         Wv     = (const float*)d_in[6];
    const float*         Wo     = (const float*)d_in[7];
    float*               out    = (float*)d_out;

    __nv_bfloat16 *gqh, *gql, *gkh, *gkl, *gvh, *gvl, *gah, *gal, *gwth, *gwtl;
    unsigned char *gm8;
    cudaGetSymbolAddress((void**)&gqh,  g_qh);
    cudaGetSymbolAddress((void**)&gql,  g_ql);
    cudaGetSymbolAddress((void**)&gkh,  g_kh);
    cudaGetSymbolAddress((void**)&gkl,  g_kl);
    cudaGetSymbolAddress((void**)&gvh,  g_vh);
    cudaGetSymbolAddress((void**)&gvl,  g_vl);
    cudaGetSymbolAddress((void**)&gah,  g_ah);
    cudaGetSymbolAddress((void**)&gal,  g_al);
    cudaGetSymbolAddress((void**)&gwth, g_wth);
    cudaGetSymbolAddress((void**)&gwtl, g_wtl);
    cudaGetSymbolAddress((void**)&gm8,  g_m8);

    cudaFuncSetAttribute(mha_mma_gemm,
                         cudaFuncAttributeMaxDynamicSharedMemorySize, GSM_TOTAL);
    cudaFuncSetAttribute(mha_attn_mma,
                         cudaFuncAttributeMaxDynamicSharedMemorySize, ASM_TOTAL);

    const int n4 = MROWS * EMB / 4;
    dim3 split_grid((n4 + 255) / 256);
    dim3 w_grid(EMB / 32, EMB / 32), w_blk(32, 8);
    dim3 gemm_grid(EMB / 128, MROWS / 128);

    mha_detect_mask_kernel<<<1, 32>>>(masked);
    const int mn4 = BATCH * SEQ * SEQ / 4;
    mha_mask8_kernel<<<(mn4 + 255) / 256, 256>>>(masked, gm8, mn4);

    // Q projection -> split bf16 directly
    mha_wsplit_kernel<<<w_grid, w_blk>>>(Wq, gwth, gwtl);
    mha_split_kernel<<<split_grid, 256>>>((const float4*)query,
                                          (__nv_bfloat162*)gah, (__nv_bfloat162*)gal, n4);
    mha_mma_gemm<<<gemm_grid, 256, GSM_TOTAL>>>(gah, gal, gwth, gwtl, nullptr, gqh, gql);

    // K projection
    mha_wsplit_kernel<<<w_grid, w_blk>>>(Wk, gwth, gwtl);
    mha_split_kernel<<<split_grid, 256>>>((const float4*)key,
                                          (__nv_bfloat162*)gah, (__nv_bfloat162*)gal, n4);
    mha_mma_gemm<<<gemm_grid, 256, GSM_TOTAL>>>(gah, gal, gwth, gwtl, nullptr, gkh, gkl);

    // V projection
    mha_wsplit_kernel<<<w_grid, w_blk>>>(Wv, gwth, gwtl);
    mha_split_kernel<<<split_grid, 256>>>((const float4*)value,
                                          (__nv_bfloat162*)gah, (__nv_bfloat162*)gal, n4);
    mha_mma_gemm<<<gemm_grid, 256, GSM_TOTAL>>>(gah, gal, gwth, gwtl, nullptr, gvh, gvl);

    // attention (writes split output for Wo GEMM)
    dim3 attn_grid(SEQ / BR, BATCH * HEADS);
    mha_attn_mma<<<attn_grid, 256, ASM_TOTAL>>>(gqh, gql, gkh, gkl, gvh, gvl,
                                                gm8, gah, gal);

    // output projection (fp32 out)
    mha_wsplit_kernel<<<w_grid, w_blk>>>(Wo, gwth, gwtl);
    mha_mma_gemm<<<gemm_grid, 256, GSM_TOTAL>>>(gah, gal, gwth, gwtl, out, nullptr, nullptr);
}

// round 6
// speedup vs baseline: 2.7616x; 1.0261x over previous
#include <cuda_runtime.h>
#include <cuda_bf16.h>
#include <cstdint>

#define BATCH 2
#define SEQ   2048
#define EMB   1024
#define HEADS 16
#define DKH   64
#define NEGV  (-1.0e9f)
#define SCALE 0.125f
#define MROWS (BATCH*SEQ)     // 4096

// ---------------------------------------------------------------------------
// Scratch — __device__ globals per allocation rules.
// ---------------------------------------------------------------------------
__device__ __nv_bfloat16 g_qh [MROWS*EMB];
__device__ __nv_bfloat16 g_ql [MROWS*EMB];
__device__ __nv_bfloat16 g_kh [MROWS*EMB];
__device__ __nv_bfloat16 g_kl [MROWS*EMB];
__device__ __nv_bfloat16 g_vh [MROWS*EMB];
__device__ __nv_bfloat16 g_vl [MROWS*EMB];
__device__ __nv_bfloat16 g_xh [3][MROWS*EMB];  // q/k/v input splits (hi)
__device__ __nv_bfloat16 g_xl [3][MROWS*EMB];  // q/k/v input splits (lo)
__device__ __nv_bfloat16 g_oh [MROWS*EMB];     // attention out hi
__device__ __nv_bfloat16 g_ol [MROWS*EMB];     // attention out lo
__device__ __nv_bfloat16 g_wth[4][EMB*EMB];    // weight^T splits hi [N][K]
__device__ __nv_bfloat16 g_wtl[4][EMB*EMB];    // weight^T splits lo [N][K]
__device__ unsigned char g_m8 [BATCH*SEQ*SEQ];
__device__ int   g_mask_is_i32;

// ---------------------------------------------------------------------------
// PTX helpers (compute_100-safe baseline ISA: mma.sync / ldmatrix / cp.async)
// ---------------------------------------------------------------------------
__device__ __forceinline__ uint32_t smem_u32(const void* p) {
    uint32_t a;
    asm("{ .reg .u64 t; cvta.to.shared.u64 t, %1; cvt.u32.u64 %0, t; }"
        : "=r"(a) : "l"(p));
    return a;
}

#define LDSM4(r, addr) \
    asm volatile("ldmatrix.sync.aligned.m8n8.x4.shared.b16 {%0,%1,%2,%3}, [%4];" \
        : "=r"((r)[0]), "=r"((r)[1]), "=r"((r)[2]), "=r"((r)[3]) : "r"(addr))
#define LDSM4T(r, addr) \
    asm volatile("ldmatrix.sync.aligned.m8n8.x4.trans.shared.b16 {%0,%1,%2,%3}, [%4];" \
        : "=r"((r)[0]), "=r"((r)[1]), "=r"((r)[2]), "=r"((r)[3]) : "r"(addr))

#define MMA_BF16(d, a, b) \
    asm volatile("mma.sync.aligned.m16n8k16.row.col.f32.bf16.bf16.f32 " \
        "{%0,%1,%2,%3}, {%4,%5,%6,%7}, {%8,%9}, {%0,%1,%2,%3};" \
        : "+f"((d)[0]), "+f"((d)[1]), "+f"((d)[2]), "+f"((d)[3]) \
        : "r"((a)[0]), "r"((a)[1]), "r"((a)[2]), "r"((a)[3]), \
          "r"((b)[0]), "r"((b)[1]))

#define CP_ASYNC16(sa, gp) \
    asm volatile("{\n\t.reg .u64 gpt;\n\tcvta.to.global.u64 gpt, %1;\n\t" \
        "cp.async.cg.shared.global [%0], [gpt], 16;\n\t}" \
        :: "r"(sa), "l"(gp))
#define CP_COMMIT()  asm volatile("cp.async.commit_group;" ::: "memory")
#define CP_WAIT0()   asm volatile("cp.async.wait_group 0;" ::: "memory")
#define CP_WAIT1()   asm volatile("cp.async.wait_group 1;" ::: "memory")

// fp32 pair -> packed bf16x2 hi and lo (2-term split)
__device__ __forceinline__ void split2(float x, float y, uint32_t& hi, uint32_t& lo)
{
    __nv_bfloat16 hx = __float2bfloat16(x), hy = __float2bfloat16(y);
    __nv_bfloat16 lx = __float2bfloat16(x - __bfloat162float(hx));
    __nv_bfloat16 ly = __float2bfloat16(y - __bfloat162float(hy));
    __nv_bfloat162 H(hx, hy), L(lx, ly);
    hi = *reinterpret_cast<uint32_t*>(&H);
    lo = *reinterpret_cast<uint32_t*>(&L);
}

// ---------------------------------------------------------------------------
// Mask representation detection (parallel).
// ---------------------------------------------------------------------------
__global__ void mha_detect_mask_kernel(const unsigned char* __restrict__ m)
{
    int s = 0;
    for (int i = threadIdx.x; i < 4096; i += 256)
        if ((i & 3) != 0) s |= m[i];
    int any = __syncthreads_or(s);
    if (threadIdx.x == 0)
        g_mask_is_i32 = (any == 0) ? 1 : 0;
}

// mask -> uint8 (avoids 16x-redundant int32 reads in attention)
__global__ __launch_bounds__(256)
void mha_mask8_kernel(const unsigned char* __restrict__ m,
                      unsigned char* __restrict__ o, int n4)
{
    int i = blockIdx.x * 256 + threadIdx.x;
    if (i >= n4) return;
    if (g_mask_is_i32) {
        int4 w = ((const int4*)m)[i];
        uchar4 u;
        u.x = (unsigned char)w.x; u.y = (unsigned char)w.y;
        u.z = (unsigned char)w.z; u.w = (unsigned char)w.w;
        ((uchar4*)o)[i] = u;
    } else {
        ((uchar4*)o)[i] = ((const uchar4*)m)[i];
    }
}

// ---------------------------------------------------------------------------
// fp32 -> (bf16 hi, bf16 lo) split, 3 tensors in one launch (z selects).
// ---------------------------------------------------------------------------
struct SplitArgs {
    const float4* x[3];
    uint32_t* hi[3];
    uint32_t* lo[3];
};

__global__ __launch_bounds__(256)
void mha_split3_kernel(SplitArgs p, int n4)
{
    int i = blockIdx.x * 256 + threadIdx.x;
    if (i >= n4) return;
    const int z = blockIdx.z;
    float4 v = p.x[z][i];
    uint32_t h0, l0, h1, l1;
    split2(v.x, v.y, h0, l0);
    split2(v.z, v.w, h1, l1);
    p.hi[z][2 * i + 0] = h0;
    p.hi[z][2 * i + 1] = h1;
    p.lo[z][2 * i + 0] = l0;
    p.lo[z][2 * i + 1] = l1;
}

// ---------------------------------------------------------------------------
// Weight transpose + split: W[K,N] fp32 -> Wt hi/lo [N,K] bf16, 4 weights.
// ---------------------------------------------------------------------------
struct WsplitArgs {
    const float* W[4];
    __nv_bfloat16* th[4];
    __nv_bfloat16* tl[4];
};

__global__ __launch_bounds__(256)
void mha_wsplit4_kernel(WsplitArgs p)
{
    __shared__ float t[32][33];
    const int z  = blockIdx.z;
    const float* W = p.W[z];
    const int n  = blockIdx.x * 32 + threadIdx.x;
    const int k0 = blockIdx.y * 32;
    #pragma unroll
    for (int r = 0; r < 32; r += 8)
        t[threadIdx.y + r][threadIdx.x] = W[(size_t)(k0 + threadIdx.y + r) * EMB + n];
    __syncthreads();
    #pragma unroll
    for (int r = 0; r < 32; r += 8) {
        float v = t[threadIdx.x][threadIdx.y + r];
        int on = blockIdx.x * 32 + threadIdx.y + r;
        int ok = k0 + threadIdx.x;
        __nv_bfloat16 h = __float2bfloat16(v);
        p.th[z][(size_t)on * EMB + ok] = h;
        p.tl[z][(size_t)on * EMB + ok] = __float2bfloat16(v - __bfloat162float(h));
    }
}

// ---------------------------------------------------------------------------
// Tensor-core GEMM body (mma.sync bf16 3-term split), CTA 128x128, K-chunk 32,
// double-buffered cp.async.
// ---------------------------------------------------------------------------
#define KC        32
#define ROWB      80
#define TILE_SB   (128 * ROWB)
#define STAGE_SB  (4 * TILE_SB)
#define GSM_TOTAL (2 * STAGE_SB)      // 81920

__device__ __forceinline__ void cp_tile(const __nv_bfloat16* __restrict__ g,
                                        int row0, int kb, uint32_t sdst, int tid)
{
    #pragma unroll
    for (int p = 0; p < 2; p++) {
        int f = tid + p * 256;
        int r = f >> 2, ch = f & 3;
        const __nv_bfloat16* gp = g + (size_t)(row0 + r) * EMB + kb + ch * 8;
        uint32_t sa = sdst + r * ROWB + ch * 16;
        CP_ASYNC16(sa, gp);
    }
}

// shared GEMM mainloop: accumulates into acc
__device__ __forceinline__ void gemm_main(const __nv_bfloat16* Ah, const __nv_bfloat16* Al,
                                          const __nv_bfloat16* Bh, const __nv_bfloat16* Bl,
                                          uint32_t sb, int m0, int n0,
                                          int tid, int lane, int wm, int wn,
                                          float acc[4][4][4])
{
    cp_tile(Ah, m0, 0, sb + 0 * TILE_SB, tid);
    cp_tile(Al, m0, 0, sb + 1 * TILE_SB, tid);
    cp_tile(Bh, n0, 0, sb + 2 * TILE_SB, tid);
    cp_tile(Bl, n0, 0, sb + 3 * TILE_SB, tid);
    CP_COMMIT();

    const int NS = EMB / KC;
    for (int s = 0; s < NS; s++) {
        CP_WAIT0();
        __syncthreads();

        if (s + 1 < NS) {
            const uint32_t nb = sb + ((s + 1) & 1) * STAGE_SB;
            const int kb = (s + 1) * KC;
            cp_tile(Ah, m0, kb, nb + 0 * TILE_SB, tid);
            cp_tile(Al, m0, kb, nb + 1 * TILE_SB, tid);
            cp_tile(Bh, n0, kb, nb + 2 * TILE_SB, tid);
            cp_tile(Bl, n0, kb, nb + 3 * TILE_SB, tid);
            CP_COMMIT();
        }

        const uint32_t abase = sb + (s & 1) * STAGE_SB;
        const uint32_t bbase = abase + 2 * TILE_SB;

        #pragma unroll
        for (int ks = 0; ks < 2; ks++) {
            uint32_t ah[4][4], al[4][4];
            #pragma unroll
            for (int mt = 0; mt < 4; mt++) {
                const int row = wm * 64 + mt * 16 + (lane & 15);
                const int ch  = ks * 2 + (lane >> 4);
                const uint32_t ad = abase + row * ROWB + ch * 16;
                LDSM4(ah[mt], ad);
                LDSM4(al[mt], ad + TILE_SB);
            }
            uint32_t bh[4][2], bl[4][2];
            #pragma unroll
            for (int g = 0; g < 2; g++) {
                const int row = wn * 32 + g * 16 + (lane & 7) + ((lane >> 4) << 3);
                const int ch  = ks * 2 + ((lane >> 3) & 1);
                const uint32_t bd = bbase + row * ROWB + ch * 16;
                uint32_t t[4];
                LDSM4(t, bd);
                bh[2*g][0] = t[0]; bh[2*g][1] = t[1];
                bh[2*g+1][0] = t[2]; bh[2*g+1][1] = t[3];
                LDSM4(t, bd + TILE_SB);
                bl[2*g][0] = t[0]; bl[2*g][1] = t[1];
                bl[2*g+1][0] = t[2]; bl[2*g+1][1] = t[3];
            }
            #pragma unroll
            for (int mt = 0; mt < 4; mt++)
                #pragma unroll
                for (int nt = 0; nt < 4; nt++) {
                    MMA_BF16(acc[mt][nt], ah[mt], bh[nt]);
                    MMA_BF16(acc[mt][nt], ah[mt], bl[nt]);
                    MMA_BF16(acc[mt][nt], al[mt], bh[nt]);
                }
        }
        __syncthreads();
    }
}

// merged Q/K/V projections: z selects operand set; writes split bf16 hi/lo
struct Gemm3Args {
    const __nv_bfloat16 *Ah[3], *Al[3], *Bh[3], *Bl[3];
    __nv_bfloat16 *Ch[3], *Cl[3];
};

__global__ __launch_bounds__(256)
void mha_mma_gemm3(Gemm3Args p)
{
    extern __shared__ char smem[];
    const uint32_t sb = smem_u32(smem);
    const int tid  = threadIdx.x;
    const int wid  = tid >> 5;
    const int lane = tid & 31;
    const int wm   = wid & 1;
    const int wn   = wid >> 1;
    const int m0   = blockIdx.y * 128;
    const int n0   = blockIdx.x * 128;
    const int z    = blockIdx.z;

    float acc[4][4][4];
    #pragma unroll
    for (int mt = 0; mt < 4; mt++)
        #pragma unroll
        for (int nt = 0; nt < 4; nt++)
            #pragma unroll
            for (int e = 0; e < 4; e++) acc[mt][nt][e] = 0.0f;

    gemm_main(p.Ah[z], p.Al[z], p.Bh[z], p.Bl[z], sb, m0, n0, tid, lane, wm, wn, acc);

    __nv_bfloat16* Ch = p.Ch[z];
    __nv_bfloat16* Cl = p.Cl[z];
    #pragma unroll
    for (int mt = 0; mt < 4; mt++) {
        const int r0 = m0 + wm * 64 + mt * 16 + (lane >> 2);
        #pragma unroll
        for (int nt = 0; nt < 4; nt++) {
            const int c0 = n0 + wn * 32 + nt * 8 + 2 * (lane & 3);
            uint32_t hu, lu;
            split2(acc[mt][nt][0], acc[mt][nt][1], hu, lu);
            *(uint32_t*)(Ch + (size_t)r0 * EMB + c0) = hu;
            *(uint32_t*)(Cl + (size_t)r0 * EMB + c0) = lu;
            split2(acc[mt][nt][2], acc[mt][nt][3], hu, lu);
            *(uint32_t*)(Ch + (size_t)(r0 + 8) * EMB + c0) = hu;
            *(uint32_t*)(Cl + (size_t)(r0 + 8) * EMB + c0) = lu;
        }
    }
}

// single GEMM with fp32 output (Wo projection)
__global__ __launch_bounds__(256)
void mha_mma_gemm_f32(const __nv_bfloat16* __restrict__ Ah,
                      const __nv_bfloat16* __restrict__ Al,
                      const __nv_bfloat16* __restrict__ Bh,
                      const __nv_bfloat16* __restrict__ Bl,
                      float* __restrict__ C)
{
    extern __shared__ char smem[];
    const uint32_t sb = smem_u32(smem);
    const int tid  = threadIdx.x;
    const int wid  = tid >> 5;
    const int lane = tid & 31;
    const int wm   = wid & 1;
    const int wn   = wid >> 1;
    const int m0   = blockIdx.y * 128;
    const int n0   = blockIdx.x * 128;

    float acc[4][4][4];
    #pragma unroll
    for (int mt = 0; mt < 4; mt++)
        #pragma unroll
        for (int nt = 0; nt < 4; nt++)
            #pragma unroll
            for (int e = 0; e < 4; e++) acc[mt][nt][e] = 0.0f;

    gemm_main(Ah, Al, Bh, Bl, sb, m0, n0, tid, lane, wm, wn, acc);

    #pragma unroll
    for (int mt = 0; mt < 4; mt++) {
        const int r0 = m0 + wm * 64 + mt * 16 + (lane >> 2);
        #pragma unroll
        for (int nt = 0; nt < 4; nt++) {
            const int c0 = n0 + wn * 32 + nt * 8 + 2 * (lane & 3);
            *(float2*)(C + (size_t)r0 * EMB + c0)       = make_float2(acc[mt][nt][0], acc[mt][nt][1]);
            *(float2*)(C + (size_t)(r0 + 8) * EMB + c0) = make_float2(acc[mt][nt][2], acc[mt][nt][3]);
        }
    }
}

// ---------------------------------------------------------------------------
// Flash attention on mma.sync bf16 (3-term split for both QK^T and PV).
// CTA = 128 q-rows of one (b,h); 32 k-tiles of 64. 8 warps, warp w owns
// q rows 16w..16w+15 x all 64 k-cols.
// smem: Qh,Ql (16KB each) + 2 stages x (Kh,Kl,Vh,Vl 8KB each) = 96 KB
// -> 2 CTAs/SM (4 warps/SMSP) for latency hiding.
// Swizzle: 16B chunk column ch -> ch ^ (row & 7).
// ---------------------------------------------------------------------------
#define BR  128
#define BC  64
#define NKT (SEQ / BC)        // 32
#define AQH 0
#define AQL 16384
#define AST 32768
#define KVT 8192              // one 64x64 bf16 tile
#define ASTAGE (4 * KVT)      // 32768
#define ASM_TOTAL (AST + 2 * ASTAGE)   // 98304

__device__ __forceinline__ void att_cp_q(const __nv_bfloat16* __restrict__ g,
                                         uint32_t sbase, int tid)
{
    #pragma unroll
    for (int p = 0; p < 4; p++) {
        int f = tid + p * 256;
        int r = f >> 3, ch = f & 7;
        const __nv_bfloat16* gp = g + (size_t)r * EMB + ch * 8;
        uint32_t sa = sbase + r * 128 + ((ch ^ (r & 7)) << 4);
        CP_ASYNC16(sa, gp);
    }
}

__device__ __forceinline__ void att_cp_kv(const __nv_bfloat16* __restrict__ g,
                                          uint32_t sbase, int tid)
{
    #pragma unroll
    for (int p = 0; p < 2; p++) {
        int f = tid + p * 256;
        int r = f >> 3, ch = f & 7;
        const __nv_bfloat16* gp = g + (size_t)r * EMB + ch * 8;
        uint32_t sa = sbase + r * 128 + ((ch ^ (r & 7)) << 4);
        CP_ASYNC16(sa, gp);
    }
}

__global__ __launch_bounds__(256, 2)
void mha_attn_mma(const __nv_bfloat16* __restrict__ Qh, const __nv_bfloat16* __restrict__ Ql,
                  const __nv_bfloat16* __restrict__ Kh, const __nv_bfloat16* __restrict__ Kl,
                  const __nv_bfloat16* __restrict__ Vh, const __nv_bfloat16* __restrict__ Vl,
                  const unsigned char* __restrict__ mask8,
                  __nv_bfloat16* __restrict__ Oh, __nv_bfloat16* __restrict__ Ol)
{
    extern __shared__ char smem[];
    const uint32_t sb = smem_u32(smem);
    const int tid = threadIdx.x, wid = tid >> 5, lane = tid & 31;
    const int q0 = blockIdx.x * BR;
    const int b  = blockIdx.y >> 4, h = blockIdx.y & 15;

    const size_t qoff   = ((size_t)(b * SEQ + q0)) * EMB + h * DKH;
    const size_t kvbase = ((size_t)b * SEQ) * EMB + h * DKH;

    // prologue: Q + K/V stage 0
    att_cp_q(Qh + qoff, sb + AQH, tid);
    att_cp_q(Ql + qoff, sb + AQL, tid);
    att_cp_kv(Kh + kvbase, sb + AST + 0 * KVT, tid);
    att_cp_kv(Kl + kvbase, sb + AST + 1 * KVT, tid);
    att_cp_kv(Vh + kvbase, sb + AST + 2 * KVT, tid);
    att_cp_kv(Vl + kvbase, sb + AST + 3 * KVT, tid);
    CP_COMMIT();
    CP_WAIT0();
    __syncthreads();

    // preload Q-hi A-fragments (Q-lo reloaded per tile to cap registers)
    uint32_t qfh[4][4];
    uint32_t qlbase;
    {
        const int row = 16 * wid + (lane & 15);
        #pragma unroll
        for (int kc = 0; kc < 4; kc++) {
            const int ch = 2 * kc + (lane >> 4);
            const uint32_t off = row * 128 + ((ch ^ (row & 7)) << 4);
            LDSM4(qfh[kc], sb + AQH + off);
        }
        qlbase = sb + AQL + row * 128;
    }
    const int qrow7 = (16 * wid + (lane & 15)) & 7;

    const int sx    = lane & 7;                              // swizzle xor
    const int krow  = (lane & 7) + ((lane & 16) ? 8 : 0);
    const int kchh  = (lane >> 3) & 1;
    const int vrowb = (lane & 7) + ((lane & 8) ? 8 : 0);
    const int vchh  = (lane & 16) ? 1 : 0;

    float o[8][4];
    #pragma unroll
    for (int g = 0; g < 8; g++)
        #pragma unroll
        for (int e = 0; e < 4; e++) o[g][e] = 0.0f;
    float m0 = __int_as_float(0xff800000);
    float m1 = __int_as_float(0xff800000);
    float l0 = 0.0f, l1 = 0.0f;

    const unsigned char* mb0 = mask8 +
        ((size_t)(b * SEQ + q0 + 16 * wid + (lane >> 2))) * SEQ + 2 * (lane & 3);
    const unsigned char* mb1 = mb0 + 8 * SEQ;

    for (int kt = 0; kt < NKT; kt++) {
        if (kt + 1 < NKT) {
            const size_t kv = kvbase + (size_t)(kt + 1) * BC * EMB;
            const uint32_t nb = sb + AST + ((kt + 1) & 1) * ASTAGE;
            att_cp_kv(Kh + kv, nb + 0 * KVT, tid);
            att_cp_kv(Kl + kv, nb + 1 * KVT, tid);
            att_cp_kv(Vh + kv, nb + 2 * KVT, tid);
            att_cp_kv(Vl + kv, nb + 3 * KVT, tid);
            CP_COMMIT();
            CP_WAIT1();
        } else {
            CP_WAIT0();
        }
        __syncthreads();

        const uint32_t bKh = sb + AST + (kt & 1) * ASTAGE;
        const uint32_t bKl = bKh + KVT;
        const uint32_t bVh = bKh + 2 * KVT;
        const uint32_t bVl = bKh + 3 * KVT;

        // ---- S = Q K^T (3-term split); 8 n8-groups of 64 k-cols ----
        float s[8][4];
        #pragma unroll
        for (int g = 0; g < 8; g++)
            #pragma unroll
            for (int e = 0; e < 4; e++) s[g][e] = 0.0f;

        #pragma unroll
        for (int kc = 0; kc < 4; kc++) {
            uint32_t qfl[4];
            {
                const int ch = 2 * kc + (lane >> 4);
                LDSM4(qfl, qlbase + ((ch ^ qrow7) << 4));
            }
            #pragma unroll
            for (int jp = 0; jp < 2; jp++) {
                uint32_t kh0[4], kl0[4], kh1[4], kl1[4];
                const int ch = 2 * kc + kchh;
                const uint32_t pc = (uint32_t)((ch ^ sx) << 4);
                const uint32_t o0 = (uint32_t)((32 * jp + krow) * 128) + pc;
                const uint32_t o1 = o0 + 16 * 128;
                LDSM4(kh0, bKh + o0);
                LDSM4(kl0, bKl + o0);
                LDSM4(kh1, bKh + o1);
                LDSM4(kl1, bKl + o1);
                MMA_BF16(s[4*jp+0], qfh[kc], kh0);
                MMA_BF16(s[4*jp+1], qfh[kc], kh0 + 2);
                MMA_BF16(s[4*jp+2], qfh[kc], kh1);
                MMA_BF16(s[4*jp+3], qfh[kc], kh1 + 2);
                MMA_BF16(s[4*jp+0], qfh[kc], kl0);
                MMA_BF16(s[4*jp+1], qfh[kc], kl0 + 2);
                MMA_BF16(s[4*jp+2], qfh[kc], kl1);
                MMA_BF16(s[4*jp+3], qfh[kc], kl1 + 2);
                MMA_BF16(s[4*jp+0], qfl, kh0);
                MMA_BF16(s[4*jp+1], qfl, kh0 + 2);
                MMA_BF16(s[4*jp+2], qfl, kh1);
                MMA_BF16(s[4*jp+3], qfl, kh1 + 2);
            }
        }

        // ---- scale + mask ----
        const unsigned char* mr0 = mb0 + (size_t)kt * BC;
        const unsigned char* mr1 = mb1 + (size_t)kt * BC;
        #pragma unroll
        for (int g = 0; g < 8; g++) {
            uchar2 u0 = *(const uchar2*)(mr0 + 8 * g);
            uchar2 u1 = *(const uchar2*)(mr1 + 8 * g);
            s[g][0] = u0.x ? NEGV : s[g][0] * SCALE;
            s[g][1] = u0.y ? NEGV : s[g][1] * SCALE;
            s[g][2] = u1.x ? NEGV : s[g][2] * SCALE;
            s[g][3] = u1.y ? NEGV : s[g][3] * SCALE;
        }

        // ---- online softmax (rows lane>>2 and +8; 4-lane groups) ----
        float mx0 = NEGV * 2.0f, mx1 = NEGV * 2.0f;
        #pragma unroll
        for (int g = 0; g < 8; g++) {
            mx0 = fmaxf(mx0, fmaxf(s[g][0], s[g][1]));
            mx1 = fmaxf(mx1, fmaxf(s[g][2], s[g][3]));
        }
        mx0 = fmaxf(mx0, __shfl_xor_sync(0xffffffffu, mx0, 1));
        mx0 = fmaxf(mx0, __shfl_xor_sync(0xffffffffu, mx0, 2));
        mx1 = fmaxf(mx1, __shfl_xor_sync(0xffffffffu, mx1, 1));
        mx1 = fmaxf(mx1, __shfl_xor_sync(0xffffffffu, mx1, 2));
        const float mn0 = fmaxf(m0, mx0), mn1 = fmaxf(m1, mx1);
        const float a0 = __expf(m0 - mn0), a1 = __expf(m1 - mn1);
        float sum0 = 0.0f, sum1 = 0.0f;
        #pragma unroll
        for (int g = 0; g < 8; g++) {
            s[g][0] = __expf(s[g][0] - mn0);
            s[g][1] = __expf(s[g][1] - mn0);
            s[g][2] = __expf(s[g][2] - mn1);
            s[g][3] = __expf(s[g][3] - mn1);
            sum0 += s[g][0] + s[g][1];
            sum1 += s[g][2] + s[g][3];
        }
        sum0 += __shfl_xor_sync(0xffffffffu, sum0, 1);
        sum0 += __shfl_xor_sync(0xffffffffu, sum0, 2);
        sum1 += __shfl_xor_sync(0xffffffffu, sum1, 1);
        sum1 += __shfl_xor_sync(0xffffffffu, sum1, 2);
        l0 = l0 * a0 + sum0;  m0 = mn0;
        l1 = l1 * a1 + sum1;  m1 = mn1;
        #pragma unroll
        for (int g = 0; g < 8; g++) {
            o[g][0] *= a0; o[g][1] *= a0;
            o[g][2] *= a1; o[g][3] *= a1;
        }

        // ---- O += P V (P split in-register, V via ldmatrix.trans) ----
        #pragma unroll
        for (int c = 0; c < 4; c++) {
            uint32_t pha[4], pla[4];
            split2(s[2*c][0],   s[2*c][1],   pha[0], pla[0]);
            split2(s[2*c][2],   s[2*c][3],   pha[1], pla[1]);
            split2(s[2*c+1][0], s[2*c+1][1], pha[2], pla[2]);
            split2(s[2*c+1][2], s[2*c+1][3], pha[3], pla[3]);

            uint32_t vh[4][4], vl[4][4];
            const uint32_t rbase = (uint32_t)((16 * c + vrowb) * 128);
            #pragma unroll
            for (int jd = 0; jd < 4; jd++) {
                const int ch = 2 * jd + vchh;
                const uint32_t off = rbase + ((ch ^ sx) << 4);
                LDSM4T(vh[jd], bVh + off);
                LDSM4T(vl[jd], bVl + off);
            }
            #pragma unroll
            for (int jd = 0; jd < 4; jd++) {
                MMA_BF16(o[2*jd],   pha, vh[jd]);
                MMA_BF16(o[2*jd+1], pha, vh[jd] + 2);
            }
            #pragma unroll
            for (int jd = 0; jd < 4; jd++) {
                MMA_BF16(o[2*jd],   pha, vl[jd]);
                MMA_BF16(o[2*jd+1], pha, vl[jd] + 2);
            }
            #pragma unroll
            for (int jd = 0; jd < 4; jd++) {
                MMA_BF16(o[2*jd],   pla, vh[jd]);
                MMA_BF16(o[2*jd+1], pla, vh[jd] + 2);
            }
        }

        __syncthreads();   // stage (kt&1) consumed before overwrite
    }

    // ---- epilogue: normalize, split, store hi/lo for the Wo GEMM ----
    const float i0 = 1.0f / l0, i1 = 1.0f / l1;
    const int qr = q0 + 16 * wid + (lane >> 2);
    const size_t ob = ((size_t)(b * SEQ + qr)) * EMB + h * DKH + 2 * (lane & 3);
    #pragma unroll
    for (int g = 0; g < 8; g++) {
        uint32_t hu, lu;
        split2(o[g][0] * i0, o[g][1] * i0, hu, lu);
        *(uint32_t*)(Oh + ob + 8 * g) = hu;
        *(uint32_t*)(Ol + ob + 8 * g) = lu;
        split2(o[g][2] * i1, o[g][3] * i1, hu, lu);
        *(uint32_t*)(Oh + ob + 8 * (size_t)EMB + 8 * g) = hu;
        *(uint32_t*)(Ol + ob + 8 * (size_t)EMB + 8 * g) = lu;
    }
}

// ---------------------------------------------------------------------------
extern "C" void kernel_launch(void* const* d_in, const int* in_sizes, int n_in,
                              void* d_out, int out_size)
{
    (void)in_sizes; (void)n_in; (void)out_size;
    const float*         query  = (const float*)d_in[0];
    const float*         key    = (const float*)d_in[1];
    const float*         value  = (const float*)d_in[2];
    const unsigned char* masked = (const unsigned char*)d_in[3];
    const float*         Wq     = (const float*)d_in[4];
    const float*         Wk     = (const float*)d_in[5];
    const float*         Wv     = (const float*)d_in[6];
    const float*         Wo     = (const float*)d_in[7];
    float*               out    = (float*)d_out;

    __nv_bfloat16 *gqh, *gql, *gkh, *gkl, *gvh, *gvl, *goh, *gol;
    __nv_bfloat16 *gxh, *gxl, *gwth, *gwtl;
    unsigned char *gm8;
    cudaGetSymbolAddress((void**)&gqh,  g_qh);
    cudaGetSymbolAddress((void**)&gql,  g_ql);
    cudaGetSymbolAddress((void**)&gkh,  g_kh);
    cudaGetSymbolAddress((void**)&gkl,  g_kl);
    cudaGetSymbolAddress((void**)&gvh,  g_vh);
    cudaGetSymbolAddress((void**)&gvl,  g_vl);
    cudaGetSymbolAddress((void**)&goh,  g_oh);
    cudaGetSymbolAddress((void**)&gol,  g_ol);
    cudaGetSymbolAddress((void**)&gxh,  g_xh);
    cudaGetSymbolAddress((void**)&gxl,  g_xl);
    cudaGetSymbolAddress((void**)&gwth, g_wth);
    cudaGetSymbolAddress((void**)&gwtl, g_wtl);
    cudaGetSymbolAddress((void**)&gm8,  g_m8);

    const size_t XN = (size_t)MROWS * EMB;
    const size_t WN = (size_t)EMB * EMB;

    cudaFuncSetAttribute(mha_mma_gemm3,
                         cudaFuncAttributeMaxDynamicSharedMemorySize, GSM_TOTAL);
    cudaFuncSetAttribute(mha_mma_gemm_f32,
                         cudaFuncAttributeMaxDynamicSharedMemorySize, GSM_TOTAL);
    cudaFuncSetAttribute(mha_attn_mma,
                         cudaFuncAttributeMaxDynamicSharedMemorySize, ASM_TOTAL);

    const int n4 = MROWS * EMB / 4;

    mha_detect_mask_kernel<<<1, 256>>>(masked);

    // 4 weight transposes+splits in one launch
    WsplitArgs wa;
    wa.W[0] = Wq; wa.W[1] = Wk; wa.W[2] = Wv; wa.W[3] = Wo;
    for (int z = 0; z < 4; z++) { wa.th[z] = gwth + z * WN; wa.tl[z] = gwtl + z * WN; }
    dim3 w_grid(EMB / 32, EMB / 32, 4), w_blk(32, 8);
    mha_wsplit4_kernel<<<w_grid, w_blk>>>(wa);

    // 3 input splits in one launch
    SplitArgs sa;
    sa.x[0] = (const float4*)query; sa.x[1] = (const float4*)key; sa.x[2] = (const float4*)value;
    for (int z = 0; z < 3; z++) {
        sa.hi[z] = (uint32_t*)(gxh + z * XN);
        sa.lo[z] = (uint32_t*)(gxl + z * XN);
    }
    dim3 s_grid((n4 + 255) / 256, 1, 3);
    mha_split3_kernel<<<s_grid, 256>>>(sa, n4);

    // mask -> uint8
    const int mn4 = BATCH * SEQ * SEQ / 4;
    mha_mask8_kernel<<<(mn4 + 255) / 256, 256>>>(masked, gm8, mn4);

    // 3 projections in one launch
    Gemm3Args ga;
    for (int z = 0; z < 3; z++) {
        ga.Ah[z] = gxh + z * XN;  ga.Al[z] = gxl + z * XN;
        ga.Bh[z] = gwth + z * WN; ga.Bl[z] = gwtl + z * WN;
    }
    ga.Ch[0] = gqh; ga.Cl[0] = gql;
    ga.Ch[1] = gkh; ga.Cl[1] = gkl;
    ga.Ch[2] = gvh; ga.Cl[2] = gvl;
    dim3 g3(EMB / 128, MROWS / 128, 3);
    mha_mma_gemm3<<<g3, 256, GSM_TOTAL>>>(ga);

    // attention (writes split output for Wo GEMM)
    dim3 attn_grid(SEQ / BR, BATCH * HEADS);
    mha_attn_mma<<<attn_grid, 256, ASM_TOTAL>>>(gqh, gql, gkh, gkl, gvh, gvl,
                                                gm8, goh, gol);

    // output projection (fp32 out)
    dim3 g1(EMB / 128, MROWS / 128);
    mha_mma_gemm_f32<<<g1, 256, GSM_TOTAL>>>(goh, gol, gwth + 3 * WN, gwtl + 3 * WN, out);
}

// round 7
// speedup vs baseline: 2.7839x; 1.0081x over previous
#include <cuda_runtime.h>
#include <cuda_bf16.h>
#include <cstdint>

#define BATCH 2
#define SEQ   2048
#define EMB   1024
#define HEADS 16
#define DKH   64
#define NEGV  (-1.0e9f)
#define SCALE 0.125f
#define MROWS (BATCH*SEQ)     // 4096

// ---------------------------------------------------------------------------
// Scratch — __device__ globals per allocation rules.
// ---------------------------------------------------------------------------
__device__ __nv_bfloat16 g_qh [MROWS*EMB];
__device__ __nv_bfloat16 g_ql [MROWS*EMB];
__device__ __nv_bfloat16 g_kh [MROWS*EMB];
__device__ __nv_bfloat16 g_kl [MROWS*EMB];
__device__ __nv_bfloat16 g_vh [MROWS*EMB];
__device__ __nv_bfloat16 g_vl [MROWS*EMB];
__device__ __nv_bfloat16 g_xh [3][MROWS*EMB];  // q/k/v input splits (hi)
__device__ __nv_bfloat16 g_xl [3][MROWS*EMB];  // q/k/v input splits (lo)
__device__ __nv_bfloat16 g_oh [MROWS*EMB];     // attention out hi
__device__ __nv_bfloat16 g_ol [MROWS*EMB];     // attention out lo
__device__ __nv_bfloat16 g_wth[4][EMB*EMB];    // weight^T splits hi [N][K]
__device__ __nv_bfloat16 g_wtl[4][EMB*EMB];    // weight^T splits lo [N][K]
__device__ unsigned char g_m8 [BATCH*SEQ*SEQ];
__device__ int   g_mask_is_i32;

// ---------------------------------------------------------------------------
// PTX helpers (compute_100-safe baseline ISA: mma.sync / ldmatrix / cp.async)
// ---------------------------------------------------------------------------
__device__ __forceinline__ uint32_t smem_u32(const void* p) {
    uint32_t a;
    asm("{ .reg .u64 t; cvta.to.shared.u64 t, %1; cvt.u32.u64 %0, t; }"
        : "=r"(a) : "l"(p));
    return a;
}

#define LDSM4(r, addr) \
    asm volatile("ldmatrix.sync.aligned.m8n8.x4.shared.b16 {%0,%1,%2,%3}, [%4];" \
        : "=r"((r)[0]), "=r"((r)[1]), "=r"((r)[2]), "=r"((r)[3]) : "r"(addr))
#define LDSM4T(r, addr) \
    asm volatile("ldmatrix.sync.aligned.m8n8.x4.trans.shared.b16 {%0,%1,%2,%3}, [%4];" \
        : "=r"((r)[0]), "=r"((r)[1]), "=r"((r)[2]), "=r"((r)[3]) : "r"(addr))

#define MMA_BF16(d, a, b) \
    asm volatile("mma.sync.aligned.m16n8k16.row.col.f32.bf16.bf16.f32 " \
        "{%0,%1,%2,%3}, {%4,%5,%6,%7}, {%8,%9}, {%0,%1,%2,%3};" \
        : "+f"((d)[0]), "+f"((d)[1]), "+f"((d)[2]), "+f"((d)[3]) \
        : "r"((a)[0]), "r"((a)[1]), "r"((a)[2]), "r"((a)[3]), \
          "r"((b)[0]), "r"((b)[1]))

#define CP_ASYNC16(sa, gp) \
    asm volatile("{\n\t.reg .u64 gpt;\n\tcvta.to.global.u64 gpt, %1;\n\t" \
        "cp.async.cg.shared.global [%0], [gpt], 16;\n\t}" \
        :: "r"(sa), "l"(gp))
#define CP_COMMIT()  asm volatile("cp.async.commit_group;" ::: "memory")
#define CP_WAIT0()   asm volatile("cp.async.wait_group 0;" ::: "memory")
#define CP_WAIT1()   asm volatile("cp.async.wait_group 1;" ::: "memory")

// fp32 pair -> packed bf16x2 hi and lo (2-term split)
__device__ __forceinline__ void split2(float x, float y, uint32_t& hi, uint32_t& lo)
{
    __nv_bfloat16 hx = __float2bfloat16(x), hy = __float2bfloat16(y);
    __nv_bfloat16 lx = __float2bfloat16(x - __bfloat162float(hx));
    __nv_bfloat16 ly = __float2bfloat16(y - __bfloat162float(hy));
    __nv_bfloat162 H(hx, hy), L(lx, ly);
    hi = *reinterpret_cast<uint32_t*>(&H);
    lo = *reinterpret_cast<uint32_t*>(&L);
}

// ---------------------------------------------------------------------------
// Mask representation detection (parallel).
// ---------------------------------------------------------------------------
__global__ void mha_detect_mask_kernel(const unsigned char* __restrict__ m)
{
    int s = 0;
    for (int i = threadIdx.x; i < 4096; i += 256)
        if ((i & 3) != 0) s |= m[i];
    int any = __syncthreads_or(s);
    if (threadIdx.x == 0)
        g_mask_is_i32 = (any == 0) ? 1 : 0;
}

// mask -> uint8
__global__ __launch_bounds__(256)
void mha_mask8_kernel(const unsigned char* __restrict__ m,
                      unsigned char* __restrict__ o, int n4)
{
    int i = blockIdx.x * 256 + threadIdx.x;
    if (i >= n4) return;
    if (g_mask_is_i32) {
        int4 w = ((const int4*)m)[i];
        uchar4 u;
        u.x = (unsigned char)w.x; u.y = (unsigned char)w.y;
        u.z = (unsigned char)w.z; u.w = (unsigned char)w.w;
        ((uchar4*)o)[i] = u;
    } else {
        ((uchar4*)o)[i] = ((const uchar4*)m)[i];
    }
}

// ---------------------------------------------------------------------------
// fp32 -> (bf16 hi, bf16 lo) split, 3 tensors in one launch (z selects).
// ---------------------------------------------------------------------------
struct SplitArgs {
    const float4* x[3];
    uint32_t* hi[3];
    uint32_t* lo[3];
};

__global__ __launch_bounds__(256)
void mha_split3_kernel(SplitArgs p, int n4)
{
    int i = blockIdx.x * 256 + threadIdx.x;
    if (i >= n4) return;
    const int z = blockIdx.z;
    float4 v = p.x[z][i];
    uint32_t h0, l0, h1, l1;
    split2(v.x, v.y, h0, l0);
    split2(v.z, v.w, h1, l1);
    p.hi[z][2 * i + 0] = h0;
    p.hi[z][2 * i + 1] = h1;
    p.lo[z][2 * i + 0] = l0;
    p.lo[z][2 * i + 1] = l1;
}

// ---------------------------------------------------------------------------
// Weight transpose + split: W[K,N] fp32 -> Wt hi/lo [N,K] bf16, 4 weights.
// ---------------------------------------------------------------------------
struct WsplitArgs {
    const float* W[4];
    __nv_bfloat16* th[4];
    __nv_bfloat16* tl[4];
};

__global__ __launch_bounds__(256)
void mha_wsplit4_kernel(WsplitArgs p)
{
    __shared__ float t[32][33];
    const int z  = blockIdx.z;
    const float* W = p.W[z];
    const int n  = blockIdx.x * 32 + threadIdx.x;
    const int k0 = blockIdx.y * 32;
    #pragma unroll
    for (int r = 0; r < 32; r += 8)
        t[threadIdx.y + r][threadIdx.x] = W[(size_t)(k0 + threadIdx.y + r) * EMB + n];
    __syncthreads();
    #pragma unroll
    for (int r = 0; r < 32; r += 8) {
        float v = t[threadIdx.x][threadIdx.y + r];
        int on = blockIdx.x * 32 + threadIdx.y + r;
        int ok = k0 + threadIdx.x;
        __nv_bfloat16 h = __float2bfloat16(v);
        p.th[z][(size_t)on * EMB + ok] = h;
        p.tl[z][(size_t)on * EMB + ok] = __float2bfloat16(v - __bfloat162float(h));
    }
}

// ---------------------------------------------------------------------------
// Tensor-core GEMM body. TERM-OUTER MMA ordering: same-accumulator revisits
// are spaced 16 MMAs apart (vs 1 before) to avoid tensor-pipe RAW stalls.
// ---------------------------------------------------------------------------
#define KC        32
#define ROWB      80
#define TILE_SB   (128 * ROWB)
#define STAGE_SB  (4 * TILE_SB)
#define GSM_TOTAL (2 * STAGE_SB)      // 81920

__device__ __forceinline__ void cp_tile(const __nv_bfloat16* __restrict__ g,
                                        int row0, int kb, uint32_t sdst, int tid)
{
    #pragma unroll
    for (int p = 0; p < 2; p++) {
        int f = tid + p * 256;
        int r = f >> 2, ch = f & 3;
        const __nv_bfloat16* gp = g + (size_t)(row0 + r) * EMB + kb + ch * 8;
        uint32_t sa = sdst + r * ROWB + ch * 16;
        CP_ASYNC16(sa, gp);
    }
}

__device__ __forceinline__ void gemm_main(const __nv_bfloat16* Ah, const __nv_bfloat16* Al,
                                          const __nv_bfloat16* Bh, const __nv_bfloat16* Bl,
                                          uint32_t sb, int m0, int n0,
                                          int tid, int lane, int wm, int wn,
                                          float acc[4][4][4])
{
    cp_tile(Ah, m0, 0, sb + 0 * TILE_SB, tid);
    cp_tile(Al, m0, 0, sb + 1 * TILE_SB, tid);
    cp_tile(Bh, n0, 0, sb + 2 * TILE_SB, tid);
    cp_tile(Bl, n0, 0, sb + 3 * TILE_SB, tid);
    CP_COMMIT();

    const int NS = EMB / KC;
    for (int s = 0; s < NS; s++) {
        CP_WAIT0();
        __syncthreads();

        if (s + 1 < NS) {
            const uint32_t nb = sb + ((s + 1) & 1) * STAGE_SB;
            const int kb = (s + 1) * KC;
            cp_tile(Ah, m0, kb, nb + 0 * TILE_SB, tid);
            cp_tile(Al, m0, kb, nb + 1 * TILE_SB, tid);
            cp_tile(Bh, n0, kb, nb + 2 * TILE_SB, tid);
            cp_tile(Bl, n0, kb, nb + 3 * TILE_SB, tid);
            CP_COMMIT();
        }

        const uint32_t abase = sb + (s & 1) * STAGE_SB;
        const uint32_t bbase = abase + 2 * TILE_SB;

        #pragma unroll
        for (int ks = 0; ks < 2; ks++) {
            uint32_t ah[4][4], al[4][4];
            #pragma unroll
            for (int mt = 0; mt < 4; mt++) {
                const int row = wm * 64 + mt * 16 + (lane & 15);
                const int ch  = ks * 2 + (lane >> 4);
                const uint32_t ad = abase + row * ROWB + ch * 16;
                LDSM4(ah[mt], ad);
                LDSM4(al[mt], ad + TILE_SB);
            }
            uint32_t bh[4][2], bl[4][2];
            #pragma unroll
            for (int g = 0; g < 2; g++) {
                const int row = wn * 32 + g * 16 + (lane & 7) + ((lane >> 4) << 3);
                const int ch  = ks * 2 + ((lane >> 3) & 1);
                const uint32_t bd = bbase + row * ROWB + ch * 16;
                uint32_t t[4];
                LDSM4(t, bd);
                bh[2*g][0] = t[0]; bh[2*g][1] = t[1];
                bh[2*g+1][0] = t[2]; bh[2*g+1][1] = t[3];
                LDSM4(t, bd + TILE_SB);
                bl[2*g][0] = t[0]; bl[2*g][1] = t[1];
                bl[2*g+1][0] = t[2]; bl[2*g+1][1] = t[3];
            }
            // term-outer: each accumulator revisited only every 16 MMAs
            #pragma unroll
            for (int mt = 0; mt < 4; mt++)
                #pragma unroll
                for (int nt = 0; nt < 4; nt++)
                    MMA_BF16(acc[mt][nt], ah[mt], bh[nt]);
            #pragma unroll
            for (int mt = 0; mt < 4; mt++)
                #pragma unroll
                for (int nt = 0; nt < 4; nt++)
                    MMA_BF16(acc[mt][nt], ah[mt], bl[nt]);
            #pragma unroll
            for (int mt = 0; mt < 4; mt++)
                #pragma unroll
                for (int nt = 0; nt < 4; nt++)
                    MMA_BF16(acc[mt][nt], al[mt], bh[nt]);
        }
        __syncthreads();
    }
}

// merged Q/K/V projections
struct Gemm3Args {
    const __nv_bfloat16 *Ah[3], *Al[3], *Bh[3], *Bl[3];
    __nv_bfloat16 *Ch[3], *Cl[3];
};

__global__ __launch_bounds__(256)
void mha_mma_gemm3(Gemm3Args p)
{
    extern __shared__ char smem[];
    const uint32_t sb = smem_u32(smem);
    const int tid  = threadIdx.x;
    const int wid  = tid >> 5;
    const int lane = tid & 31;
    const int wm   = wid & 1;
    const int wn   = wid >> 1;
    const int m0   = blockIdx.y * 128;
    const int n0   = blockIdx.x * 128;
    const int z    = blockIdx.z;

    float acc[4][4][4];
    #pragma unroll
    for (int mt = 0; mt < 4; mt++)
        #pragma unroll
        for (int nt = 0; nt < 4; nt++)
            #pragma unroll
            for (int e = 0; e < 4; e++) acc[mt][nt][e] = 0.0f;

    gemm_main(p.Ah[z], p.Al[z], p.Bh[z], p.Bl[z], sb, m0, n0, tid, lane, wm, wn, acc);

    __nv_bfloat16* Ch = p.Ch[z];
    __nv_bfloat16* Cl = p.Cl[z];
    #pragma unroll
    for (int mt = 0; mt < 4; mt++) {
        const int r0 = m0 + wm * 64 + mt * 16 + (lane >> 2);
        #pragma unroll
        for (int nt = 0; nt < 4; nt++) {
            const int c0 = n0 + wn * 32 + nt * 8 + 2 * (lane & 3);
            uint32_t hu, lu;
            split2(acc[mt][nt][0], acc[mt][nt][1], hu, lu);
            *(uint32_t*)(Ch + (size_t)r0 * EMB + c0) = hu;
            *(uint32_t*)(Cl + (size_t)r0 * EMB + c0) = lu;
            split2(acc[mt][nt][2], acc[mt][nt][3], hu, lu);
            *(uint32_t*)(Ch + (size_t)(r0 + 8) * EMB + c0) = hu;
            *(uint32_t*)(Cl + (size_t)(r0 + 8) * EMB + c0) = lu;
        }
    }
}

// single GEMM with fp32 output (Wo projection)
__global__ __launch_bounds__(256)
void mha_mma_gemm_f32(const __nv_bfloat16* __restrict__ Ah,
                      const __nv_bfloat16* __restrict__ Al,
                      const __nv_bfloat16* __restrict__ Bh,
                      const __nv_bfloat16* __restrict__ Bl,
                      float* __restrict__ C)
{
    extern __shared__ char smem[];
    const uint32_t sb = smem_u32(smem);
    const int tid  = threadIdx.x;
    const int wid  = tid >> 5;
    const int lane = tid & 31;
    const int wm   = wid & 1;
    const int wn   = wid >> 1;
    const int m0   = blockIdx.y * 128;
    const int n0   = blockIdx.x * 128;

    float acc[4][4][4];
    #pragma unroll
    for (int mt = 0; mt < 4; mt++)
        #pragma unroll
        for (int nt = 0; nt < 4; nt++)
            #pragma unroll
            for (int e = 0; e < 4; e++) acc[mt][nt][e] = 0.0f;

    gemm_main(Ah, Al, Bh, Bl, sb, m0, n0, tid, lane, wm, wn, acc);

    #pragma unroll
    for (int mt = 0; mt < 4; mt++) {
        const int r0 = m0 + wm * 64 + mt * 16 + (lane >> 2);
        #pragma unroll
        for (int nt = 0; nt < 4; nt++) {
            const int c0 = n0 + wn * 32 + nt * 8 + 2 * (lane & 3);
            *(float2*)(C + (size_t)r0 * EMB + c0)       = make_float2(acc[mt][nt][0], acc[mt][nt][1]);
            *(float2*)(C + (size_t)(r0 + 8) * EMB + c0) = make_float2(acc[mt][nt][2], acc[mt][nt][3]);
        }
    }
}

// ---------------------------------------------------------------------------
// Flash attention on mma.sync bf16, BC=64, 2 CTAs/SM, LEAN REGISTERS:
// Q fragments reloaded from smem per kc (no persistent preload) so the
// 128-reg cap of __launch_bounds__(256,2) holds without spills.
// ---------------------------------------------------------------------------
#define BR  128
#define BC  64
#define NKT (SEQ / BC)        // 32
#define AQH 0
#define AQL 16384
#define AST 32768
#define KVT 8192              // one 64x64 bf16 tile
#define ASTAGE (4 * KVT)      // 32768
#define ASM_TOTAL (AST + 2 * ASTAGE)   // 98304

__device__ __forceinline__ void att_cp_q(const __nv_bfloat16* __restrict__ g,
                                         uint32_t sbase, int tid)
{
    #pragma unroll
    for (int p = 0; p < 4; p++) {
        int f = tid + p * 256;
        int r = f >> 3, ch = f & 7;
        const __nv_bfloat16* gp = g + (size_t)r * EMB + ch * 8;
        uint32_t sa = sbase + r * 128 + ((ch ^ (r & 7)) << 4);
        CP_ASYNC16(sa, gp);
    }
}

__device__ __forceinline__ void att_cp_kv(const __nv_bfloat16* __restrict__ g,
                                          uint32_t sbase, int tid)
{
    #pragma unroll
    for (int p = 0; p < 2; p++) {
        int f = tid + p * 256;
        int r = f >> 3, ch = f & 7;
        const __nv_bfloat16* gp = g + (size_t)r * EMB + ch * 8;
        uint32_t sa = sbase + r * 128 + ((ch ^ (r & 7)) << 4);
        CP_ASYNC16(sa, gp);
    }
}

__global__ __launch_bounds__(256, 2)
void mha_attn_mma(const __nv_bfloat16* __restrict__ Qh, const __nv_bfloat16* __restrict__ Ql,
                  const __nv_bfloat16* __restrict__ Kh, const __nv_bfloat16* __restrict__ Kl,
                  const __nv_bfloat16* __restrict__ Vh, const __nv_bfloat16* __restrict__ Vl,
                  const unsigned char* __restrict__ mask8,
                  __nv_bfloat16* __restrict__ Oh, __nv_bfloat16* __restrict__ Ol)
{
    extern __shared__ char smem[];
    const uint32_t sb = smem_u32(smem);
    const int tid = threadIdx.x, wid = tid >> 5, lane = tid & 31;
    const int q0 = blockIdx.x * BR;
    const int b  = blockIdx.y >> 4, h = blockIdx.y & 15;

    const size_t qoff   = ((size_t)(b * SEQ + q0)) * EMB + h * DKH;
    const size_t kvbase = ((size_t)b * SEQ) * EMB + h * DKH;

    att_cp_q(Qh + qoff, sb + AQH, tid);
    att_cp_q(Ql + qoff, sb + AQL, tid);
    att_cp_kv(Kh + kvbase, sb + AST + 0 * KVT, tid);
    att_cp_kv(Kl + kvbase, sb + AST + 1 * KVT, tid);
    att_cp_kv(Vh + kvbase, sb + AST + 2 * KVT, tid);
    att_cp_kv(Vl + kvbase, sb + AST + 3 * KVT, tid);
    CP_COMMIT();
    CP_WAIT0();
    __syncthreads();

    // Q fragment addressing (loads per kc inside the loop — lean registers)
    const int qrow   = 16 * wid + (lane & 15);
    const uint32_t qhbase = sb + AQH + qrow * 128;
    const uint32_t qlbase = sb + AQL + qrow * 128;
    const int qrow7  = qrow & 7;
    const int qchh   = lane >> 4;

    const int sx    = lane & 7;
    const int krow  = (lane & 7) + ((lane & 16) ? 8 : 0);
    const int kchh  = (lane >> 3) & 1;
    const int vrowb = (lane & 7) + ((lane & 8) ? 8 : 0);
    const int vchh  = (lane & 16) ? 1 : 0;

    float o[8][4];
    #pragma unroll
    for (int g = 0; g < 8; g++)
        #pragma unroll
        for (int e = 0; e < 4; e++) o[g][e] = 0.0f;
    float m0 = __int_as_float(0xff800000);
    float m1 = __int_as_float(0xff800000);
    float l0 = 0.0f, l1 = 0.0f;

    const unsigned char* mb0 = mask8 +
        ((size_t)(b * SEQ + q0 + 16 * wid + (lane >> 2))) * SEQ + 2 * (lane & 3);
    const unsigned char* mb1 = mb0 + 8 * SEQ;

    for (int kt = 0; kt < NKT; kt++) {
        if (kt + 1 < NKT) {
            const size_t kv = kvbase + (size_t)(kt + 1) * BC * EMB;
            const uint32_t nb = sb + AST + ((kt + 1) & 1) * ASTAGE;
            att_cp_kv(Kh + kv, nb + 0 * KVT, tid);
            att_cp_kv(Kl + kv, nb + 1 * KVT, tid);
            att_cp_kv(Vh + kv, nb + 2 * KVT, tid);
            att_cp_kv(Vl + kv, nb + 3 * KVT, tid);
            CP_COMMIT();
            CP_WAIT1();
        } else {
            CP_WAIT0();
        }
        __syncthreads();

        const uint32_t bKh = sb + AST + (kt & 1) * ASTAGE;
        const uint32_t bKl = bKh + KVT;
        const uint32_t bVh = bKh + 2 * KVT;
        const uint32_t bVl = bKh + 3 * KVT;

        // ---- S = Q K^T ----
        float s[8][4];
        #pragma unroll
        for (int g = 0; g < 8; g++)
            #pragma unroll
            for (int e = 0; e < 4; e++) s[g][e] = 0.0f;

        #pragma unroll
        for (int kc = 0; kc < 4; kc++) {
            uint32_t qfh[4], qfl[4];
            {
                const int ch = 2 * kc + qchh;
                const uint32_t po = (uint32_t)((ch ^ qrow7) << 4);
                LDSM4(qfh, qhbase + po);
                LDSM4(qfl, qlbase + po);
            }
            #pragma unroll
            for (int jp = 0; jp < 2; jp++) {
                uint32_t kh0[4], kl0[4], kh1[4], kl1[4];
                const int ch = 2 * kc + kchh;
                const uint32_t pc = (uint32_t)((ch ^ sx) << 4);
                const uint32_t o0 = (uint32_t)((32 * jp + krow) * 128) + pc;
                const uint32_t o1 = o0 + 16 * 128;
                LDSM4(kh0, bKh + o0);
                LDSM4(kl0, bKl + o0);
                LDSM4(kh1, bKh + o1);
                LDSM4(kl1, bKl + o1);
                MMA_BF16(s[4*jp+0], qfh, kh0);
                MMA_BF16(s[4*jp+1], qfh, kh0 + 2);
                MMA_BF16(s[4*jp+2], qfh, kh1);
                MMA_BF16(s[4*jp+3], qfh, kh1 + 2);
                MMA_BF16(s[4*jp+0], qfh, kl0);
                MMA_BF16(s[4*jp+1], qfh, kl0 + 2);
                MMA_BF16(s[4*jp+2], qfh, kl1);
                MMA_BF16(s[4*jp+3], qfh, kl1 + 2);
                MMA_BF16(s[4*jp+0], qfl, kh0);
                MMA_BF16(s[4*jp+1], qfl, kh0 + 2);
                MMA_BF16(s[4*jp+2], qfl, kh1);
                MMA_BF16(s[4*jp+3], qfl, kh1 + 2);
            }
        }

        // ---- scale + mask ----
        const unsigned char* mr0 = mb0 + (size_t)kt * BC;
        const unsigned char* mr1 = mb1 + (size_t)kt * BC;
        #pragma unroll
        for (int g = 0; g < 8; g++) {
            uchar2 u0 = *(const uchar2*)(mr0 + 8 * g);
            uchar2 u1 = *(const uchar2*)(mr1 + 8 * g);
            s[g][0] = u0.x ? NEGV : s[g][0] * SCALE;
            s[g][1] = u0.y ? NEGV : s[g][1] * SCALE;
            s[g][2] = u1.x ? NEGV : s[g][2] * SCALE;
            s[g][3] = u1.y ? NEGV : s[g][3] * SCALE;
        }

        // ---- online softmax ----
        float mx0 = NEGV * 2.0f, mx1 = NEGV * 2.0f;
        #pragma unroll
        for (int g = 0; g < 8; g++) {
            mx0 = fmaxf(mx0, fmaxf(s[g][0], s[g][1]));
            mx1 = fmaxf(mx1, fmaxf(s[g][2], s[g][3]));
        }
        mx0 = fmaxf(mx0, __shfl_xor_sync(0xffffffffu, mx0, 1));
        mx0 = fmaxf(mx0, __shfl_xor_sync(0xffffffffu, mx0, 2));
        mx1 = fmaxf(mx1, __shfl_xor_sync(0xffffffffu, mx1, 1));
        mx1 = fmaxf(mx1, __shfl_xor_sync(0xffffffffu, mx1, 2));
        const float mn0 = fmaxf(m0, mx0), mn1 = fmaxf(m1, mx1);
        const float a0 = __expf(m0 - mn0), a1 = __expf(m1 - mn1);
        float sum0 = 0.0f, sum1 = 0.0f;
        #pragma unroll
        for (int g = 0; g < 8; g++) {
            s[g][0] = __expf(s[g][0] - mn0);
            s[g][1] = __expf(s[g][1] - mn0);
            s[g][2] = __expf(s[g][2] - mn1);
            s[g][3] = __expf(s[g][3] - mn1);
            sum0 += s[g][0] + s[g][1];
            sum1 += s[g][2] + s[g][3];
        }
        sum0 += __shfl_xor_sync(0xffffffffu, sum0, 1);
        sum0 += __shfl_xor_sync(0xffffffffu, sum0, 2);
        sum1 += __shfl_xor_sync(0xffffffffu, sum1, 1);
        sum1 += __shfl_xor_sync(0xffffffffu, sum1, 2);
        l0 = l0 * a0 + sum0;  m0 = mn0;
        l1 = l1 * a1 + sum1;  m1 = mn1;
        #pragma unroll
        for (int g = 0; g < 8; g++) {
            o[g][0] *= a0; o[g][1] *= a0;
            o[g][2] *= a1; o[g][3] *= a1;
        }

        // ---- O += P V ----
        #pragma unroll
        for (int c = 0; c < 4; c++) {
            uint32_t pha[4], pla[4];
            split2(s[2*c][0],   s[2*c][1],   pha[0], pla[0]);
            split2(s[2*c][2],   s[2*c][3],   pha[1], pla[1]);
            split2(s[2*c+1][0], s[2*c+1][1], pha[2], pla[2]);
            split2(s[2*c+1][2], s[2*c+1][3], pha[3], pla[3]);

            uint32_t vh[4][4], vl[4][4];
            const uint32_t rbase = (uint32_t)((16 * c + vrowb) * 128);
            #pragma unroll
            for (int jd = 0; jd < 4; jd++) {
                const int ch = 2 * jd + vchh;
                const uint32_t off = rbase + ((ch ^ sx) << 4);
                LDSM4T(vh[jd], bVh + off);
                LDSM4T(vl[jd], bVl + off);
            }
            #pragma unroll
            for (int jd = 0; jd < 4; jd++) {
                MMA_BF16(o[2*jd],   pha, vh[jd]);
                MMA_BF16(o[2*jd+1], pha, vh[jd] + 2);
            }
            #pragma unroll
            for (int jd = 0; jd < 4; jd++) {
                MMA_BF16(o[2*jd],   pha, vl[jd]);
                MMA_BF16(o[2*jd+1], pha, vl[jd] + 2);
            }
            #pragma unroll
            for (int jd = 0; jd < 4; jd++) {
                MMA_BF16(o[2*jd],   pla, vh[jd]);
                MMA_BF16(o[2*jd+1], pla, vh[jd] + 2);
            }
        }

        __syncthreads();
    }

    // ---- epilogue ----
    const float i0 = 1.0f / l0, i1 = 1.0f / l1;
    const int qr = q0 + 16 * wid + (lane >> 2);
    const size_t ob = ((size_t)(b * SEQ + qr)) * EMB + h * DKH + 2 * (lane & 3);
    #pragma unroll
    for (int g = 0; g < 8; g++) {
        uint32_t hu, lu;
        split2(o[g][0] * i0, o[g][1] * i0, hu, lu);
        *(uint32_t*)(Oh + ob + 8 * g) = hu;
        *(uint32_t*)(Ol + ob + 8 * g) = lu;
        split2(o[g][2] * i1, o[g][3] * i1, hu, lu);
        *(uint32_t*)(Oh + ob + 8 * (size_t)EMB + 8 * g) = hu;
        *(uint32_t*)(Ol + ob + 8 * (size_t)EMB + 8 * g) = lu;
    }
}

// ---------------------------------------------------------------------------
extern "C" void kernel_launch(void* const* d_in, const int* in_sizes, int n_in,
                              void* d_out, int out_size)
{
    (void)in_sizes; (void)n_in; (void)out_size;
    const float*         query  = (const float*)d_in[0];
    const float*         key    = (const float*)d_in[1];
    const float*         value  = (const float*)d_in[2];
    const unsigned char* masked = (const unsigned char*)d_in[3];
    const float*         Wq     = (const float*)d_in[4];
    const float*         Wk     = (const float*)d_in[5];
    const float*         Wv     = (const float*)d_in[6];
    const float*         Wo     = (const float*)d_in[7];
    float*               out    = (float*)d_out;

    __nv_bfloat16 *gqh, *gql, *gkh, *gkl, *gvh, *gvl, *goh, *gol;
    __nv_bfloat16 *gxh, *gxl, *gwth, *gwtl;
    unsigned char *gm8;
    cudaGetSymbolAddress((void**)&gqh,  g_qh);
    cudaGetSymbolAddress((void**)&gql,  g_ql);
    cudaGetSymbolAddress((void**)&gkh,  g_kh);
    cudaGetSymbolAddress((void**)&gkl,  g_kl);
    cudaGetSymbolAddress((void**)&gvh,  g_vh);
    cudaGetSymbolAddress((void**)&gvl,  g_vl);
    cudaGetSymbolAddress((void**)&goh,  g_oh);
    cudaGetSymbolAddress((void**)&gol,  g_ol);
    cudaGetSymbolAddress((void**)&gxh,  g_xh);
    cudaGetSymbolAddress((void**)&gxl,  g_xl);
    cudaGetSymbolAddress((void**)&gwth, g_wth);
    cudaGetSymbolAddress((void**)&gwtl, g_wtl);
    cudaGetSymbolAddress((void**)&gm8,  g_m8);

    const size_t XN = (size_t)MROWS * EMB;
    const size_t WN = (size_t)EMB * EMB;

    cudaFuncSetAttribute(mha_mma_gemm3,
                         cudaFuncAttributeMaxDynamicSharedMemorySize, GSM_TOTAL);
    cudaFuncSetAttribute(mha_mma_gemm_f32,
                         cudaFuncAttributeMaxDynamicSharedMemorySize, GSM_TOTAL);
    cudaFuncSetAttribute(mha_attn_mma,
                         cudaFuncAttributeMaxDynamicSharedMemorySize, ASM_TOTAL);

    const int n4 = MROWS * EMB / 4;

    mha_detect_mask_kernel<<<1, 256>>>(masked);

    WsplitArgs wa;
    wa.W[0] = Wq; wa.W[1] = Wk; wa.W[2] = Wv; wa.W[3] = Wo;
    for (int z = 0; z < 4; z++) { wa.th[z] = gwth + z * WN; wa.tl[z] = gwtl + z * WN; }
    dim3 w_grid(EMB / 32, EMB / 32, 4), w_blk(32, 8);
    mha_wsplit4_kernel<<<w_grid, w_blk>>>(wa);

    SplitArgs sa;
    sa.x[0] = (const float4*)query; sa.x[1] = (const float4*)key; sa.x[2] = (const float4*)value;
    for (int z = 0; z < 3; z++) {
        sa.hi[z] = (uint32_t*)(gxh + z * XN);
        sa.lo[z] = (uint32_t*)(gxl + z * XN);
    }
    dim3 s_grid((n4 + 255) / 256, 1, 3);
    mha_split3_kernel<<<s_grid, 256>>>(sa, n4);

    const int mn4 = BATCH * SEQ * SEQ / 4;
    mha_mask8_kernel<<<(mn4 + 255) / 256, 256>>>(masked, gm8, mn4);

    Gemm3Args ga;
    for (int z = 0; z < 3; z++) {
        ga.Ah[z] = gxh + z * XN;  ga.Al[z] = gxl + z * XN;
        ga.Bh[z] = gwth + z * WN; ga.Bl[z] = gwtl + z * WN;
    }
    ga.Ch[0] = gqh; ga.Cl[0] = gql;
    ga.Ch[1] = gkh; ga.Cl[1] = gkl;
    ga.Ch[2] = gvh; ga.Cl[2] = gvl;
    dim3 g3(EMB / 128, MROWS / 128, 3);
    mha_mma_gemm3<<<g3, 256, GSM_TOTAL>>>(ga);

    dim3 attn_grid(SEQ / BR, BATCH * HEADS);
    mha_attn_mma<<<attn_grid, 256, ASM_TOTAL>>>(gqh, gql, gkh, gkl, gvh, gvl,
                                                gm8, goh, gol);

    dim3 g1(EMB / 128, MROWS / 128);
    mha_mma_gemm_f32<<<g1, 256, GSM_TOTAL>>>(goh, gol, gwth + 3 * WN, gwtl + 3 * WN, out);
}

// round 8
// speedup vs baseline: 2.8794x; 1.0343x over previous
#include <cuda_runtime.h>
#include <cuda_bf16.h>
#include <cstdint>

#define BATCH 2
#define SEQ   2048
#define EMB   1024
#define HEADS 16
#define DKH   64
#define NEGV  (-1.0e9f)
#define SCALE 0.125f
#define MROWS (BATCH*SEQ)     // 4096

// ---------------------------------------------------------------------------
// Scratch — __device__ globals per allocation rules.
// ---------------------------------------------------------------------------
__device__ __nv_bfloat16 g_qh [MROWS*EMB];
__device__ __nv_bfloat16 g_ql [MROWS*EMB];
__device__ __nv_bfloat16 g_kh [MROWS*EMB];
__device__ __nv_bfloat16 g_kl [MROWS*EMB];
__device__ __nv_bfloat16 g_vh [MROWS*EMB];
__device__ __nv_bfloat16 g_vl [MROWS*EMB];
__device__ __nv_bfloat16 g_xh [3][MROWS*EMB];
__device__ __nv_bfloat16 g_xl [3][MROWS*EMB];
__device__ __nv_bfloat16 g_oh [MROWS*EMB];
__device__ __nv_bfloat16 g_ol [MROWS*EMB];
__device__ __nv_bfloat16 g_wth[4][EMB*EMB];
__device__ __nv_bfloat16 g_wtl[4][EMB*EMB];
__device__ unsigned char g_m8 [BATCH*SEQ*SEQ];
__device__ int   g_mask_is_i32;

// ---------------------------------------------------------------------------
// PTX helpers
// ---------------------------------------------------------------------------
__device__ __forceinline__ uint32_t smem_u32(const void* p) {
    uint32_t a;
    asm("{ .reg .u64 t; cvta.to.shared.u64 t, %1; cvt.u32.u64 %0, t; }"
        : "=r"(a) : "l"(p));
    return a;
}

#define LDSM4(r, addr) \
    asm volatile("ldmatrix.sync.aligned.m8n8.x4.shared.b16 {%0,%1,%2,%3}, [%4];" \
        : "=r"((r)[0]), "=r"((r)[1]), "=r"((r)[2]), "=r"((r)[3]) : "r"(addr))
#define LDSM4T(r, addr) \
    asm volatile("ldmatrix.sync.aligned.m8n8.x4.trans.shared.b16 {%0,%1,%2,%3}, [%4];" \
        : "=r"((r)[0]), "=r"((r)[1]), "=r"((r)[2]), "=r"((r)[3]) : "r"(addr))

#define MMA_BF16(d, a, b) \
    asm volatile("mma.sync.aligned.m16n8k16.row.col.f32.bf16.bf16.f32 " \
        "{%0,%1,%2,%3}, {%4,%5,%6,%7}, {%8,%9}, {%0,%1,%2,%3};" \
        : "+f"((d)[0]), "+f"((d)[1]), "+f"((d)[2]), "+f"((d)[3]) \
        : "r"((a)[0]), "r"((a)[1]), "r"((a)[2]), "r"((a)[3]), \
          "r"((b)[0]), "r"((b)[1]))

#define CP_ASYNC16(sa, gp) \
    asm volatile("{\n\t.reg .u64 gpt;\n\tcvta.to.global.u64 gpt, %1;\n\t" \
        "cp.async.cg.shared.global [%0], [gpt], 16;\n\t}" \
        :: "r"(sa), "l"(gp))
#define CP_COMMIT()  asm volatile("cp.async.commit_group;" ::: "memory")
#define CP_WAIT0()   asm volatile("cp.async.wait_group 0;" ::: "memory")
#define CP_WAIT1()   asm volatile("cp.async.wait_group 1;" ::: "memory")

__device__ __forceinline__ void split2(float x, float y, uint32_t& hi, uint32_t& lo)
{
    __nv_bfloat16 hx = __float2bfloat16(x), hy = __float2bfloat16(y);
    __nv_bfloat16 lx = __float2bfloat16(x - __bfloat162float(hx));
    __nv_bfloat16 ly = __float2bfloat16(y - __bfloat162float(hy));
    __nv_bfloat162 H(hx, hy), L(lx, ly);
    hi = *reinterpret_cast<uint32_t*>(&H);
    lo = *reinterpret_cast<uint32_t*>(&L);
}

// ---------------------------------------------------------------------------
// Prep kernels (unchanged)
// ---------------------------------------------------------------------------
__global__ void mha_detect_mask_kernel(const unsigned char* __restrict__ m)
{
    int s = 0;
    for (int i = threadIdx.x; i < 4096; i += 256)
        if ((i & 3) != 0) s |= m[i];
    int any = __syncthreads_or(s);
    if (threadIdx.x == 0)
        g_mask_is_i32 = (any == 0) ? 1 : 0;
}

__global__ __launch_bounds__(256)
void mha_mask8_kernel(const unsigned char* __restrict__ m,
                      unsigned char* __restrict__ o, int n4)
{
    int i = blockIdx.x * 256 + threadIdx.x;
    if (i >= n4) return;
    if (g_mask_is_i32) {
        int4 w = ((const int4*)m)[i];
        uchar4 u;
        u.x = (unsigned char)w.x; u.y = (unsigned char)w.y;
        u.z = (unsigned char)w.z; u.w = (unsigned char)w.w;
        ((uchar4*)o)[i] = u;
    } else {
        ((uchar4*)o)[i] = ((const uchar4*)m)[i];
    }
}

struct SplitArgs {
    const float4* x[3];
    uint32_t* hi[3];
    uint32_t* lo[3];
};

__global__ __launch_bounds__(256)
void mha_split3_kernel(SplitArgs p, int n4)
{
    int i = blockIdx.x * 256 + threadIdx.x;
    if (i >= n4) return;
    const int z = blockIdx.z;
    float4 v = p.x[z][i];
    uint32_t h0, l0, h1, l1;
    split2(v.x, v.y, h0, l0);
    split2(v.z, v.w, h1, l1);
    p.hi[z][2 * i + 0] = h0;
    p.hi[z][2 * i + 1] = h1;
    p.lo[z][2 * i + 0] = l0;
    p.lo[z][2 * i + 1] = l1;
}

struct WsplitArgs {
    const float* W[4];
    __nv_bfloat16* th[4];
    __nv_bfloat16* tl[4];
};

__global__ __launch_bounds__(256)
void mha_wsplit4_kernel(WsplitArgs p)
{
    __shared__ float t[32][33];
    const int z  = blockIdx.z;
    const float* W = p.W[z];
    const int n  = blockIdx.x * 32 + threadIdx.x;
    const int k0 = blockIdx.y * 32;
    #pragma unroll
    for (int r = 0; r < 32; r += 8)
        t[threadIdx.y + r][threadIdx.x] = W[(size_t)(k0 + threadIdx.y + r) * EMB + n];
    __syncthreads();
    #pragma unroll
    for (int r = 0; r < 32; r += 8) {
        float v = t[threadIdx.x][threadIdx.y + r];
        int on = blockIdx.x * 32 + threadIdx.y + r;
        int ok = k0 + threadIdx.x;
        __nv_bfloat16 h = __float2bfloat16(v);
        p.th[z][(size_t)on * EMB + ok] = h;
        p.tl[z][(size_t)on * EMB + ok] = __float2bfloat16(v - __bfloat162float(h));
    }
}

// ---------------------------------------------------------------------------
// GEMM: CTA 128x256, warp tile 64x64 (2m x 4n warps), KC=32.
// Tiles stored with 64-byte rows; swizzle: chunk ch -> ch ^ ((r>>1)&3)
// (rows 0..7 map to 8 distinct 16B bank columns; conflict-free for STS
// and all ldmatrix phases).
// Stage: Ah(8K) Al(8K) Bh(16K) Bl(16K) = 48KB, double buffered = 96KB.
// ---------------------------------------------------------------------------
#define KC        32
#define A_TSB     8192
#define B_TSB     16384
#define STAGE_SB  (2*A_TSB + 2*B_TSB)   // 49152
#define GSM_TOTAL (2 * STAGE_SB)        // 98304

#define GSWZ(r, ch) ((uint32_t)((r) * 64 + ((((ch) ^ (((r) >> 1) & 3))) << 4)))

// A tile: 128 rows x 32 bf16 (512 16B-chunks -> 2 per thread)
__device__ __forceinline__ void cp_tile_a(const __nv_bfloat16* __restrict__ g,
                                          int row0, int kb, uint32_t sdst, int tid)
{
    #pragma unroll
    for (int p = 0; p < 2; p++) {
        int f = tid + p * 256;
        int r = f >> 2, ch = f & 3;
        const __nv_bfloat16* gp = g + (size_t)(row0 + r) * EMB + kb + ch * 8;
        CP_ASYNC16(sdst + GSWZ(r, ch), gp);
    }
}

// B tile: 256 rows x 32 bf16 (1024 chunks -> 4 per thread)
__device__ __forceinline__ void cp_tile_b(const __nv_bfloat16* __restrict__ g,
                                          int row0, int kb, uint32_t sdst, int tid)
{
    #pragma unroll
    for (int p = 0; p < 4; p++) {
        int f = tid + p * 256;
        int r = f >> 2, ch = f & 3;
        const __nv_bfloat16* gp = g + (size_t)(row0 + r) * EMB + kb + ch * 8;
        CP_ASYNC16(sdst + GSWZ(r, ch), gp);
    }
}

__device__ __forceinline__ void gemm_main(const __nv_bfloat16* Ah, const __nv_bfloat16* Al,
                                          const __nv_bfloat16* Bh, const __nv_bfloat16* Bl,
                                          uint32_t sb, int m0, int n0,
                                          int tid, int lane, int wm, int wn,
                                          float acc[4][8][4])
{
    cp_tile_a(Ah, m0, 0, sb, tid);
    cp_tile_a(Al, m0, 0, sb + A_TSB, tid);
    cp_tile_b(Bh, n0, 0, sb + 2 * A_TSB, tid);
    cp_tile_b(Bl, n0, 0, sb + 2 * A_TSB + B_TSB, tid);
    CP_COMMIT();

    const int NS = EMB / KC;           // 32
    for (int s = 0; s < NS; s++) {
        CP_WAIT0();
        __syncthreads();

        if (s + 1 < NS) {
            const uint32_t nb = sb + ((s + 1) & 1) * STAGE_SB;
            const int kb = (s + 1) * KC;
            cp_tile_a(Ah, m0, kb, nb, tid);
            cp_tile_a(Al, m0, kb, nb + A_TSB, tid);
            cp_tile_b(Bh, n0, kb, nb + 2 * A_TSB, tid);
            cp_tile_b(Bl, n0, kb, nb + 2 * A_TSB + B_TSB, tid);
            CP_COMMIT();
        }

        const uint32_t abase = sb + (s & 1) * STAGE_SB;
        const uint32_t bbase = abase + 2 * A_TSB;

        #pragma unroll
        for (int ks = 0; ks < 2; ks++) {
            uint32_t ah[4][4], al[4][4];
            {
                const int ch = ks * 2 + (lane >> 4);
                #pragma unroll
                for (int mt = 0; mt < 4; mt++) {
                    const int row = wm * 64 + mt * 16 + (lane & 15);
                    const uint32_t ad = abase + GSWZ(row, ch);
                    LDSM4(ah[mt], ad);
                    LDSM4(al[mt], ad + A_TSB);
                }
            }
            #pragma unroll
            for (int ntp = 0; ntp < 4; ntp++) {
                const int row = wn * 64 + ntp * 16 + (lane & 7) + ((lane >> 4) << 3);
                const int ch  = ks * 2 + ((lane >> 3) & 1);
                const uint32_t bd = bbase + GSWZ(row, ch);
                uint32_t tb[4], tl[4];
                LDSM4(tb, bd);
                LDSM4(tl, bd + B_TSB);
                const int n0t = 2 * ntp, n1t = 2 * ntp + 1;
                // term order hh, hl, lh -> same-acc spacing 8 MMAs
                #pragma unroll
                for (int mt = 0; mt < 4; mt++) {
                    MMA_BF16(acc[mt][n0t], ah[mt], tb);
                    MMA_BF16(acc[mt][n1t], ah[mt], tb + 2);
                }
                #pragma unroll
                for (int mt = 0; mt < 4; mt++) {
                    MMA_BF16(acc[mt][n0t], ah[mt], tl);
                    MMA_BF16(acc[mt][n1t], ah[mt], tl + 2);
                }
                #pragma unroll
                for (int mt = 0; mt < 4; mt++) {
                    MMA_BF16(acc[mt][n0t], al[mt], tb);
                    MMA_BF16(acc[mt][n1t], al[mt], tb + 2);
                }
            }
        }
        __syncthreads();
    }
}

struct Gemm3Args {
    const __nv_bfloat16 *Ah[3], *Al[3], *Bh[3], *Bl[3];
    __nv_bfloat16 *Ch[3], *Cl[3];
};

__global__ __launch_bounds__(256, 1)
void mha_mma_gemm3(Gemm3Args p)
{
    extern __shared__ char smem[];
    const uint32_t sb = smem_u32(smem);
    const int tid  = threadIdx.x;
    const int wid  = tid >> 5;
    const int lane = tid & 31;
    const int wm   = wid & 1;
    const int wn   = wid >> 1;
    const int m0   = blockIdx.y * 128;
    const int n0   = blockIdx.x * 256;
    const int z    = blockIdx.z;

    float acc[4][8][4];
    #pragma unroll
    for (int mt = 0; mt < 4; mt++)
        #pragma unroll
        for (int nt = 0; nt < 8; nt++)
            #pragma unroll
            for (int e = 0; e < 4; e++) acc[mt][nt][e] = 0.0f;

    gemm_main(p.Ah[z], p.Al[z], p.Bh[z], p.Bl[z], sb, m0, n0, tid, lane, wm, wn, acc);

    __nv_bfloat16* Ch = p.Ch[z];
    __nv_bfloat16* Cl = p.Cl[z];
    #pragma unroll
    for (int mt = 0; mt < 4; mt++) {
        const int r0 = m0 + wm * 64 + mt * 16 + (lane >> 2);
        #pragma unroll
        for (int nt = 0; nt < 8; nt++) {
            const int c0 = n0 + wn * 64 + nt * 8 + 2 * (lane & 3);
            uint32_t hu, lu;
            split2(acc[mt][nt][0], acc[mt][nt][1], hu, lu);
            *(uint32_t*)(Ch + (size_t)r0 * EMB + c0) = hu;
            *(uint32_t*)(Cl + (size_t)r0 * EMB + c0) = lu;
            split2(acc[mt][nt][2], acc[mt][nt][3], hu, lu);
            *(uint32_t*)(Ch + (size_t)(r0 + 8) * EMB + c0) = hu;
            *(uint32_t*)(Cl + (size_t)(r0 + 8) * EMB + c0) = lu;
        }
    }
}

__global__ __launch_bounds__(256, 1)
void mha_mma_gemm_f32(const __nv_bfloat16* __restrict__ Ah,
                      const __nv_bfloat16* __restrict__ Al,
                      const __nv_bfloat16* __restrict__ Bh,
                      const __nv_bfloat16* __restrict__ Bl,
                      float* __restrict__ C)
{
    extern __shared__ char smem[];
    const uint32_t sb = smem_u32(smem);
    const int tid  = threadIdx.x;
    const int wid  = tid >> 5;
    const int lane = tid & 31;
    const int wm   = wid & 1;
    const int wn   = wid >> 1;
    const int m0   = blockIdx.y * 128;
    const int n0   = blockIdx.x * 256;

    float acc[4][8][4];
    #pragma unroll
    for (int mt = 0; mt < 4; mt++)
        #pragma unroll
        for (int nt = 0; nt < 8; nt++)
            #pragma unroll
            for (int e = 0; e < 4; e++) acc[mt][nt][e] = 0.0f;

    gemm_main(Ah, Al, Bh, Bl, sb, m0, n0, tid, lane, wm, wn, acc);

    #pragma unroll
    for (int mt = 0; mt < 4; mt++) {
        const int r0 = m0 + wm * 64 + mt * 16 + (lane >> 2);
        #pragma unroll
        for (int nt = 0; nt < 8; nt++) {
            const int c0 = n0 + wn * 64 + nt * 8 + 2 * (lane & 3);
            *(float2*)(C + (size_t)r0 * EMB + c0)       = make_float2(acc[mt][nt][0], acc[mt][nt][1]);
            *(float2*)(C + (size_t)(r0 + 8) * EMB + c0) = make_float2(acc[mt][nt][2], acc[mt][nt][3]);
        }
    }
}

// ---------------------------------------------------------------------------
// Flash attention: BR=256, BC=64. Warp owns 32 q-rows as two 16-row halves
// that SHARE every K and V fragment load (2x fragment reuse vs BR=128).
// smem: Qh,Ql 32KB each + 2 stages x 32KB = 128KB; 1 CTA/SM.
// ---------------------------------------------------------------------------
#define BR  256
#define BC  64
#define NKT (SEQ / BC)        // 32
#define AQH 0
#define AQL 32768
#define AST 65536
#define KVT 8192
#define ASTAGE (4 * KVT)      // 32768
#define ASM_TOTAL (AST + 2 * ASTAGE)   // 131072

// Q tile: 256 rows x 128B (2048 chunks -> 8/thread); 128B-row swizzle ch^(r&7)
__device__ __forceinline__ void att_cp_q(const __nv_bfloat16* __restrict__ g,
                                         uint32_t sbase, int tid)
{
    #pragma unroll
    for (int p = 0; p < 8; p++) {
        int f = tid + p * 256;
        int r = f >> 3, ch = f & 7;
        const __nv_bfloat16* gp = g + (size_t)r * EMB + ch * 8;
        uint32_t sa = sbase + r * 128 + ((ch ^ (r & 7)) << 4);
        CP_ASYNC16(sa, gp);
    }
}

__device__ __forceinline__ void att_cp_kv(const __nv_bfloat16* __restrict__ g,
                                          uint32_t sbase, int tid)
{
    #pragma unroll
    for (int p = 0; p < 2; p++) {
        int f = tid + p * 256;
        int r = f >> 3, ch = f & 7;
        const __nv_bfloat16* gp = g + (size_t)r * EMB + ch * 8;
        uint32_t sa = sbase + r * 128 + ((ch ^ (r & 7)) << 4);
        CP_ASYNC16(sa, gp);
    }
}

__global__ __launch_bounds__(256, 1)
void mha_attn_mma(const __nv_bfloat16* __restrict__ Qh, const __nv_bfloat16* __restrict__ Ql,
                  const __nv_bfloat16* __restrict__ Kh, const __nv_bfloat16* __restrict__ Kl,
                  const __nv_bfloat16* __restrict__ Vh, const __nv_bfloat16* __restrict__ Vl,
                  const unsigned char* __restrict__ mask8,
                  __nv_bfloat16* __restrict__ Oh, __nv_bfloat16* __restrict__ Ol)
{
    extern __shared__ char smem[];
    const uint32_t sb = smem_u32(smem);
    const int tid = threadIdx.x, wid = tid >> 5, lane = tid & 31;
    const int q0 = blockIdx.x * BR;
    const int b  = blockIdx.y >> 4, h = blockIdx.y & 15;

    const size_t qoff   = ((size_t)(b * SEQ + q0)) * EMB + h * DKH;
    const size_t kvbase = ((size_t)b * SEQ) * EMB + h * DKH;

    att_cp_q(Qh + qoff, sb + AQH, tid);
    att_cp_q(Ql + qoff, sb + AQL, tid);
    att_cp_kv(Kh + kvbase, sb + AST + 0 * KVT, tid);
    att_cp_kv(Kl + kvbase, sb + AST + 1 * KVT, tid);
    att_cp_kv(Vh + kvbase, sb + AST + 2 * KVT, tid);
    att_cp_kv(Vl + kvbase, sb + AST + 3 * KVT, tid);
    CP_COMMIT();
    CP_WAIT0();
    __syncthreads();

    // Q addressing for the two 16-row halves (rows 32w+u*16+(lane&15))
    const int qrow0 = 32 * wid + (lane & 15);      // half 0
    const int q7    = qrow0 & 7;                   // same for half 1 (+16)
    const uint32_t qhb0 = sb + AQH + qrow0 * 128;
    const uint32_t qlb0 = sb + AQL + qrow0 * 128;
    const uint32_t qhb1 = qhb0 + 16 * 128;
    const uint32_t qlb1 = qlb0 + 16 * 128;
    const int qchh = lane >> 4;

    const int sx    = lane & 7;
    const int krow  = (lane & 7) + ((lane & 16) ? 8 : 0);
    const int kchh  = (lane >> 3) & 1;
    const int vrowb = (lane & 7) + ((lane & 8) ? 8 : 0);
    const int vchh  = (lane & 16) ? 1 : 0;

    float o[2][8][4];
    float s[2][8][4];
    #pragma unroll
    for (int u = 0; u < 2; u++)
        #pragma unroll
        for (int g = 0; g < 8; g++)
            #pragma unroll
            for (int e = 0; e < 4; e++) o[u][g][e] = 0.0f;
    float rm[2][2], rl[2][2];
    #pragma unroll
    for (int u = 0; u < 2; u++) {
        rm[u][0] = __int_as_float(0xff800000);
        rm[u][1] = __int_as_float(0xff800000);
        rl[u][0] = 0.0f; rl[u][1] = 0.0f;
    }

    // mask base: row (q0 + 32w + lane>>2), col 2*(lane&3); halves at +u*16*SEQ
    const unsigned char* mbase = mask8 +
        ((size_t)(b * SEQ + q0 + 32 * wid + (lane >> 2))) * SEQ + 2 * (lane & 3);

    for (int kt = 0; kt < NKT; kt++) {
        if (kt + 1 < NKT) {
            const size_t kv = kvbase + (size_t)(kt + 1) * BC * EMB;
            const uint32_t nb = sb + AST + ((kt + 1) & 1) * ASTAGE;
            att_cp_kv(Kh + kv, nb + 0 * KVT, tid);
            att_cp_kv(Kl + kv, nb + 1 * KVT, tid);
            att_cp_kv(Vh + kv, nb + 2 * KVT, tid);
            att_cp_kv(Vl + kv, nb + 3 * KVT, tid);
            CP_COMMIT();
            CP_WAIT1();
        } else {
            CP_WAIT0();
        }
        __syncthreads();

        const uint32_t bKh = sb + AST + (kt & 1) * ASTAGE;
        const uint32_t bKl = bKh + KVT;
        const uint32_t bVh = bKh + 2 * KVT;
        const uint32_t bVl = bKh + 3 * KVT;

        // ---- S = Q K^T for both halves (K frags loaded ONCE) ----
        #pragma unroll
        for (int u = 0; u < 2; u++)
            #pragma unroll
            for (int g = 0; g < 8; g++)
                #pragma unroll
                for (int e = 0; e < 4; e++) s[u][g][e] = 0.0f;

        #pragma unroll
        for (int kc = 0; kc < 4; kc++) {
            uint32_t qh0[4], ql0[4], qh1[4], ql1[4];
            {
                const int ch = 2 * kc + qchh;
                const uint32_t po = (uint32_t)((ch ^ q7) << 4);
                LDSM4(qh0, qhb0 + po);
                LDSM4(ql0, qlb0 + po);
                LDSM4(qh1, qhb1 + po);
                LDSM4(ql1, qlb1 + po);
            }
            #pragma unroll
            for (int jp = 0; jp < 2; jp++) {
                uint32_t kh0[4], kl0[4], kh1[4], kl1[4];
                const int ch = 2 * kc + kchh;
                const uint32_t pc = (uint32_t)((ch ^ sx) << 4);
                const uint32_t o0 = (uint32_t)((32 * jp + krow) * 128) + pc;
                const uint32_t o1 = o0 + 16 * 128;
                LDSM4(kh0, bKh + o0);
                LDSM4(kl0, bKl + o0);
                LDSM4(kh1, bKh + o1);
                LDSM4(kl1, bKl + o1);
                // hh (both halves)
                MMA_BF16(s[0][4*jp+0], qh0, kh0);
                MMA_BF16(s[0][4*jp+1], qh0, kh0 + 2);
                MMA_BF16(s[0][4*jp+2], qh0, kh1);
                MMA_BF16(s[0][4*jp+3], qh0, kh1 + 2);
                MMA_BF16(s[1][4*jp+0], qh1, kh0);
                MMA_BF16(s[1][4*jp+1], qh1, kh0 + 2);
                MMA_BF16(s[1][4*jp+2], qh1, kh1);
                MMA_BF16(s[1][4*jp+3], qh1, kh1 + 2);
                // hl
                MMA_BF16(s[0][4*jp+0], qh0, kl0);
                MMA_BF16(s[0][4*jp+1], qh0, kl0 + 2);
                MMA_BF16(s[0][4*jp+2], qh0, kl1);
                MMA_BF16(s[0][4*jp+3], qh0, kl1 + 2);
                MMA_BF16(s[1][4*jp+0], qh1, kl0);
                MMA_BF16(s[1][4*jp+1], qh1, kl0 + 2);
                MMA_BF16(s[1][4*jp+2], qh1, kl1);
                MMA_BF16(s[1][4*jp+3], qh1, kl1 + 2);
                // lh
                MMA_BF16(s[0][4*jp+0], ql0, kh0);
                MMA_BF16(s[0][4*jp+1], ql0, kh0 + 2);
                MMA_BF16(s[0][4*jp+2], ql0, kh1);
                MMA_BF16(s[0][4*jp+3], ql0, kh1 + 2);
                MMA_BF16(s[1][4*jp+0], ql1, kh0);
                MMA_BF16(s[1][4*jp+1], ql1, kh0 + 2);
                MMA_BF16(s[1][4*jp+2], ql1, kh1);
                MMA_BF16(s[1][4*jp+3], ql1, kh1 + 2);
            }
        }

        // ---- scale + mask + online softmax per half ----
        #pragma unroll
        for (int u = 0; u < 2; u++) {
            const unsigned char* mr0 = mbase + (size_t)u * 16 * SEQ + (size_t)kt * BC;
            const unsigned char* mr1 = mr0 + 8 * SEQ;
            #pragma unroll
            for (int g = 0; g < 8; g++) {
                uchar2 u0 = *(const uchar2*)(mr0 + 8 * g);
                uchar2 u1 = *(const uchar2*)(mr1 + 8 * g);
                s[u][g][0] = u0.x ? NEGV : s[u][g][0] * SCALE;
                s[u][g][1] = u0.y ? NEGV : s[u][g][1] * SCALE;
                s[u][g][2] = u1.x ? NEGV : s[u][g][2] * SCALE;
                s[u][g][3] = u1.y ? NEGV : s[u][g][3] * SCALE;
            }

            float mx0 = NEGV * 2.0f, mx1 = NEGV * 2.0f;
            #pragma unroll
            for (int g = 0; g < 8; g++) {
                mx0 = fmaxf(mx0, fmaxf(s[u][g][0], s[u][g][1]));
                mx1 = fmaxf(mx1, fmaxf(s[u][g][2], s[u][g][3]));
            }
            mx0 = fmaxf(mx0, __shfl_xor_sync(0xffffffffu, mx0, 1));
            mx0 = fmaxf(mx0, __shfl_xor_sync(0xffffffffu, mx0, 2));
            mx1 = fmaxf(mx1, __shfl_xor_sync(0xffffffffu, mx1, 1));
            mx1 = fmaxf(mx1, __shfl_xor_sync(0xffffffffu, mx1, 2));
            const float mn0 = fmaxf(rm[u][0], mx0), mn1 = fmaxf(rm[u][1], mx1);
            const float a0 = __expf(rm[u][0] - mn0), a1 = __expf(rm[u][1] - mn1);
            float sum0 = 0.0f, sum1 = 0.0f;
            #pragma unroll
            for (int g = 0; g < 8; g++) {
                s[u][g][0] = __expf(s[u][g][0] - mn0);
                s[u][g][1] = __expf(s[u][g][1] - mn0);
                s[u][g][2] = __expf(s[u][g][2] - mn1);
                s[u][g][3] = __expf(s[u][g][3] - mn1);
                sum0 += s[u][g][0] + s[u][g][1];
                sum1 += s[u][g][2] + s[u][g][3];
            }
            sum0 += __shfl_xor_sync(0xffffffffu, sum0, 1);
            sum0 += __shfl_xor_sync(0xffffffffu, sum0, 2);
            sum1 += __shfl_xor_sync(0xffffffffu, sum1, 1);
            sum1 += __shfl_xor_sync(0xffffffffu, sum1, 2);
            rl[u][0] = rl[u][0] * a0 + sum0;  rm[u][0] = mn0;
            rl[u][1] = rl[u][1] * a1 + sum1;  rm[u][1] = mn1;
            #pragma unroll
            for (int g = 0; g < 8; g++) {
                o[u][g][0] *= a0; o[u][g][1] *= a0;
                o[u][g][2] *= a1; o[u][g][3] *= a1;
            }
        }

        // ---- O += P V for both halves (V frags loaded ONCE) ----
        #pragma unroll
        for (int c = 0; c < 4; c++) {
            uint32_t vh[4][4], vl[4][4];
            const uint32_t rbase = (uint32_t)((16 * c + vrowb) * 128);
            #pragma unroll
            for (int jd = 0; jd < 4; jd++) {
                const int ch = 2 * jd + vchh;
                const uint32_t off = rbase + ((ch ^ sx) << 4);
                LDSM4T(vh[jd], bVh + off);
                LDSM4T(vl[jd], bVl + off);
            }
            #pragma unroll
            for (int u = 0; u < 2; u++) {
                uint32_t pha[4], pla[4];
                split2(s[u][2*c][0],   s[u][2*c][1],   pha[0], pla[0]);
                split2(s[u][2*c][2],   s[u][2*c][3],   pha[1], pla[1]);
                split2(s[u][2*c+1][0], s[u][2*c+1][1], pha[2], pla[2]);
                split2(s[u][2*c+1][2], s[u][2*c+1][3], pha[3], pla[3]);
                #pragma unroll
                for (int jd = 0; jd < 4; jd++) {
                    MMA_BF16(o[u][2*jd],   pha, vh[jd]);
                    MMA_BF16(o[u][2*jd+1], pha, vh[jd] + 2);
                }
                #pragma unroll
                for (int jd = 0; jd < 4; jd++) {
                    MMA_BF16(o[u][2*jd],   pha, vl[jd]);
                    MMA_BF16(o[u][2*jd+1], pha, vl[jd] + 2);
                }
                #pragma unroll
                for (int jd = 0; jd < 4; jd++) {
                    MMA_BF16(o[u][2*jd],   pla, vh[jd]);
                    MMA_BF16(o[u][2*jd+1], pla, vh[jd] + 2);
                }
            }
        }

        __syncthreads();
    }

    // ---- epilogue per half ----
    #pragma unroll
    for (int u = 0; u < 2; u++) {
        const float i0 = 1.0f / rl[u][0], i1 = 1.0f / rl[u][1];
        const int qr = q0 + 32 * wid + 16 * u + (lane >> 2);
        const size_t ob = ((size_t)(b * SEQ + qr)) * EMB + h * DKH + 2 * (lane & 3);
        #pragma unroll
        for (int g = 0; g < 8; g++) {
            uint32_t hu, lu;
            split2(o[u][g][0] * i0, o[u][g][1] * i0, hu, lu);
            *(uint32_t*)(Oh + ob + 8 * g) = hu;
            *(uint32_t*)(Ol + ob + 8 * g) = lu;
            split2(o[u][g][2] * i1, o[u][g][3] * i1, hu, lu);
            *(uint32_t*)(Oh + ob + 8 * (size_t)EMB + 8 * g) = hu;
            *(uint32_t*)(Ol + ob + 8 * (size_t)EMB + 8 * g) = lu;
        }
    }
}

// ---------------------------------------------------------------------------
extern "C" void kernel_launch(void* const* d_in, const int* in_sizes, int n_in,
                              void* d_out, int out_size)
{
    (void)in_sizes; (void)n_in; (void)out_size;
    const float*         query  = (const float*)d_in[0];
    const float*         key    = (const float*)d_in[1];
    const float*         value  = (const float*)d_in[2];
    const unsigned char* masked = (const unsigned char*)d_in[3];
    const float*         Wq     = (const float*)d_in[4];
    const float*         Wk     = (const float*)d_in[5];
    const float*         Wv     = (const float*)d_in[6];
    const float*         Wo     = (const float*)d_in[7];
    float*               out    = (float*)d_out;

    __nv_bfloat16 *gqh, *gql, *gkh, *gkl, *gvh, *gvl, *goh, *gol;
    __nv_bfloat16 *gxh, *gxl, *gwth, *gwtl;
    unsigned char *gm8;
    cudaGetSymbolAddress((void**)&gqh,  g_qh);
    cudaGetSymbolAddress((void**)&gql,  g_ql);
    cudaGetSymbolAddress((void**)&gkh,  g_kh);
    cudaGetSymbolAddress((void**)&gkl,  g_kl);
    cudaGetSymbolAddress((void**)&gvh,  g_vh);
    cudaGetSymbolAddress((void**)&gvl,  g_vl);
    cudaGetSymbolAddress((void**)&goh,  g_oh);
    cudaGetSymbolAddress((void**)&gol,  g_ol);
    cudaGetSymbolAddress((void**)&gxh,  g_xh);
    cudaGetSymbolAddress((void**)&gxl,  g_xl);
    cudaGetSymbolAddress((void**)&gwth, g_wth);
    cudaGetSymbolAddress((void**)&gwtl, g_wtl);
    cudaGetSymbolAddress((void**)&gm8,  g_m8);

    const size_t XN = (size_t)MROWS * EMB;
    const size_t WN = (size_t)EMB * EMB;

    cudaFuncSetAttribute(mha_mma_gemm3,
                         cudaFuncAttributeMaxDynamicSharedMemorySize, GSM_TOTAL);
    cudaFuncSetAttribute(mha_mma_gemm_f32,
                         cudaFuncAttributeMaxDynamicSharedMemorySize, GSM_TOTAL);
    cudaFuncSetAttribute(mha_attn_mma,
                         cudaFuncAttributeMaxDynamicSharedMemorySize, ASM_TOTAL);

    const int n4 = MROWS * EMB / 4;

    mha_detect_mask_kernel<<<1, 256>>>(masked);

    WsplitArgs wa;
    wa.W[0] = Wq; wa.W[1] = Wk; wa.W[2] = Wv; wa.W[3] = Wo;
    for (int z = 0; z < 4; z++) { wa.th[z] = gwth + z * WN; wa.tl[z] = gwtl + z * WN; }
    dim3 w_grid(EMB / 32, EMB / 32, 4), w_blk(32, 8);
    mha_wsplit4_kernel<<<w_grid, w_blk>>>(wa);

    SplitArgs sa;
    sa.x[0] = (const float4*)query; sa.x[1] = (const float4*)key; sa.x[2] = (const float4*)value;
    for (int z = 0; z < 3; z++) {
        sa.hi[z] = (uint32_t*)(gxh + z * XN);
        sa.lo[z] = (uint32_t*)(gxl + z * XN);
    }
    dim3 s_grid((n4 + 255) / 256, 1, 3);
    mha_split3_kernel<<<s_grid, 256>>>(sa, n4);

    const int mn4 = BATCH * SEQ * SEQ / 4;
    mha_mask8_kernel<<<(mn4 + 255) / 256, 256>>>(masked, gm8, mn4);

    Gemm3Args ga;
    for (int z = 0; z < 3; z++) {
        ga.Ah[z] = gxh + z * XN;  ga.Al[z] = gxl + z * XN;
        ga.Bh[z] = gwth + z * WN; ga.Bl[z] = gwtl + z * WN;
    }
    ga.Ch[0] = gqh; ga.Cl[0] = gql;
    ga.Ch[1] = gkh; ga.Cl[1] = gkl;
    ga.Ch[2] = gvh; ga.Cl[2] = gvl;
    dim3 g3(EMB / 256, MROWS / 128, 3);     // (4, 32, 3)
    mha_mma_gemm3<<<g3, 256, GSM_TOTAL>>>(ga);

    dim3 attn_grid(SEQ / BR, BATCH * HEADS); // (8, 32)
    mha_attn_mma<<<attn_grid, 256, ASM_TOTAL>>>(gqh, gql, gkh, gkl, gvh, gvl,
                                                gm8, goh, gol);

    dim3 g1(EMB / 256, MROWS / 128);         // (4, 32)
    mha_mma_gemm_f32<<<g1, 256, GSM_TOTAL>>>(goh, gol, gwth + 3 * WN, gwtl + 3 * WN, out);
}

// round 9
// speedup vs baseline: 3.6761x; 1.2767x over previous
#include <cuda_runtime.h>
#include <cuda_fp16.h>
#include <cstdint>

#define BATCH 2
#define SEQ   2048
#define EMB   1024
#define HEADS 16
#define DKH   64
#define NEGV  (-1.0e9f)
#define SCALE 0.125f
#define MROWS (BATCH*SEQ)     // 4096

// ---------------------------------------------------------------------------
// Scratch — __device__ globals per allocation rules. fp16 2-product scheme:
// A-side operands (X, Q, attention-out) split hi/lo; B-side (W, K, V) single.
// ---------------------------------------------------------------------------
__device__ __half g_qh [MROWS*EMB];
__device__ __half g_ql [MROWS*EMB];
__device__ __half g_kh [MROWS*EMB];     // single fp16
__device__ __half g_vh [MROWS*EMB];     // single fp16
__device__ __half g_xh [3][MROWS*EMB];
__device__ __half g_xl [3][MROWS*EMB];
__device__ __half g_oh [MROWS*EMB];
__device__ __half g_ol [MROWS*EMB];
__device__ __half g_wth[4][EMB*EMB];    // weight^T single fp16 [N][K]
__device__ unsigned char g_m8 [BATCH*SEQ*SEQ];
__device__ int   g_mask_is_i32;

// ---------------------------------------------------------------------------
// PTX helpers
// ---------------------------------------------------------------------------
__device__ __forceinline__ uint32_t smem_u32(const void* p) {
    uint32_t a;
    asm("{ .reg .u64 t; cvta.to.shared.u64 t, %1; cvt.u32.u64 %0, t; }"
        : "=r"(a) : "l"(p));
    return a;
}

#define LDSM4(r, addr) \
    asm volatile("ldmatrix.sync.aligned.m8n8.x4.shared.b16 {%0,%1,%2,%3}, [%4];" \
        : "=r"((r)[0]), "=r"((r)[1]), "=r"((r)[2]), "=r"((r)[3]) : "r"(addr))
#define LDSM4T(r, addr) \
    asm volatile("ldmatrix.sync.aligned.m8n8.x4.trans.shared.b16 {%0,%1,%2,%3}, [%4];" \
        : "=r"((r)[0]), "=r"((r)[1]), "=r"((r)[2]), "=r"((r)[3]) : "r"(addr))

#define MMA_F16(d, a, b) \
    asm volatile("mma.sync.aligned.m16n8k16.row.col.f32.f16.f16.f32 " \
        "{%0,%1,%2,%3}, {%4,%5,%6,%7}, {%8,%9}, {%0,%1,%2,%3};" \
        : "+f"((d)[0]), "+f"((d)[1]), "+f"((d)[2]), "+f"((d)[3]) \
        : "r"((a)[0]), "r"((a)[1]), "r"((a)[2]), "r"((a)[3]), \
          "r"((b)[0]), "r"((b)[1]))

#define CP_ASYNC16(sa, gp) \
    asm volatile("{\n\t.reg .u64 gpt;\n\tcvta.to.global.u64 gpt, %1;\n\t" \
        "cp.async.cg.shared.global [%0], [gpt], 16;\n\t}" \
        :: "r"(sa), "l"(gp))
#define CP_COMMIT()  asm volatile("cp.async.commit_group;" ::: "memory")
#define CP_WAIT0()   asm volatile("cp.async.wait_group 0;" ::: "memory")
#define CP_WAIT1()   asm volatile("cp.async.wait_group 1;" ::: "memory")

// fp32 pair -> packed fp16x2 hi and lo (2-term fp16 split, RN)
__device__ __forceinline__ void split2h(float x, float y, uint32_t& hi, uint32_t& lo)
{
    __half hx = __float2half_rn(x), hy = __float2half_rn(y);
    __half lx = __float2half_rn(x - __half2float(hx));
    __half ly = __float2half_rn(y - __half2float(hy));
    __half2 H = __halves2half2(hx, hy), L = __halves2half2(lx, ly);
    hi = *reinterpret_cast<uint32_t*>(&H);
    lo = *reinterpret_cast<uint32_t*>(&L);
}
__device__ __forceinline__ uint32_t pack2h(float x, float y)
{
    __half2 H = __halves2half2(__float2half_rn(x), __float2half_rn(y));
    return *reinterpret_cast<uint32_t*>(&H);
}

// ---------------------------------------------------------------------------
// Prep kernels
// ---------------------------------------------------------------------------
__global__ void mha_detect_mask_kernel(const unsigned char* __restrict__ m)
{
    int s = 0;
    for (int i = threadIdx.x; i < 4096; i += 256)
        if ((i & 3) != 0) s |= m[i];
    int any = __syncthreads_or(s);
    if (threadIdx.x == 0)
        g_mask_is_i32 = (any == 0) ? 1 : 0;
}

__global__ __launch_bounds__(256)
void mha_mask8_kernel(const unsigned char* __restrict__ m,
                      unsigned char* __restrict__ o, int n4)
{
    int i = blockIdx.x * 256 + threadIdx.x;
    if (i >= n4) return;
    if (g_mask_is_i32) {
        int4 w = ((const int4*)m)[i];
        uchar4 u;
        u.x = (unsigned char)w.x; u.y = (unsigned char)w.y;
        u.z = (unsigned char)w.z; u.w = (unsigned char)w.w;
        ((uchar4*)o)[i] = u;
    } else {
        ((uchar4*)o)[i] = ((const uchar4*)m)[i];
    }
}

struct SplitArgs {
    const float4* x[3];
    uint32_t* hi[3];
    uint32_t* lo[3];
};

__global__ __launch_bounds__(256)
void mha_split3_kernel(SplitArgs p, int n4)
{
    int i = blockIdx.x * 256 + threadIdx.x;
    if (i >= n4) return;
    const int z = blockIdx.z;
    float4 v = p.x[z][i];
    uint32_t h0, l0, h1, l1;
    split2h(v.x, v.y, h0, l0);
    split2h(v.z, v.w, h1, l1);
    p.hi[z][2 * i + 0] = h0;
    p.hi[z][2 * i + 1] = h1;
    p.lo[z][2 * i + 0] = l0;
    p.lo[z][2 * i + 1] = l1;
}

// Weight transpose: W[K,N] fp32 -> Wt single fp16 [N,K], 4 weights.
struct WsplitArgs {
    const float* W[4];
    __half* th[4];
};

__global__ __launch_bounds__(256)
void mha_wsplit4_kernel(WsplitArgs p)
{
    __shared__ float t[32][33];
    const int z  = blockIdx.z;
    const float* W = p.W[z];
    const int n  = blockIdx.x * 32 + threadIdx.x;
    const int k0 = blockIdx.y * 32;
    #pragma unroll
    for (int r = 0; r < 32; r += 8)
        t[threadIdx.y + r][threadIdx.x] = W[(size_t)(k0 + threadIdx.y + r) * EMB + n];
    __syncthreads();
    #pragma unroll
    for (int r = 0; r < 32; r += 8) {
        float v = t[threadIdx.x][threadIdx.y + r];
        int on = blockIdx.x * 32 + threadIdx.y + r;
        int ok = k0 + threadIdx.x;
        p.th[z][(size_t)on * EMB + ok] = __float2half_rn(v);
    }
}

// ---------------------------------------------------------------------------
// GEMM: CTA 128x256, warp tile 64x64 (2m x 4n warps), KC=32, fp16 2-product:
//   C = Ah@B + Al@B   (B single fp16)
// Stage: Ah(8K) Al(8K) B(16K) = 32KB, double buffered = 64KB.
// 64-byte rows; swizzle ch -> ch ^ ((r>>1)&3).
// ---------------------------------------------------------------------------
#define KC        32
#define A_TSB     8192
#define B_TSB     16384
#define STAGE_SB  (2*A_TSB + B_TSB)     // 32768
#define GSM_TOTAL (2 * STAGE_SB)        // 65536

#define GSWZ(r, ch) ((uint32_t)((r) * 64 + ((((ch) ^ (((r) >> 1) & 3))) << 4)))

__device__ __forceinline__ void cp_tile_a(const __half* __restrict__ g,
                                          int row0, int kb, uint32_t sdst, int tid)
{
    #pragma unroll
    for (int p = 0; p < 2; p++) {
        int f = tid + p * 256;
        int r = f >> 2, ch = f & 3;
        const __half* gp = g + (size_t)(row0 + r) * EMB + kb + ch * 8;
        CP_ASYNC16(sdst + GSWZ(r, ch), gp);
    }
}

__device__ __forceinline__ void cp_tile_b(const __half* __restrict__ g,
                                          int row0, int kb, uint32_t sdst, int tid)
{
    #pragma unroll
    for (int p = 0; p < 4; p++) {
        int f = tid + p * 256;
        int r = f >> 2, ch = f & 3;
        const __half* gp = g + (size_t)(row0 + r) * EMB + kb + ch * 8;
        CP_ASYNC16(sdst + GSWZ(r, ch), gp);
    }
}

__device__ __forceinline__ void gemm_main(const __half* Ah, const __half* Al,
                                          const __half* B,
                                          uint32_t sb, int m0, int n0,
                                          int tid, int lane, int wm, int wn,
                                          float acc[4][8][4])
{
    cp_tile_a(Ah, m0, 0, sb, tid);
    cp_tile_a(Al, m0, 0, sb + A_TSB, tid);
    cp_tile_b(B,  n0, 0, sb + 2 * A_TSB, tid);
    CP_COMMIT();

    const int NS = EMB / KC;           // 32
    for (int s = 0; s < NS; s++) {
        CP_WAIT0();
        __syncthreads();

        if (s + 1 < NS) {
            const uint32_t nb = sb + ((s + 1) & 1) * STAGE_SB;
            const int kb = (s + 1) * KC;
            cp_tile_a(Ah, m0, kb, nb, tid);
            cp_tile_a(Al, m0, kb, nb + A_TSB, tid);
            cp_tile_b(B,  n0, kb, nb + 2 * A_TSB, tid);
            CP_COMMIT();
        }

        const uint32_t abase = sb + (s & 1) * STAGE_SB;
        const uint32_t bbase = abase + 2 * A_TSB;

        #pragma unroll
        for (int ks = 0; ks < 2; ks++) {
            uint32_t ah[4][4], al[4][4];
            {
                const int ch = ks * 2 + (lane >> 4);
                #pragma unroll
                for (int mt = 0; mt < 4; mt++) {
                    const int row = wm * 64 + mt * 16 + (lane & 15);
                    const uint32_t ad = abase + GSWZ(row, ch);
                    LDSM4(ah[mt], ad);
                    LDSM4(al[mt], ad + A_TSB);
                }
            }
            #pragma unroll
            for (int ntp = 0; ntp < 4; ntp++) {
                const int row = wn * 64 + ntp * 16 + (lane & 7) + ((lane >> 4) << 3);
                const int ch  = ks * 2 + ((lane >> 3) & 1);
                uint32_t tb[4];
                LDSM4(tb, bbase + GSWZ(row, ch));
                const int n0t = 2 * ntp, n1t = 2 * ntp + 1;
                #pragma unroll
                for (int mt = 0; mt < 4; mt++) {
                    MMA_F16(acc[mt][n0t], ah[mt], tb);
                    MMA_F16(acc[mt][n1t], ah[mt], tb + 2);
                }
                #pragma unroll
                for (int mt = 0; mt < 4; mt++) {
                    MMA_F16(acc[mt][n0t], al[mt], tb);
                    MMA_F16(acc[mt][n1t], al[mt], tb + 2);
                }
            }
        }
        __syncthreads();
    }
}

// merged Q/K/V projections; Cl==null -> single fp16 output
struct Gemm3Args {
    const __half *Ah[3], *Al[3], *B[3];
    __half *Ch[3], *Cl[3];
};

__global__ __launch_bounds__(256, 1)
void mha_mma_gemm3(Gemm3Args p)
{
    extern __shared__ char smem[];
    const uint32_t sb = smem_u32(smem);
    const int tid  = threadIdx.x;
    const int wid  = tid >> 5;
    const int lane = tid & 31;
    const int wm   = wid & 1;
    const int wn   = wid >> 1;
    const int m0   = blockIdx.y * 128;
    const int n0   = blockIdx.x * 256;
    const int z    = blockIdx.z;

    float acc[4][8][4];
    #pragma unroll
    for (int mt = 0; mt < 4; mt++)
        #pragma unroll
        for (int nt = 0; nt < 8; nt++)
            #pragma unroll
            for (int e = 0; e < 4; e++) acc[mt][nt][e] = 0.0f;

    gemm_main(p.Ah[z], p.Al[z], p.B[z], sb, m0, n0, tid, lane, wm, wn, acc);

    __half* Ch = p.Ch[z];
    __half* Cl = p.Cl[z];
    if (Cl) {
        #pragma unroll
        for (int mt = 0; mt < 4; mt++) {
            const int r0 = m0 + wm * 64 + mt * 16 + (lane >> 2);
            #pragma unroll
            for (int nt = 0; nt < 8; nt++) {
                const int c0 = n0 + wn * 64 + nt * 8 + 2 * (lane & 3);
                uint32_t hu, lu;
                split2h(acc[mt][nt][0], acc[mt][nt][1], hu, lu);
                *(uint32_t*)(Ch + (size_t)r0 * EMB + c0) = hu;
                *(uint32_t*)(Cl + (size_t)r0 * EMB + c0) = lu;
                split2h(acc[mt][nt][2], acc[mt][nt][3], hu, lu);
                *(uint32_t*)(Ch + (size_t)(r0 + 8) * EMB + c0) = hu;
                *(uint32_t*)(Cl + (size_t)(r0 + 8) * EMB + c0) = lu;
            }
        }
    } else {
        #pragma unroll
        for (int mt = 0; mt < 4; mt++) {
            const int r0 = m0 + wm * 64 + mt * 16 + (lane >> 2);
            #pragma unroll
            for (int nt = 0; nt < 8; nt++) {
                const int c0 = n0 + wn * 64 + nt * 8 + 2 * (lane & 3);
                *(uint32_t*)(Ch + (size_t)r0 * EMB + c0) =
                    pack2h(acc[mt][nt][0], acc[mt][nt][1]);
                *(uint32_t*)(Ch + (size_t)(r0 + 8) * EMB + c0) =
                    pack2h(acc[mt][nt][2], acc[mt][nt][3]);
            }
        }
    }
}

__global__ __launch_bounds__(256, 1)
void mha_mma_gemm_f32(const __half* __restrict__ Ah,
                      const __half* __restrict__ Al,
                      const __half* __restrict__ B,
                      float* __restrict__ C)
{
    extern __shared__ char smem[];
    const uint32_t sb = smem_u32(smem);
    const int tid  = threadIdx.x;
    const int wid  = tid >> 5;
    const int lane = tid & 31;
    const int wm   = wid & 1;
    const int wn   = wid >> 1;
    const int m0   = blockIdx.y * 128;
    const int n0   = blockIdx.x * 256;

    float acc[4][8][4];
    #pragma unroll
    for (int mt = 0; mt < 4; mt++)
        #pragma unroll
        for (int nt = 0; nt < 8; nt++)
            #pragma unroll
            for (int e = 0; e < 4; e++) acc[mt][nt][e] = 0.0f;

    gemm_main(Ah, Al, B, sb, m0, n0, tid, lane, wm, wn, acc);

    #pragma unroll
    for (int mt = 0; mt < 4; mt++) {
        const int r0 = m0 + wm * 64 + mt * 16 + (lane >> 2);
        #pragma unroll
        for (int nt = 0; nt < 8; nt++) {
            const int c0 = n0 + wn * 64 + nt * 8 + 2 * (lane & 3);
            *(float2*)(C + (size_t)r0 * EMB + c0)       = make_float2(acc[mt][nt][0], acc[mt][nt][1]);
            *(float2*)(C + (size_t)(r0 + 8) * EMB + c0) = make_float2(acc[mt][nt][2], acc[mt][nt][3]);
        }
    }
}

// ---------------------------------------------------------------------------
// Flash attention, fp16 2-product: S = Qh@K + Ql@K; O = Ph@V + Pl@V.
// BR=256, BC=64; warp owns 32 q-rows as two 16-row halves sharing K/V frags.
// smem: Qh,Ql 32KB each + 2 stages x (Kh 8K + Vh 8K) = 96KB.
// ---------------------------------------------------------------------------
#define BR  256
#define BC  64
#define NKT (SEQ / BC)        // 32
#define AQH 0
#define AQL 32768
#define AST 65536
#define KVT 8192
#define ASTAGE (2 * KVT)      // 16384
#define ASM_TOTAL (AST + 2 * ASTAGE)   // 98304

__device__ __forceinline__ void att_cp_q(const __half* __restrict__ g,
                                         uint32_t sbase, int tid)
{
    #pragma unroll
    for (int p = 0; p < 8; p++) {
        int f = tid + p * 256;
        int r = f >> 3, ch = f & 7;
        const __half* gp = g + (size_t)r * EMB + ch * 8;
        uint32_t sa = sbase + r * 128 + ((ch ^ (r & 7)) << 4);
        CP_ASYNC16(sa, gp);
    }
}

__device__ __forceinline__ void att_cp_kv(const __half* __restrict__ g,
                                          uint32_t sbase, int tid)
{
    #pragma unroll
    for (int p = 0; p < 2; p++) {
        int f = tid + p * 256;
        int r = f >> 3, ch = f & 7;
        const __half* gp = g + (size_t)r * EMB + ch * 8;
        uint32_t sa = sbase + r * 128 + ((ch ^ (r & 7)) << 4);
        CP_ASYNC16(sa, gp);
    }
}

__global__ __launch_bounds__(256, 1)
void mha_attn_mma(const __half* __restrict__ Qh, const __half* __restrict__ Ql,
                  const __half* __restrict__ K,  const __half* __restrict__ V,
                  const unsigned char* __restrict__ mask8,
                  __half* __restrict__ Oh, __half* __restrict__ Ol)
{
    extern __shared__ char smem[];
    const uint32_t sb = smem_u32(smem);
    const int tid = threadIdx.x, wid = tid >> 5, lane = tid & 31;
    const int q0 = blockIdx.x * BR;
    const int b  = blockIdx.y >> 4, h = blockIdx.y & 15;

    const size_t qoff   = ((size_t)(b * SEQ + q0)) * EMB + h * DKH;
    const size_t kvbase = ((size_t)b * SEQ) * EMB + h * DKH;

    att_cp_q(Qh + qoff, sb + AQH, tid);
    att_cp_q(Ql + qoff, sb + AQL, tid);
    att_cp_kv(K + kvbase, sb + AST + 0 * KVT, tid);
    att_cp_kv(V + kvbase, sb + AST + 1 * KVT, tid);
    CP_COMMIT();
    CP_WAIT0();
    __syncthreads();

    const int qrow0 = 32 * wid + (lane & 15);
    const int q7    = qrow0 & 7;
    const uint32_t qhb0 = sb + AQH + qrow0 * 128;
    const uint32_t qlb0 = sb + AQL + qrow0 * 128;
    const uint32_t qhb1 = qhb0 + 16 * 128;
    const uint32_t qlb1 = qlb0 + 16 * 128;
    const int qchh = lane >> 4;

    const int sx    = lane & 7;
    const int krow  = (lane & 7) + ((lane & 16) ? 8 : 0);
    const int kchh  = (lane >> 3) & 1;
    const int vrowb = (lane & 7) + ((lane & 8) ? 8 : 0);
    const int vchh  = (lane & 16) ? 1 : 0;

    float o[2][8][4];
    float s[2][8][4];
    #pragma unroll
    for (int u = 0; u < 2; u++)
        #pragma unroll
        for (int g = 0; g < 8; g++)
            #pragma unroll
            for (int e = 0; e < 4; e++) o[u][g][e] = 0.0f;
    float rm[2][2], rl[2][2];
    #pragma unroll
    for (int u = 0; u < 2; u++) {
        rm[u][0] = __int_as_float(0xff800000);
        rm[u][1] = __int_as_float(0xff800000);
        rl[u][0] = 0.0f; rl[u][1] = 0.0f;
    }

    const unsigned char* mbase = mask8 +
        ((size_t)(b * SEQ + q0 + 32 * wid + (lane >> 2))) * SEQ + 2 * (lane & 3);

    for (int kt = 0; kt < NKT; kt++) {
        if (kt + 1 < NKT) {
            const size_t kv = kvbase + (size_t)(kt + 1) * BC * EMB;
            const uint32_t nb = sb + AST + ((kt + 1) & 1) * ASTAGE;
            att_cp_kv(K + kv, nb + 0 * KVT, tid);
            att_cp_kv(V + kv, nb + 1 * KVT, tid);
            CP_COMMIT();
            CP_WAIT1();
        } else {
            CP_WAIT0();
        }
        __syncthreads();

        const uint32_t bK = sb + AST + (kt & 1) * ASTAGE;
        const uint32_t bV = bK + KVT;

        // ---- S = Q K^T (2-product), both halves share K fragments ----
        #pragma unroll
        for (int u = 0; u < 2; u++)
            #pragma unroll
            for (int g = 0; g < 8; g++)
                #pragma unroll
                for (int e = 0; e < 4; e++) s[u][g][e] = 0.0f;

        #pragma unroll
        for (int kc = 0; kc < 4; kc++) {
            uint32_t qh0[4], ql0[4], qh1[4], ql1[4];
            {
                const int ch = 2 * kc + qchh;
                const uint32_t po = (uint32_t)((ch ^ q7) << 4);
                LDSM4(qh0, qhb0 + po);
                LDSM4(ql0, qlb0 + po);
                LDSM4(qh1, qhb1 + po);
                LDSM4(ql1, qlb1 + po);
            }
            #pragma unroll
            for (int jp = 0; jp < 2; jp++) {
                uint32_t kf0[4], kf1[4];
                const int ch = 2 * kc + kchh;
                const uint32_t pc = (uint32_t)((ch ^ sx) << 4);
                const uint32_t o0 = (uint32_t)((32 * jp + krow) * 128) + pc;
                const uint32_t o1 = o0 + 16 * 128;
                LDSM4(kf0, bK + o0);
                LDSM4(kf1, bK + o1);
                // term hi (both halves)
                MMA_F16(s[0][4*jp+0], qh0, kf0);
                MMA_F16(s[0][4*jp+1], qh0, kf0 + 2);
                MMA_F16(s[0][4*jp+2], qh0, kf1);
                MMA_F16(s[0][4*jp+3], qh0, kf1 + 2);
                MMA_F16(s[1][4*jp+0], qh1, kf0);
                MMA_F16(s[1][4*jp+1], qh1, kf0 + 2);
                MMA_F16(s[1][4*jp+2], qh1, kf1);
                MMA_F16(s[1][4*jp+3], qh1, kf1 + 2);
                // term lo
                MMA_F16(s[0][4*jp+0], ql0, kf0);
                MMA_F16(s[0][4*jp+1], ql0, kf0 + 2);
                MMA_F16(s[0][4*jp+2], ql0, kf1);
                MMA_F16(s[0][4*jp+3], ql0, kf1 + 2);
                MMA_F16(s[1][4*jp+0], ql1, kf0);
                MMA_F16(s[1][4*jp+1], ql1, kf0 + 2);
                MMA_F16(s[1][4*jp+2], ql1, kf1);
                MMA_F16(s[1][4*jp+3], ql1, kf1 + 2);
            }
        }

        // ---- scale + mask + online softmax per half ----
        #pragma unroll
        for (int u = 0; u < 2; u++) {
            const unsigned char* mr0 = mbase + (size_t)u * 16 * SEQ + (size_t)kt * BC;
            const unsigned char* mr1 = mr0 + 8 * SEQ;
            #pragma unroll
            for (int g = 0; g < 8; g++) {
                uchar2 u0 = *(const uchar2*)(mr0 + 8 * g);
                uchar2 u1 = *(const uchar2*)(mr1 + 8 * g);
                s[u][g][0] = u0.x ? NEGV : s[u][g][0] * SCALE;
                s[u][g][1] = u0.y ? NEGV : s[u][g][1] * SCALE;
                s[u][g][2] = u1.x ? NEGV : s[u][g][2] * SCALE;
                s[u][g][3] = u1.y ? NEGV : s[u][g][3] * SCALE;
            }

            float mx0 = NEGV * 2.0f, mx1 = NEGV * 2.0f;
            #pragma unroll
            for (int g = 0; g < 8; g++) {
                mx0 = fmaxf(mx0, fmaxf(s[u][g][0], s[u][g][1]));
                mx1 = fmaxf(mx1, fmaxf(s[u][g][2], s[u][g][3]));
            }
            mx0 = fmaxf(mx0, __shfl_xor_sync(0xffffffffu, mx0, 1));
            mx0 = fmaxf(mx0, __shfl_xor_sync(0xffffffffu, mx0, 2));
            mx1 = fmaxf(mx1, __shfl_xor_sync(0xffffffffu, mx1, 1));
            mx1 = fmaxf(mx1, __shfl_xor_sync(0xffffffffu, mx1, 2));
            const float mn0 = fmaxf(rm[u][0], mx0), mn1 = fmaxf(rm[u][1], mx1);
            const float a0 = __expf(rm[u][0] - mn0), a1 = __expf(rm[u][1] - mn1);
            float sum0 = 0.0f, sum1 = 0.0f;
            #pragma unroll
            for (int g = 0; g < 8; g++) {
                s[u][g][0] = __expf(s[u][g][0] - mn0);
                s[u][g][1] = __expf(s[u][g][1] - mn0);
                s[u][g][2] = __expf(s[u][g][2] - mn1);
                s[u][g][3] = __expf(s[u][g][3] - mn1);
                sum0 += s[u][g][0] + s[u][g][1];
                sum1 += s[u][g][2] + s[u][g][3];
            }
            sum0 += __shfl_xor_sync(0xffffffffu, sum0, 1);
            sum0 += __shfl_xor_sync(0xffffffffu, sum0, 2);
            sum1 += __shfl_xor_sync(0xffffffffu, sum1, 1);
            sum1 += __shfl_xor_sync(0xffffffffu, sum1, 2);
            rl[u][0] = rl[u][0] * a0 + sum0;  rm[u][0] = mn0;
            rl[u][1] = rl[u][1] * a1 + sum1;  rm[u][1] = mn1;
            #pragma unroll
            for (int g = 0; g < 8; g++) {
                o[u][g][0] *= a0; o[u][g][1] *= a0;
                o[u][g][2] *= a1; o[u][g][3] *= a1;
            }
        }

        // ---- O += P V (2-product; V frags loaded once per c) ----
        #pragma unroll
        for (int c = 0; c < 4; c++) {
            uint32_t vf[4][4];
            const uint32_t rbase = (uint32_t)((16 * c + vrowb) * 128);
            #pragma unroll
            for (int jd = 0; jd < 4; jd++) {
                const int ch = 2 * jd + vchh;
                LDSM4T(vf[jd], bV + rbase + ((ch ^ sx) << 4));
            }
            #pragma unroll
            for (int u = 0; u < 2; u++) {
                uint32_t pha[4], pla[4];
                split2h(s[u][2*c][0],   s[u][2*c][1],   pha[0], pla[0]);
                split2h(s[u][2*c][2],   s[u][2*c][3],   pha[1], pla[1]);
                split2h(s[u][2*c+1][0], s[u][2*c+1][1], pha[2], pla[2]);
                split2h(s[u][2*c+1][2], s[u][2*c+1][3], pha[3], pla[3]);
                #pragma unroll
                for (int jd = 0; jd < 4; jd++) {
                    MMA_F16(o[u][2*jd],   pha, vf[jd]);
                    MMA_F16(o[u][2*jd+1], pha, vf[jd] + 2);
                }
                #pragma unroll
                for (int jd = 0; jd < 4; jd++) {
                    MMA_F16(o[u][2*jd],   pla, vf[jd]);
                    MMA_F16(o[u][2*jd+1], pla, vf[jd] + 2);
                }
            }
        }

        __syncthreads();
    }

    // ---- epilogue per half: normalize, fp16 split for Wo GEMM ----
    #pragma unroll
    for (int u = 0; u < 2; u++) {
        const float i0 = 1.0f / rl[u][0], i1 = 1.0f / rl[u][1];
        const int qr = q0 + 32 * wid + 16 * u + (lane >> 2);
        const size_t ob = ((size_t)(b * SEQ + qr)) * EMB + h * DKH + 2 * (lane & 3);
        #pragma unroll
        for (int g = 0; g < 8; g++) {
            uint32_t hu, lu;
            split2h(o[u][g][0] * i0, o[u][g][1] * i0, hu, lu);
            *(uint32_t*)(Oh + ob + 8 * g) = hu;
            *(uint32_t*)(Ol + ob + 8 * g) = lu;
            split2h(o[u][g][2] * i1, o[u][g][3] * i1, hu, lu);
            *(uint32_t*)(Oh + ob + 8 * (size_t)EMB + 8 * g) = hu;
            *(uint32_t*)(Ol + ob + 8 * (size_t)EMB + 8 * g) = lu;
        }
    }
}

// ---------------------------------------------------------------------------
extern "C" void kernel_launch(void* const* d_in, const int* in_sizes, int n_in,
                              void* d_out, int out_size)
{
    (void)in_sizes; (void)n_in; (void)out_size;
    const float*         query  = (const float*)d_in[0];
    const float*         key    = (const float*)d_in[1];
    const float*         value  = (const float*)d_in[2];
    const unsigned char* masked = (const unsigned char*)d_in[3];
    const float*         Wq     = (const float*)d_in[4];
    const float*         Wk     = (const float*)d_in[5];
    const float*         Wv     = (const float*)d_in[6];
    const float*         Wo     = (const float*)d_in[7];
    float*               out    = (float*)d_out;

    __half *gqh, *gql, *gkh, *gvh, *goh, *gol, *gxh, *gxl, *gwth;
    unsigned char *gm8;
    cudaGetSymbolAddress((void**)&gqh,  g_qh);
    cudaGetSymbolAddress((void**)&gql,  g_ql);
    cudaGetSymbolAddress((void**)&gkh,  g_kh);
    cudaGetSymbolAddress((void**)&gvh,  g_vh);
    cudaGetSymbolAddress((void**)&goh,  g_oh);
    cudaGetSymbolAddress((void**)&gol,  g_ol);
    cudaGetSymbolAddress((void**)&gxh,  g_xh);
    cudaGetSymbolAddress((void**)&gxl,  g_xl);
    cudaGetSymbolAddress((void**)&gwth, g_wth);
    cudaGetSymbolAddress((void**)&gm8,  g_m8);

    const size_t XN = (size_t)MROWS * EMB;
    const size_t WN = (size_t)EMB * EMB;

    cudaFuncSetAttribute(mha_mma_gemm3,
                         cudaFuncAttributeMaxDynamicSharedMemorySize, GSM_TOTAL);
    cudaFuncSetAttribute(mha_mma_gemm_f32,
                         cudaFuncAttributeMaxDynamicSharedMemorySize, GSM_TOTAL);
    cudaFuncSetAttribute(mha_attn_mma,
                         cudaFuncAttributeMaxDynamicSharedMemorySize, ASM_TOTAL);

    const int n4 = MROWS * EMB / 4;

    mha_detect_mask_kernel<<<1, 256>>>(masked);

    WsplitArgs wa;
    wa.W[0] = Wq; wa.W[1] = Wk; wa.W[2] = Wv; wa.W[3] = Wo;
    for (int z = 0; z < 4; z++) wa.th[z] = gwth + z * WN;
    dim3 w_grid(EMB / 32, EMB / 32, 4), w_blk(32, 8);
    mha_wsplit4_kernel<<<w_grid, w_blk>>>(wa);

    SplitArgs sa;
    sa.x[0] = (const float4*)query; sa.x[1] = (const float4*)key; sa.x[2] = (const float4*)value;
    for (int z = 0; z < 3; z++) {
        sa.hi[z] = (uint32_t*)(gxh + z * XN);
        sa.lo[z] = (uint32_t*)(gxl + z * XN);
    }
    dim3 s_grid((n4 + 255) / 256, 1, 3);
    mha_split3_kernel<<<s_grid, 256>>>(sa, n4);

    const int mn4 = BATCH * SEQ * SEQ / 4;
    mha_mask8_kernel<<<(mn4 + 255) / 256, 256>>>(masked, gm8, mn4);

    Gemm3Args ga;
    for (int z = 0; z < 3; z++) {
        ga.Ah[z] = gxh + z * XN;  ga.Al[z] = gxl + z * XN;
        ga.B[z]  = gwth + z * WN;
    }
    ga.Ch[0] = gqh; ga.Cl[0] = gql;
    ga.Ch[1] = gkh; ga.Cl[1] = nullptr;
    ga.Ch[2] = gvh; ga.Cl[2] = nullptr;
    dim3 g3(EMB / 256, MROWS / 128, 3);      // (4, 32, 3)
    mha_mma_gemm3<<<g3, 256, GSM_TOTAL>>>(ga);

    dim3 attn_grid(SEQ / BR, BATCH * HEADS);  // (8, 32)
    mha_attn_mma<<<attn_grid, 256, ASM_TOTAL>>>(gqh, gql, gkh, gvh, gm8, goh, gol);

    dim3 g1(EMB / 256, MROWS / 128);          // (4, 32)
    mha_mma_gemm_f32<<<g1, 256, GSM_TOTAL>>>(goh, gol, gwth + 3 * WN, out);
}

// round 10
// speedup vs baseline: 3.8764x; 1.0545x over previous
#include <cuda_runtime.h>
#include <cuda_fp16.h>
#include <cstdint>

#define BATCH 2
#define SEQ   2048
#define EMB   1024
#define HEADS 16
#define DKH   64
#define NEGV  (-1.0e9f)
#define SCALE 0.125f
#define MROWS (BATCH*SEQ)     // 4096

// ---------------------------------------------------------------------------
// Scratch — __device__ globals per allocation rules. fp16 2-product scheme.
// ---------------------------------------------------------------------------
__device__ __half g_qh [MROWS*EMB];
__device__ __half g_ql [MROWS*EMB];
__device__ __half g_kh [MROWS*EMB];
__device__ __half g_vh [MROWS*EMB];
__device__ __half g_xh [3][MROWS*EMB];
__device__ __half g_xl [3][MROWS*EMB];
__device__ __half g_oh [MROWS*EMB];
__device__ __half g_ol [MROWS*EMB];
__device__ __half g_wth[4][EMB*EMB];
__device__ unsigned char g_m8 [BATCH*SEQ*SEQ];
__device__ int   g_mask_is_i32;

// ---------------------------------------------------------------------------
// PTX helpers
// ---------------------------------------------------------------------------
__device__ __forceinline__ uint32_t smem_u32(const void* p) {
    uint32_t a;
    asm("{ .reg .u64 t; cvta.to.shared.u64 t, %1; cvt.u32.u64 %0, t; }"
        : "=r"(a) : "l"(p));
    return a;
}

#define LDSM4(r, addr) \
    asm volatile("ldmatrix.sync.aligned.m8n8.x4.shared.b16 {%0,%1,%2,%3}, [%4];" \
        : "=r"((r)[0]), "=r"((r)[1]), "=r"((r)[2]), "=r"((r)[3]) : "r"(addr))
#define LDSM4T(r, addr) \
    asm volatile("ldmatrix.sync.aligned.m8n8.x4.trans.shared.b16 {%0,%1,%2,%3}, [%4];" \
        : "=r"((r)[0]), "=r"((r)[1]), "=r"((r)[2]), "=r"((r)[3]) : "r"(addr))

#define MMA_F16(d, a, b) \
    asm volatile("mma.sync.aligned.m16n8k16.row.col.f32.f16.f16.f32 " \
        "{%0,%1,%2,%3}, {%4,%5,%6,%7}, {%8,%9}, {%0,%1,%2,%3};" \
        : "+f"((d)[0]), "+f"((d)[1]), "+f"((d)[2]), "+f"((d)[3]) \
        : "r"((a)[0]), "r"((a)[1]), "r"((a)[2]), "r"((a)[3]), \
          "r"((b)[0]), "r"((b)[1]))

#define CP_ASYNC16(sa, gp) \
    asm volatile("{\n\t.reg .u64 gpt;\n\tcvta.to.global.u64 gpt, %1;\n\t" \
        "cp.async.cg.shared.global [%0], [gpt], 16;\n\t}" \
        :: "r"(sa), "l"(gp))
#define CP_COMMIT()  asm volatile("cp.async.commit_group;" ::: "memory")
#define CP_WAIT0()   asm volatile("cp.async.wait_group 0;" ::: "memory")
#define CP_WAIT1()   asm volatile("cp.async.wait_group 1;" ::: "memory")
#define CP_WAIT2()   asm volatile("cp.async.wait_group 2;" ::: "memory")

__device__ __forceinline__ void split2h(float x, float y, uint32_t& hi, uint32_t& lo)
{
    __half hx = __float2half_rn(x), hy = __float2half_rn(y);
    __half lx = __float2half_rn(x - __half2float(hx));
    __half ly = __float2half_rn(y - __half2float(hy));
    __half2 H = __halves2half2(hx, hy), L = __halves2half2(lx, ly);
    hi = *reinterpret_cast<uint32_t*>(&H);
    lo = *reinterpret_cast<uint32_t*>(&L);
}
__device__ __forceinline__ uint32_t pack2h(float x, float y)
{
    __half2 H = __halves2half2(__float2half_rn(x), __float2half_rn(y));
    return *reinterpret_cast<uint32_t*>(&H);
}

// ---------------------------------------------------------------------------
// Prep kernels (unchanged)
// ---------------------------------------------------------------------------
__global__ void mha_detect_mask_kernel(const unsigned char* __restrict__ m)
{
    int s = 0;
    for (int i = threadIdx.x; i < 4096; i += 256)
        if ((i & 3) != 0) s |= m[i];
    int any = __syncthreads_or(s);
    if (threadIdx.x == 0)
        g_mask_is_i32 = (any == 0) ? 1 : 0;
}

__global__ __launch_bounds__(256)
void mha_mask8_kernel(const unsigned char* __restrict__ m,
                      unsigned char* __restrict__ o, int n4)
{
    int i = blockIdx.x * 256 + threadIdx.x;
    if (i >= n4) return;
    if (g_mask_is_i32) {
        int4 w = ((const int4*)m)[i];
        uchar4 u;
        u.x = (unsigned char)w.x; u.y = (unsigned char)w.y;
        u.z = (unsigned char)w.z; u.w = (unsigned char)w.w;
        ((uchar4*)o)[i] = u;
    } else {
        ((uchar4*)o)[i] = ((const uchar4*)m)[i];
    }
}

struct SplitArgs {
    const float4* x[3];
    uint32_t* hi[3];
    uint32_t* lo[3];
};

__global__ __launch_bounds__(256)
void mha_split3_kernel(SplitArgs p, int n4)
{
    int i = blockIdx.x * 256 + threadIdx.x;
    if (i >= n4) return;
    const int z = blockIdx.z;
    float4 v = p.x[z][i];
    uint32_t h0, l0, h1, l1;
    split2h(v.x, v.y, h0, l0);
    split2h(v.z, v.w, h1, l1);
    p.hi[z][2 * i + 0] = h0;
    p.hi[z][2 * i + 1] = h1;
    p.lo[z][2 * i + 0] = l0;
    p.lo[z][2 * i + 1] = l1;
}

struct WsplitArgs {
    const float* W[4];
    __half* th[4];
};

__global__ __launch_bounds__(256)
void mha_wsplit4_kernel(WsplitArgs p)
{
    __shared__ float t[32][33];
    const int z  = blockIdx.z;
    const float* W = p.W[z];
    const int n  = blockIdx.x * 32 + threadIdx.x;
    const int k0 = blockIdx.y * 32;
    #pragma unroll
    for (int r = 0; r < 32; r += 8)
        t[threadIdx.y + r][threadIdx.x] = W[(size_t)(k0 + threadIdx.y + r) * EMB + n];
    __syncthreads();
    #pragma unroll
    for (int r = 0; r < 32; r += 8) {
        float v = t[threadIdx.x][threadIdx.y + r];
        int on = blockIdx.x * 32 + threadIdx.y + r;
        int ok = k0 + threadIdx.x;
        p.th[z][(size_t)on * EMB + ok] = __float2half_rn(v);
    }
}

// ---------------------------------------------------------------------------
// GEMM: CTA 128x256, warp tile 64x64, KC=32, fp16 2-product, 3-STAGE
// cp.async pipeline (prefetch distance 2, wait_group 2).
// Stage: Ah(8K) Al(8K) B(16K) = 32KB; 3 stages = 96KB.
// ---------------------------------------------------------------------------
#define KC        32
#define A_TSB     8192
#define B_TSB     16384
#define STAGE_SB  (2*A_TSB + B_TSB)     // 32768
#define GSM_TOTAL (3 * STAGE_SB)        // 98304

#define GSWZ(r, ch) ((uint32_t)((r) * 64 + ((((ch) ^ (((r) >> 1) & 3))) << 4)))

__device__ __forceinline__ void cp_tile_a(const __half* __restrict__ g,
                                          int row0, int kb, uint32_t sdst, int tid)
{
    #pragma unroll
    for (int p = 0; p < 2; p++) {
        int f = tid + p * 256;
        int r = f >> 2, ch = f & 3;
        const __half* gp = g + (size_t)(row0 + r) * EMB + kb + ch * 8;
        CP_ASYNC16(sdst + GSWZ(r, ch), gp);
    }
}

__device__ __forceinline__ void cp_tile_b(const __half* __restrict__ g,
                                          int row0, int kb, uint32_t sdst, int tid)
{
    #pragma unroll
    for (int p = 0; p < 4; p++) {
        int f = tid + p * 256;
        int r = f >> 2, ch = f & 3;
        const __half* gp = g + (size_t)(row0 + r) * EMB + kb + ch * 8;
        CP_ASYNC16(sdst + GSWZ(r, ch), gp);
    }
}

__device__ __forceinline__ void gemm_stage_load(const __half* Ah, const __half* Al,
                                                const __half* B, int m0, int n0,
                                                int kb, uint32_t buf, int tid)
{
    cp_tile_a(Ah, m0, kb, buf, tid);
    cp_tile_a(Al, m0, kb, buf + A_TSB, tid);
    cp_tile_b(B,  n0, kb, buf + 2 * A_TSB, tid);
    CP_COMMIT();
}

__device__ __forceinline__ void gemm_main(const __half* Ah, const __half* Al,
                                          const __half* B,
                                          uint32_t sb, int m0, int n0,
                                          int tid, int lane, int wm, int wn,
                                          float acc[4][8][4])
{
    const int NS = EMB / KC;           // 32
    gemm_stage_load(Ah, Al, B, m0, n0, 0, sb, tid);
    gemm_stage_load(Ah, Al, B, m0, n0, KC, sb + STAGE_SB, tid);

    for (int s = 0; s < NS; s++) {
        // buffer (s+2)%3 was freed by the end-of-iter sync of s-1
        if (s + 2 < NS)
            gemm_stage_load(Ah, Al, B, m0, n0, (s + 2) * KC,
                            sb + ((s + 2) % 3) * STAGE_SB, tid);
        if (s + 2 < NS)      CP_WAIT2();
        else if (s + 1 < NS) CP_WAIT1();
        else                 CP_WAIT0();
        __syncthreads();

        const uint32_t abase = sb + (s % 3) * STAGE_SB;
        const uint32_t bbase = abase + 2 * A_TSB;

        #pragma unroll
        for (int ks = 0; ks < 2; ks++) {
            uint32_t ah[4][4], al[4][4];
            {
                const int ch = ks * 2 + (lane >> 4);
                #pragma unroll
                for (int mt = 0; mt < 4; mt++) {
                    const int row = wm * 64 + mt * 16 + (lane & 15);
                    const uint32_t ad = abase + GSWZ(row, ch);
                    LDSM4(ah[mt], ad);
                    LDSM4(al[mt], ad + A_TSB);
                }
            }
            #pragma unroll
            for (int ntp = 0; ntp < 4; ntp++) {
                const int row = wn * 64 + ntp * 16 + (lane & 7) + ((lane >> 4) << 3);
                const int ch  = ks * 2 + ((lane >> 3) & 1);
                uint32_t tb[4];
                LDSM4(tb, bbase + GSWZ(row, ch));
                const int n0t = 2 * ntp, n1t = 2 * ntp + 1;
                #pragma unroll
                for (int mt = 0; mt < 4; mt++) {
                    MMA_F16(acc[mt][n0t], ah[mt], tb);
                    MMA_F16(acc[mt][n1t], ah[mt], tb + 2);
                }
                #pragma unroll
                for (int mt = 0; mt < 4; mt++) {
                    MMA_F16(acc[mt][n0t], al[mt], tb);
                    MMA_F16(acc[mt][n1t], al[mt], tb + 2);
                }
            }
        }
        __syncthreads();
    }
}

struct Gemm3Args {
    const __half *Ah[3], *Al[3], *B[3];
    __half *Ch[3], *Cl[3];
};

__global__ __launch_bounds__(256, 1)
void mha_mma_gemm3(Gemm3Args p)
{
    extern __shared__ char smem[];
    const uint32_t sb = smem_u32(smem);
    const int tid  = threadIdx.x;
    const int wid  = tid >> 5;
    const int lane = tid & 31;
    const int wm   = wid & 1;
    const int wn   = wid >> 1;
    const int m0   = blockIdx.y * 128;
    const int n0   = blockIdx.x * 256;
    const int z    = blockIdx.z;

    float acc[4][8][4];
    #pragma unroll
    for (int mt = 0; mt < 4; mt++)
        #pragma unroll
        for (int nt = 0; nt < 8; nt++)
            #pragma unroll
            for (int e = 0; e < 4; e++) acc[mt][nt][e] = 0.0f;

    gemm_main(p.Ah[z], p.Al[z], p.B[z], sb, m0, n0, tid, lane, wm, wn, acc);

    __half* Ch = p.Ch[z];
    __half* Cl = p.Cl[z];
    if (Cl) {
        #pragma unroll
        for (int mt = 0; mt < 4; mt++) {
            const int r0 = m0 + wm * 64 + mt * 16 + (lane >> 2);
            #pragma unroll
            for (int nt = 0; nt < 8; nt++) {
                const int c0 = n0 + wn * 64 + nt * 8 + 2 * (lane & 3);
                uint32_t hu, lu;
                split2h(acc[mt][nt][0], acc[mt][nt][1], hu, lu);
                *(uint32_t*)(Ch + (size_t)r0 * EMB + c0) = hu;
                *(uint32_t*)(Cl + (size_t)r0 * EMB + c0) = lu;
                split2h(acc[mt][nt][2], acc[mt][nt][3], hu, lu);
                *(uint32_t*)(Ch + (size_t)(r0 + 8) * EMB + c0) = hu;
                *(uint32_t*)(Cl + (size_t)(r0 + 8) * EMB + c0) = lu;
            }
        }
    } else {
        #pragma unroll
        for (int mt = 0; mt < 4; mt++) {
            const int r0 = m0 + wm * 64 + mt * 16 + (lane >> 2);
            #pragma unroll
            for (int nt = 0; nt < 8; nt++) {
                const int c0 = n0 + wn * 64 + nt * 8 + 2 * (lane & 3);
                *(uint32_t*)(Ch + (size_t)r0 * EMB + c0) =
                    pack2h(acc[mt][nt][0], acc[mt][nt][1]);
                *(uint32_t*)(Ch + (size_t)(r0 + 8) * EMB + c0) =
                    pack2h(acc[mt][nt][2], acc[mt][nt][3]);
            }
        }
    }
}

__global__ __launch_bounds__(256, 1)
void mha_mma_gemm_f32(const __half* __restrict__ Ah,
                      const __half* __restrict__ Al,
                      const __half* __restrict__ B,
                      float* __restrict__ C)
{
    extern __shared__ char smem[];
    const uint32_t sb = smem_u32(smem);
    const int tid  = threadIdx.x;
    const int wid  = tid >> 5;
    const int lane = tid & 31;
    const int wm   = wid & 1;
    const int wn   = wid >> 1;
    const int m0   = blockIdx.y * 128;
    const int n0   = blockIdx.x * 256;

    float acc[4][8][4];
    #pragma unroll
    for (int mt = 0; mt < 4; mt++)
        #pragma unroll
        for (int nt = 0; nt < 8; nt++)
            #pragma unroll
            for (int e = 0; e < 4; e++) acc[mt][nt][e] = 0.0f;

    gemm_main(Ah, Al, B, sb, m0, n0, tid, lane, wm, wn, acc);

    #pragma unroll
    for (int mt = 0; mt < 4; mt++) {
        const int r0 = m0 + wm * 64 + mt * 16 + (lane >> 2);
        #pragma unroll
        for (int nt = 0; nt < 8; nt++) {
            const int c0 = n0 + wn * 64 + nt * 8 + 2 * (lane & 3);
            *(float2*)(C + (size_t)r0 * EMB + c0)       = make_float2(acc[mt][nt][0], acc[mt][nt][1]);
            *(float2*)(C + (size_t)(r0 + 8) * EMB + c0) = make_float2(acc[mt][nt][2], acc[mt][nt][3]);
        }
    }
}

// ---------------------------------------------------------------------------
// Flash attention, fp16 2-product, BR=128, BC=64, 2 CTAs/SM (4 warps/SMSP):
// warp owns 16 q-rows; softmax of one CTA overlaps MMAs of the other.
// smem per CTA: Qh,Ql 16KB each + 2 stages x (K 8K + V 8K) = 64KB.
// ---------------------------------------------------------------------------
#define BR  128
#define BC  64
#define NKT (SEQ / BC)        // 32
#define AQH 0
#define AQL 16384
#define AST 32768
#define KVT 8192
#define ASTAGE (2 * KVT)      // 16384
#define ASM_TOTAL (AST + 2 * ASTAGE)   // 65536

__device__ __forceinline__ void att_cp_q(const __half* __restrict__ g,
                                         uint32_t sbase, int tid)
{
    #pragma unroll
    for (int p = 0; p < 4; p++) {
        int f = tid + p * 256;
        int r = f >> 3, ch = f & 7;
        const __half* gp = g + (size_t)r * EMB + ch * 8;
        uint32_t sa = sbase + r * 128 + ((ch ^ (r & 7)) << 4);
        CP_ASYNC16(sa, gp);
    }
}

__device__ __forceinline__ void att_cp_kv(const __half* __restrict__ g,
                                          uint32_t sbase, int tid)
{
    #pragma unroll
    for (int p = 0; p < 2; p++) {
        int f = tid + p * 256;
        int r = f >> 3, ch = f & 7;
        const __half* gp = g + (size_t)r * EMB + ch * 8;
        uint32_t sa = sbase + r * 128 + ((ch ^ (r & 7)) << 4);
        CP_ASYNC16(sa, gp);
    }
}

__global__ __launch_bounds__(256, 2)
void mha_attn_mma(const __half* __restrict__ Qh, const __half* __restrict__ Ql,
                  const __half* __restrict__ K,  const __half* __restrict__ V,
                  const unsigned char* __restrict__ mask8,
                  __half* __restrict__ Oh, __half* __restrict__ Ol)
{
    extern __shared__ char smem[];
    const uint32_t sb = smem_u32(smem);
    const int tid = threadIdx.x, wid = tid >> 5, lane = tid & 31;
    const int q0 = blockIdx.x * BR;
    const int b  = blockIdx.y >> 4, h = blockIdx.y & 15;

    const size_t qoff   = ((size_t)(b * SEQ + q0)) * EMB + h * DKH;
    const size_t kvbase = ((size_t)b * SEQ) * EMB + h * DKH;

    att_cp_q(Qh + qoff, sb + AQH, tid);
    att_cp_q(Ql + qoff, sb + AQL, tid);
    att_cp_kv(K + kvbase, sb + AST + 0 * KVT, tid);
    att_cp_kv(V + kvbase, sb + AST + 1 * KVT, tid);
    CP_COMMIT();
    CP_WAIT0();
    __syncthreads();

    const int qrow = 16 * wid + (lane & 15);
    const int q7   = qrow & 7;
    const uint32_t qhb = sb + AQH + qrow * 128;
    const uint32_t qlb = sb + AQL + qrow * 128;
    const int qchh = lane >> 4;

    const int sx    = lane & 7;
    const int krow  = (lane & 7) + ((lane & 16) ? 8 : 0);
    const int kchh  = (lane >> 3) & 1;
    const int vrowb = (lane & 7) + ((lane & 8) ? 8 : 0);
    const int vchh  = (lane & 16) ? 1 : 0;

    float o[8][4];
    float s[8][4];
    #pragma unroll
    for (int g = 0; g < 8; g++)
        #pragma unroll
        for (int e = 0; e < 4; e++) o[g][e] = 0.0f;
    float m0 = __int_as_float(0xff800000);
    float m1 = __int_as_float(0xff800000);
    float l0 = 0.0f, l1 = 0.0f;

    const unsigned char* mb0 = mask8 +
        ((size_t)(b * SEQ + q0 + 16 * wid + (lane >> 2))) * SEQ + 2 * (lane & 3);
    const unsigned char* mb1 = mb0 + 8 * SEQ;

    for (int kt = 0; kt < NKT; kt++) {
        if (kt + 1 < NKT) {
            const size_t kv = kvbase + (size_t)(kt + 1) * BC * EMB;
            const uint32_t nb = sb + AST + ((kt + 1) & 1) * ASTAGE;
            att_cp_kv(K + kv, nb + 0 * KVT, tid);
            att_cp_kv(V + kv, nb + 1 * KVT, tid);
            CP_COMMIT();
            CP_WAIT1();
        } else {
            CP_WAIT0();
        }
        __syncthreads();

        const uint32_t bK = sb + AST + (kt & 1) * ASTAGE;
        const uint32_t bV = bK + KVT;

        // ---- S = Q K^T (2-product) ----
        #pragma unroll
        for (int g = 0; g < 8; g++)
            #pragma unroll
            for (int e = 0; e < 4; e++) s[g][e] = 0.0f;

        #pragma unroll
        for (int kc = 0; kc < 4; kc++) {
            uint32_t qfh[4], qfl[4];
            {
                const int ch = 2 * kc + qchh;
                const uint32_t po = (uint32_t)((ch ^ q7) << 4);
                LDSM4(qfh, qhb + po);
                LDSM4(qfl, qlb + po);
            }
            #pragma unroll
            for (int jp = 0; jp < 2; jp++) {
                uint32_t kf0[4], kf1[4];
                const int ch = 2 * kc + kchh;
                const uint32_t pc = (uint32_t)((ch ^ sx) << 4);
                const uint32_t o0 = (uint32_t)((32 * jp + krow) * 128) + pc;
                const uint32_t o1 = o0 + 16 * 128;
                LDSM4(kf0, bK + o0);
                LDSM4(kf1, bK + o1);
                MMA_F16(s[4*jp+0], qfh, kf0);
                MMA_F16(s[4*jp+1], qfh, kf0 + 2);
                MMA_F16(s[4*jp+2], qfh, kf1);
                MMA_F16(s[4*jp+3], qfh, kf1 + 2);
                MMA_F16(s[4*jp+0], qfl, kf0);
                MMA_F16(s[4*jp+1], qfl, kf0 + 2);
                MMA_F16(s[4*jp+2], qfl, kf1);
                MMA_F16(s[4*jp+3], qfl, kf1 + 2);
            }
        }

        // ---- scale + mask ----
        const unsigned char* mr0 = mb0 + (size_t)kt * BC;
        const unsigned char* mr1 = mb1 + (size_t)kt * BC;
        #pragma unroll
        for (int g = 0; g < 8; g++) {
            uchar2 u0 = *(const uchar2*)(mr0 + 8 * g);
            uchar2 u1 = *(const uchar2*)(mr1 + 8 * g);
            s[g][0] = u0.x ? NEGV : s[g][0] * SCALE;
            s[g][1] = u0.y ? NEGV : s[g][1] * SCALE;
            s[g][2] = u1.x ? NEGV : s[g][2] * SCALE;
            s[g][3] = u1.y ? NEGV : s[g][3] * SCALE;
        }

        // ---- online softmax (rows lane>>2 and +8; 4-lane groups) ----
        float mx0 = NEGV * 2.0f, mx1 = NEGV * 2.0f;
        #pragma unroll
        for (int g = 0; g < 8; g++) {
            mx0 = fmaxf(mx0, fmaxf(s[g][0], s[g][1]));
            mx1 = fmaxf(mx1, fmaxf(s[g][2], s[g][3]));
        }
        mx0 = fmaxf(mx0, __shfl_xor_sync(0xffffffffu, mx0, 1));
        mx0 = fmaxf(mx0, __shfl_xor_sync(0xffffffffu, mx0, 2));
        mx1 = fmaxf(mx1, __shfl_xor_sync(0xffffffffu, mx1, 1));
        mx1 = fmaxf(mx1, __shfl_xor_sync(0xffffffffu, mx1, 2));
        const float mn0 = fmaxf(m0, mx0), mn1 = fmaxf(m1, mx1);
        const float a0 = __expf(m0 - mn0), a1 = __expf(m1 - mn1);
        float sum0 = 0.0f, sum1 = 0.0f;
        #pragma unroll
        for (int g = 0; g < 8; g++) {
            s[g][0] = __expf(s[g][0] - mn0);
            s[g][1] = __expf(s[g][1] - mn0);
            s[g][2] = __expf(s[g][2] - mn1);
            s[g][3] = __expf(s[g][3] - mn1);
            sum0 += s[g][0] + s[g][1];
            sum1 += s[g][2] + s[g][3];
        }
        sum0 += __shfl_xor_sync(0xffffffffu, sum0, 1);
        sum0 += __shfl_xor_sync(0xffffffffu, sum0, 2);
        sum1 += __shfl_xor_sync(0xffffffffu, sum1, 1);
        sum1 += __shfl_xor_sync(0xffffffffu, sum1, 2);
        l0 = l0 * a0 + sum0;  m0 = mn0;
        l1 = l1 * a1 + sum1;  m1 = mn1;
        #pragma unroll
        for (int g = 0; g < 8; g++) {
            o[g][0] *= a0; o[g][1] *= a0;
            o[g][2] *= a1; o[g][3] *= a1;
        }

        // ---- O += P V (2-product) ----
        #pragma unroll
        for (int c = 0; c < 4; c++) {
            uint32_t pha[4], pla[4];
            split2h(s[2*c][0],   s[2*c][1],   pha[0], pla[0]);
            split2h(s[2*c][2],   s[2*c][3],   pha[1], pla[1]);
            split2h(s[2*c+1][0], s[2*c+1][1], pha[2], pla[2]);
            split2h(s[2*c+1][2], s[2*c+1][3], pha[3], pla[3]);

            uint32_t vf[4][4];
            const uint32_t rbase = (uint32_t)((16 * c + vrowb) * 128);
            #pragma unroll
            for (int jd = 0; jd < 4; jd++) {
                const int ch = 2 * jd + vchh;
                LDSM4T(vf[jd], bV + rbase + ((ch ^ sx) << 4));
            }
            #pragma unroll
            for (int jd = 0; jd < 4; jd++) {
                MMA_F16(o[2*jd],   pha, vf[jd]);
                MMA_F16(o[2*jd+1], pha, vf[jd] + 2);
            }
            #pragma unroll
            for (int jd = 0; jd < 4; jd++) {
                MMA_F16(o[2*jd],   pla, vf[jd]);
                MMA_F16(o[2*jd+1], pla, vf[jd] + 2);
            }
        }

        __syncthreads();
    }

    // ---- epilogue: normalize, fp16 split for Wo GEMM ----
    const float i0 = 1.0f / l0, i1 = 1.0f / l1;
    const int qr = q0 + 16 * wid + (lane >> 2);
    const size_t ob = ((size_t)(b * SEQ + qr)) * EMB + h * DKH + 2 * (lane & 3);
    #pragma unroll
    for (int g = 0; g < 8; g++) {
        uint32_t hu, lu;
        split2h(o[g][0] * i0, o[g][1] * i0, hu, lu);
        *(uint32_t*)(Oh + ob + 8 * g) = hu;
        *(uint32_t*)(Ol + ob + 8 * g) = lu;
        split2h(o[g][2] * i1, o[g][3] * i1, hu, lu);
        *(uint32_t*)(Oh + ob + 8 * (size_t)EMB + 8 * g) = hu;
        *(uint32_t*)(Ol + ob + 8 * (size_t)EMB + 8 * g) = lu;
    }
}

// ---------------------------------------------------------------------------
extern "C" void kernel_launch(void* const* d_in, const int* in_sizes, int n_in,
                              void* d_out, int out_size)
{
    (void)in_sizes; (void)n_in; (void)out_size;
    const float*         query  = (const float*)d_in[0];
    const float*         key    = (const float*)d_in[1];
    const float*         value  = (const float*)d_in[2];
    const unsigned char* masked = (const unsigned char*)d_in[3];
    const float*         Wq     = (const float*)d_in[4];
    const float*         Wk     = (const float*)d_in[5];
    const float*         Wv     = (const float*)d_in[6];
    const float*         Wo     = (const float*)d_in[7];
    float*               out    = (float*)d_out;

    __half *gqh, *gql, *gkh, *gvh, *goh, *gol, *gxh, *gxl, *gwth;
    unsigned char *gm8;
    cudaGetSymbolAddress((void**)&gqh,  g_qh);
    cudaGetSymbolAddress((void**)&gql,  g_ql);
    cudaGetSymbolAddress((void**)&gkh,  g_kh);
    cudaGetSymbolAddress((void**)&gvh,  g_vh);
    cudaGetSymbolAddress((void**)&goh,  g_oh);
    cudaGetSymbolAddress((void**)&gol,  g_ol);
    cudaGetSymbolAddress((void**)&gxh,  g_xh);
    cudaGetSymbolAddress((void**)&gxl,  g_xl);
    cudaGetSymbolAddress((void**)&gwth, g_wth);
    cudaGetSymbolAddress((void**)&gm8,  g_m8);

    const size_t XN = (size_t)MROWS * EMB;
    const size_t WN = (size_t)EMB * EMB;

    cudaFuncSetAttribute(mha_mma_gemm3,
                         cudaFuncAttributeMaxDynamicSharedMemorySize, GSM_TOTAL);
    cudaFuncSetAttribute(mha_mma_gemm_f32,
                         cudaFuncAttributeMaxDynamicSharedMemorySize, GSM_TOTAL);
    cudaFuncSetAttribute(mha_attn_mma,
                         cudaFuncAttributeMaxDynamicSharedMemorySize, ASM_TOTAL);

    const int n4 = MROWS * EMB / 4;

    mha_detect_mask_kernel<<<1, 256>>>(masked);

    WsplitArgs wa;
    wa.W[0] = Wq; wa.W[1] = Wk; wa.W[2] = Wv; wa.W[3] = Wo;
    for (int z = 0; z < 4; z++) wa.th[z] = gwth + z * WN;
    dim3 w_grid(EMB / 32, EMB / 32, 4), w_blk(32, 8);
    mha_wsplit4_kernel<<<w_grid, w_blk>>>(wa);

    SplitArgs sa;
    sa.x[0] = (const float4*)query; sa.x[1] = (const float4*)key; sa.x[2] = (const float4*)value;
    for (int z = 0; z < 3; z++) {
        sa.hi[z] = (uint32_t*)(gxh + z * XN);
        sa.lo[z] = (uint32_t*)(gxl + z * XN);
    }
    dim3 s_grid((n4 + 255) / 256, 1, 3);
    mha_split3_kernel<<<s_grid, 256>>>(sa, n4);

    const int mn4 = BATCH * SEQ * SEQ / 4;
    mha_mask8_kernel<<<(mn4 + 255) / 256, 256>>>(masked, gm8, mn4);

    Gemm3Args ga;
    for (int z = 0; z < 3; z++) {
        ga.Ah[z] = gxh + z * XN;  ga.Al[z] = gxl + z * XN;
        ga.B[z]  = gwth + z * WN;
    }
    ga.Ch[0] = gqh; ga.Cl[0] = gql;
    ga.Ch[1] = gkh; ga.Cl[1] = nullptr;
    ga.Ch[2] = gvh; ga.Cl[2] = nullptr;
    dim3 g3(EMB / 256, MROWS / 128, 3);      // (4, 32, 3)
    mha_mma_gemm3<<<g3, 256, GSM_TOTAL>>>(ga);

    dim3 attn_grid(SEQ / BR, BATCH * HEADS);  // (16, 32)
    mha_attn_mma<<<attn_grid, 256, ASM_TOTAL>>>(gqh, gql, gkh, gvh, gm8, goh, gol);

    dim3 g1(EMB / 256, MROWS / 128);          // (4, 32)
    mha_mma_gemm_f32<<<g1, 256, GSM_TOTAL>>>(goh, gol, gwth + 3 * WN, out);
}

// round 11
// speedup vs baseline: 4.7149x; 1.2163x over previous
#include <cuda_runtime.h>
#include <cuda_fp16.h>
#include <cstdint>

#define BATCH 2
#define SEQ   2048
#define EMB   1024
#define HEADS 16
#define DKH   64
#define NEGV  (-1.0e9f)
#define SCALE 0.125f
#define MROWS (BATCH*SEQ)     // 4096

// ---------------------------------------------------------------------------
// Scratch — __device__ globals per allocation rules.
// fp16 scheme: projection inputs X split hi/lo (2-product GEMM);
// Q/K/V/O and all weights single fp16.
// ---------------------------------------------------------------------------
__device__ __half g_qh [MROWS*EMB];
__device__ __half g_kh [MROWS*EMB];
__device__ __half g_vh [MROWS*EMB];
__device__ __half g_xh [3][MROWS*EMB];
__device__ __half g_xl [3][MROWS*EMB];
__device__ __half g_oh [MROWS*EMB];
__device__ __half g_wth[4][EMB*EMB];
__device__ unsigned char g_m8 [BATCH*SEQ*SEQ];
__device__ int   g_mask_is_i32;

// ---------------------------------------------------------------------------
// PTX helpers
// ---------------------------------------------------------------------------
__device__ __forceinline__ uint32_t smem_u32(const void* p) {
    uint32_t a;
    asm("{ .reg .u64 t; cvta.to.shared.u64 t, %1; cvt.u32.u64 %0, t; }"
        : "=r"(a) : "l"(p));
    return a;
}

#define LDSM4(r, addr) \
    asm volatile("ldmatrix.sync.aligned.m8n8.x4.shared.b16 {%0,%1,%2,%3}, [%4];" \
        : "=r"((r)[0]), "=r"((r)[1]), "=r"((r)[2]), "=r"((r)[3]) : "r"(addr))
#define LDSM4T(r, addr) \
    asm volatile("ldmatrix.sync.aligned.m8n8.x4.trans.shared.b16 {%0,%1,%2,%3}, [%4];" \
        : "=r"((r)[0]), "=r"((r)[1]), "=r"((r)[2]), "=r"((r)[3]) : "r"(addr))

#define MMA_F16(d, a, b) \
    asm volatile("mma.sync.aligned.m16n8k16.row.col.f32.f16.f16.f32 " \
        "{%0,%1,%2,%3}, {%4,%5,%6,%7}, {%8,%9}, {%0,%1,%2,%3};" \
        : "+f"((d)[0]), "+f"((d)[1]), "+f"((d)[2]), "+f"((d)[3]) \
        : "r"((a)[0]), "r"((a)[1]), "r"((a)[2]), "r"((a)[3]), \
          "r"((b)[0]), "r"((b)[1]))

#define CP_ASYNC16(sa, gp) \
    asm volatile("{\n\t.reg .u64 gpt;\n\tcvta.to.global.u64 gpt, %1;\n\t" \
        "cp.async.cg.shared.global [%0], [gpt], 16;\n\t}" \
        :: "r"(sa), "l"(gp))
#define CP_COMMIT()  asm volatile("cp.async.commit_group;" ::: "memory")
#define CP_WAIT0()   asm volatile("cp.async.wait_group 0;" ::: "memory")
#define CP_WAIT1()   asm volatile("cp.async.wait_group 1;" ::: "memory")
#define CP_WAIT2()   asm volatile("cp.async.wait_group 2;" ::: "memory")

__device__ __forceinline__ void split2h(float x, float y, uint32_t& hi, uint32_t& lo)
{
    __half hx = __float2half_rn(x), hy = __float2half_rn(y);
    __half lx = __float2half_rn(x - __half2float(hx));
    __half ly = __float2half_rn(y - __half2float(hy));
    __half2 H = __halves2half2(hx, hy), L = __halves2half2(lx, ly);
    hi = *reinterpret_cast<uint32_t*>(&H);
    lo = *reinterpret_cast<uint32_t*>(&L);
}
__device__ __forceinline__ uint32_t pack2h(float x, float y)
{
    __half2 H = __halves2half2(__float2half_rn(x), __float2half_rn(y));
    return *reinterpret_cast<uint32_t*>(&H);
}

// ---------------------------------------------------------------------------
// Prep kernels
// ---------------------------------------------------------------------------
__global__ void mha_detect_mask_kernel(const unsigned char* __restrict__ m)
{
    int s = 0;
    for (int i = threadIdx.x; i < 4096; i += 256)
        if ((i & 3) != 0) s |= m[i];
    int any = __syncthreads_or(s);
    if (threadIdx.x == 0)
        g_mask_is_i32 = (any == 0) ? 1 : 0;
}

__global__ __launch_bounds__(256)
void mha_mask8_kernel(const unsigned char* __restrict__ m,
                      unsigned char* __restrict__ o, int n4)
{
    int i = blockIdx.x * 256 + threadIdx.x;
    if (i >= n4) return;
    if (g_mask_is_i32) {
        int4 w = ((const int4*)m)[i];
        uchar4 u;
        u.x = (unsigned char)w.x; u.y = (unsigned char)w.y;
        u.z = (unsigned char)w.z; u.w = (unsigned char)w.w;
        ((uchar4*)o)[i] = u;
    } else {
        ((uchar4*)o)[i] = ((const uchar4*)m)[i];
    }
}

struct SplitArgs {
    const float4* x[3];
    uint32_t* hi[3];
    uint32_t* lo[3];
};

__global__ __launch_bounds__(256)
void mha_split3_kernel(SplitArgs p, int n4)
{
    int i = blockIdx.x * 256 + threadIdx.x;
    if (i >= n4) return;
    const int z = blockIdx.z;
    float4 v = p.x[z][i];
    uint32_t h0, l0, h1, l1;
    split2h(v.x, v.y, h0, l0);
    split2h(v.z, v.w, h1, l1);
    p.hi[z][2 * i + 0] = h0;
    p.hi[z][2 * i + 1] = h1;
    p.lo[z][2 * i + 0] = l0;
    p.lo[z][2 * i + 1] = l1;
}

struct WsplitArgs {
    const float* W[4];
    __half* th[4];
};

__global__ __launch_bounds__(256)
void mha_wsplit4_kernel(WsplitArgs p)
{
    __shared__ float t[32][33];
    const int z  = blockIdx.z;
    const float* W = p.W[z];
    const int n  = blockIdx.x * 32 + threadIdx.x;
    const int k0 = blockIdx.y * 32;
    #pragma unroll
    for (int r = 0; r < 32; r += 8)
        t[threadIdx.y + r][threadIdx.x] = W[(size_t)(k0 + threadIdx.y + r) * EMB + n];
    __syncthreads();
    #pragma unroll
    for (int r = 0; r < 32; r += 8) {
        float v = t[threadIdx.x][threadIdx.y + r];
        int on = blockIdx.x * 32 + threadIdx.y + r;
        int ok = k0 + threadIdx.x;
        p.th[z][(size_t)on * EMB + ok] = __float2half_rn(v);
    }
}

// ---------------------------------------------------------------------------
// GEMM: CTA 128x256, warp tile 64x64, KC=32, 3-stage cp.async pipeline.
// SPLIT template: true -> C = Ah@B + Al@B (2-product); false -> C = A@B.
// Stage layout (fixed): Ah(8K) Al(8K, unused if !SPLIT) B(16K) = 32KB.
// ---------------------------------------------------------------------------
#define KC        32
#define A_TSB     8192
#define B_TSB     16384
#define STAGE_SB  (2*A_TSB + B_TSB)     // 32768
#define GSM_TOTAL (3 * STAGE_SB)        // 98304

#define GSWZ(r, ch) ((uint32_t)((r) * 64 + ((((ch) ^ (((r) >> 1) & 3))) << 4)))

__device__ __forceinline__ void cp_tile_a(const __half* __restrict__ g,
                                          int row0, int kb, uint32_t sdst, int tid)
{
    #pragma unroll
    for (int p = 0; p < 2; p++) {
        int f = tid + p * 256;
        int r = f >> 2, ch = f & 3;
        const __half* gp = g + (size_t)(row0 + r) * EMB + kb + ch * 8;
        CP_ASYNC16(sdst + GSWZ(r, ch), gp);
    }
}

__device__ __forceinline__ void cp_tile_b(const __half* __restrict__ g,
                                          int row0, int kb, uint32_t sdst, int tid)
{
    #pragma unroll
    for (int p = 0; p < 4; p++) {
        int f = tid + p * 256;
        int r = f >> 2, ch = f & 3;
        const __half* gp = g + (size_t)(row0 + r) * EMB + kb + ch * 8;
        CP_ASYNC16(sdst + GSWZ(r, ch), gp);
    }
}

template<bool SPLIT>
__device__ __forceinline__ void gemm_stage_load(const __half* Ah, const __half* Al,
                                                const __half* B, int m0, int n0,
                                                int kb, uint32_t buf, int tid)
{
    cp_tile_a(Ah, m0, kb, buf, tid);
    if (SPLIT) cp_tile_a(Al, m0, kb, buf + A_TSB, tid);
    cp_tile_b(B,  n0, kb, buf + 2 * A_TSB, tid);
    CP_COMMIT();
}

template<bool SPLIT>
__device__ __forceinline__ void gemm_main(const __half* Ah, const __half* Al,
                                          const __half* B,
                                          uint32_t sb, int m0, int n0,
                                          int tid, int lane, int wm, int wn,
                                          float acc[4][8][4])
{
    const int NS = EMB / KC;           // 32
    gemm_stage_load<SPLIT>(Ah, Al, B, m0, n0, 0, sb, tid);
    gemm_stage_load<SPLIT>(Ah, Al, B, m0, n0, KC, sb + STAGE_SB, tid);

    for (int s = 0; s < NS; s++) {
        if (s + 2 < NS)
            gemm_stage_load<SPLIT>(Ah, Al, B, m0, n0, (s + 2) * KC,
                                   sb + ((s + 2) % 3) * STAGE_SB, tid);
        if (s + 2 < NS)      CP_WAIT2();
        else if (s + 1 < NS) CP_WAIT1();
        else                 CP_WAIT0();
        __syncthreads();

        const uint32_t abase = sb + (s % 3) * STAGE_SB;
        const uint32_t bbase = abase + 2 * A_TSB;

        #pragma unroll
        for (int ks = 0; ks < 2; ks++) {
            uint32_t ah[4][4], al[4][4];
            {
                const int ch = ks * 2 + (lane >> 4);
                #pragma unroll
                for (int mt = 0; mt < 4; mt++) {
                    const int row = wm * 64 + mt * 16 + (lane & 15);
                    const uint32_t ad = abase + GSWZ(row, ch);
                    LDSM4(ah[mt], ad);
                    if (SPLIT) LDSM4(al[mt], ad + A_TSB);
                }
            }
            #pragma unroll
            for (int ntp = 0; ntp < 4; ntp++) {
                const int row = wn * 64 + ntp * 16 + (lane & 7) + ((lane >> 4) << 3);
                const int ch  = ks * 2 + ((lane >> 3) & 1);
                uint32_t tb[4];
                LDSM4(tb, bbase + GSWZ(row, ch));
                const int n0t = 2 * ntp, n1t = 2 * ntp + 1;
                #pragma unroll
                for (int mt = 0; mt < 4; mt++) {
                    MMA_F16(acc[mt][n0t], ah[mt], tb);
                    MMA_F16(acc[mt][n1t], ah[mt], tb + 2);
                }
                if (SPLIT) {
                    #pragma unroll
                    for (int mt = 0; mt < 4; mt++) {
                        MMA_F16(acc[mt][n0t], al[mt], tb);
                        MMA_F16(acc[mt][n1t], al[mt], tb + 2);
                    }
                }
            }
        }
        __syncthreads();
    }
}

// merged Q/K/V projections: split-A GEMM, single fp16 output
struct Gemm3Args {
    const __half *Ah[3], *Al[3], *B[3];
    __half *C[3];
};

__global__ __launch_bounds__(256, 1)
void mha_mma_gemm3(Gemm3Args p)
{
    extern __shared__ char smem[];
    const uint32_t sb = smem_u32(smem);
    const int tid  = threadIdx.x;
    const int wid  = tid >> 5;
    const int lane = tid & 31;
    const int wm   = wid & 1;
    const int wn   = wid >> 1;
    const int m0   = blockIdx.y * 128;
    const int n0   = blockIdx.x * 256;
    const int z    = blockIdx.z;

    float acc[4][8][4];
    #pragma unroll
    for (int mt = 0; mt < 4; mt++)
        #pragma unroll
        for (int nt = 0; nt < 8; nt++)
            #pragma unroll
            for (int e = 0; e < 4; e++) acc[mt][nt][e] = 0.0f;

    gemm_main<true>(p.Ah[z], p.Al[z], p.B[z], sb, m0, n0, tid, lane, wm, wn, acc);

    __half* C = p.C[z];
    #pragma unroll
    for (int mt = 0; mt < 4; mt++) {
        const int r0 = m0 + wm * 64 + mt * 16 + (lane >> 2);
        #pragma unroll
        for (int nt = 0; nt < 8; nt++) {
            const int c0 = n0 + wn * 64 + nt * 8 + 2 * (lane & 3);
            *(uint32_t*)(C + (size_t)r0 * EMB + c0) =
                pack2h(acc[mt][nt][0], acc[mt][nt][1]);
            *(uint32_t*)(C + (size_t)(r0 + 8) * EMB + c0) =
                pack2h(acc[mt][nt][2], acc[mt][nt][3]);
        }
    }
}

// Wo projection: plain fp16 GEMM (A single), fp32 output
__global__ __launch_bounds__(256, 1)
void mha_mma_gemm_f32(const __half* __restrict__ A,
                      const __half* __restrict__ B,
                      float* __restrict__ C)
{
    extern __shared__ char smem[];
    const uint32_t sb = smem_u32(smem);
    const int tid  = threadIdx.x;
    const int wid  = tid >> 5;
    const int lane = tid & 31;
    const int wm   = wid & 1;
    const int wn   = wid >> 1;
    const int m0   = blockIdx.y * 128;
    const int n0   = blockIdx.x * 256;

    float acc[4][8][4];
    #pragma unroll
    for (int mt = 0; mt < 4; mt++)
        #pragma unroll
        for (int nt = 0; nt < 8; nt++)
            #pragma unroll
            for (int e = 0; e < 4; e++) acc[mt][nt][e] = 0.0f;

    gemm_main<false>(A, nullptr, B, sb, m0, n0, tid, lane, wm, wn, acc);

    #pragma unroll
    for (int mt = 0; mt < 4; mt++) {
        const int r0 = m0 + wm * 64 + mt * 16 + (lane >> 2);
        #pragma unroll
        for (int nt = 0; nt < 8; nt++) {
            const int c0 = n0 + wn * 64 + nt * 8 + 2 * (lane & 3);
            *(float2*)(C + (size_t)r0 * EMB + c0)       = make_float2(acc[mt][nt][0], acc[mt][nt][1]);
            *(float2*)(C + (size_t)(r0 + 8) * EMB + c0) = make_float2(acc[mt][nt][2], acc[mt][nt][3]);
        }
    }
}

// ---------------------------------------------------------------------------
// Flash attention, single-fp16 Q/K/V/P: S = Q@K^T, O = P@V (one product each).
// BR=128, BC=64, 2 CTAs/SM. Q fragments preloaded to registers.
// smem per CTA: Qh 16KB + 2 stages x (K 8K + V 8K) = 48KB.
// ---------------------------------------------------------------------------
#define BR  128
#define BC  64
#define NKT (SEQ / BC)        // 32
#define AQH 0
#define AST 16384
#define KVT 8192
#define ASTAGE (2 * KVT)      // 16384
#define ASM_TOTAL (AST + 2 * ASTAGE)   // 49152

__device__ __forceinline__ void att_cp_q(const __half* __restrict__ g,
                                         uint32_t sbase, int tid)
{
    #pragma unroll
    for (int p = 0; p < 4; p++) {
        int f = tid + p * 256;
        int r = f >> 3, ch = f & 7;
        const __half* gp = g + (size_t)r * EMB + ch * 8;
        uint32_t sa = sbase + r * 128 + ((ch ^ (r & 7)) << 4);
        CP_ASYNC16(sa, gp);
    }
}

__device__ __forceinline__ void att_cp_kv(const __half* __restrict__ g,
                                          uint32_t sbase, int tid)
{
    #pragma unroll
    for (int p = 0; p < 2; p++) {
        int f = tid + p * 256;
        int r = f >> 3, ch = f & 7;
        const __half* gp = g + (size_t)r * EMB + ch * 8;
        uint32_t sa = sbase + r * 128 + ((ch ^ (r & 7)) << 4);
        CP_ASYNC16(sa, gp);
    }
}

__global__ __launch_bounds__(256, 2)
void mha_attn_mma(const __half* __restrict__ Q,
                  const __half* __restrict__ K,  const __half* __restrict__ V,
                  const unsigned char* __restrict__ mask8,
                  __half* __restrict__ O)
{
    extern __shared__ char smem[];
    const uint32_t sb = smem_u32(smem);
    const int tid = threadIdx.x, wid = tid >> 5, lane = tid & 31;
    const int q0 = blockIdx.x * BR;
    const int b  = blockIdx.y >> 4, h = blockIdx.y & 15;

    const size_t qoff   = ((size_t)(b * SEQ + q0)) * EMB + h * DKH;
    const size_t kvbase = ((size_t)b * SEQ) * EMB + h * DKH;

    att_cp_q(Q + qoff, sb + AQH, tid);
    att_cp_kv(K + kvbase, sb + AST + 0 * KVT, tid);
    att_cp_kv(V + kvbase, sb + AST + 1 * KVT, tid);
    CP_COMMIT();
    CP_WAIT0();
    __syncthreads();

    // preload Q fragments (constant across all 32 k-tiles)
    uint32_t qf[4][4];
    {
        const int qrow = 16 * wid + (lane & 15);
        const uint32_t qb = sb + AQH + qrow * 128;
        const int q7 = qrow & 7;
        #pragma unroll
        for (int kc = 0; kc < 4; kc++) {
            const int ch = 2 * kc + (lane >> 4);
            LDSM4(qf[kc], qb + ((ch ^ q7) << 4));
        }
    }

    const int sx    = lane & 7;
    const int krow  = (lane & 7) + ((lane & 16) ? 8 : 0);
    const int kchh  = (lane >> 3) & 1;
    const int vrowb = (lane & 7) + ((lane & 8) ? 8 : 0);
    const int vchh  = (lane & 16) ? 1 : 0;

    float o[8][4];
    float s[8][4];
    #pragma unroll
    for (int g = 0; g < 8; g++)
        #pragma unroll
        for (int e = 0; e < 4; e++) o[g][e] = 0.0f;
    float m0 = __int_as_float(0xff800000);
    float m1 = __int_as_float(0xff800000);
    float l0 = 0.0f, l1 = 0.0f;

    const unsigned char* mb0 = mask8 +
        ((size_t)(b * SEQ + q0 + 16 * wid + (lane >> 2))) * SEQ + 2 * (lane & 3);
    const unsigned char* mb1 = mb0 + 8 * SEQ;

    for (int kt = 0; kt < NKT; kt++) {
        if (kt + 1 < NKT) {
            const size_t kv = kvbase + (size_t)(kt + 1) * BC * EMB;
            const uint32_t nb = sb + AST + ((kt + 1) & 1) * ASTAGE;
            att_cp_kv(K + kv, nb + 0 * KVT, tid);
            att_cp_kv(V + kv, nb + 1 * KVT, tid);
            CP_COMMIT();
            CP_WAIT1();
        } else {
            CP_WAIT0();
        }
        __syncthreads();

        const uint32_t bK = sb + AST + (kt & 1) * ASTAGE;
        const uint32_t bV = bK + KVT;

        // ---- S = Q K^T (single product) ----
        #pragma unroll
        for (int g = 0; g < 8; g++)
            #pragma unroll
            for (int e = 0; e < 4; e++) s[g][e] = 0.0f;

        #pragma unroll
        for (int kc = 0; kc < 4; kc++) {
            #pragma unroll
            for (int jp = 0; jp < 2; jp++) {
                uint32_t kf0[4], kf1[4];
                const int ch = 2 * kc + kchh;
                const uint32_t pc = (uint32_t)((ch ^ sx) << 4);
                const uint32_t o0 = (uint32_t)((32 * jp + krow) * 128) + pc;
                const uint32_t o1 = o0 + 16 * 128;
                LDSM4(kf0, bK + o0);
                LDSM4(kf1, bK + o1);
                MMA_F16(s[4*jp+0], qf[kc], kf0);
                MMA_F16(s[4*jp+1], qf[kc], kf0 + 2);
                MMA_F16(s[4*jp+2], qf[kc], kf1);
                MMA_F16(s[4*jp+3], qf[kc], kf1 + 2);
            }
        }

        // ---- scale + mask ----
        const unsigned char* mr0 = mb0 + (size_t)kt * BC;
        const unsigned char* mr1 = mb1 + (size_t)kt * BC;
        #pragma unroll
        for (int g = 0; g < 8; g++) {
            uchar2 u0 = *(const uchar2*)(mr0 + 8 * g);
            uchar2 u1 = *(const uchar2*)(mr1 + 8 * g);
            s[g][0] = u0.x ? NEGV : s[g][0] * SCALE;
            s[g][1] = u0.y ? NEGV : s[g][1] * SCALE;
            s[g][2] = u1.x ? NEGV : s[g][2] * SCALE;
            s[g][3] = u1.y ? NEGV : s[g][3] * SCALE;
        }

        // ---- online softmax ----
        float mx0 = NEGV * 2.0f, mx1 = NEGV * 2.0f;
        #pragma unroll
        for (int g = 0; g < 8; g++) {
            mx0 = fmaxf(mx0, fmaxf(s[g][0], s[g][1]));
            mx1 = fmaxf(mx1, fmaxf(s[g][2], s[g][3]));
        }
        mx0 = fmaxf(mx0, __shfl_xor_sync(0xffffffffu, mx0, 1));
        mx0 = fmaxf(mx0, __shfl_xor_sync(0xffffffffu, mx0, 2));
        mx1 = fmaxf(mx1, __shfl_xor_sync(0xffffffffu, mx1, 1));
        mx1 = fmaxf(mx1, __shfl_xor_sync(0xffffffffu, mx1, 2));
        const float mn0 = fmaxf(m0, mx0), mn1 = fmaxf(m1, mx1);
        const float a0 = __expf(m0 - mn0), a1 = __expf(m1 - mn1);
        float sum0 = 0.0f, sum1 = 0.0f;
        #pragma unroll
        for (int g = 0; g < 8; g++) {
            s[g][0] = __expf(s[g][0] - mn0);
            s[g][1] = __expf(s[g][1] - mn0);
            s[g][2] = __expf(s[g][2] - mn1);
            s[g][3] = __expf(s[g][3] - mn1);
            sum0 += s[g][0] + s[g][1];
            sum1 += s[g][2] + s[g][3];
        }
        sum0 += __shfl_xor_sync(0xffffffffu, sum0, 1);
        sum0 += __shfl_xor_sync(0xffffffffu, sum0, 2);
        sum1 += __shfl_xor_sync(0xffffffffu, sum1, 1);
        sum1 += __shfl_xor_sync(0xffffffffu, sum1, 2);
        l0 = l0 * a0 + sum0;  m0 = mn0;
        l1 = l1 * a1 + sum1;  m1 = mn1;
        #pragma unroll
        for (int g = 0; g < 8; g++) {
            o[g][0] *= a0; o[g][1] *= a0;
            o[g][2] *= a1; o[g][3] *= a1;
        }

        // ---- O += P V (single-fp16 P) ----
        #pragma unroll
        for (int c = 0; c < 4; c++) {
            uint32_t pa[4];
            pa[0] = pack2h(s[2*c][0],   s[2*c][1]);
            pa[1] = pack2h(s[2*c][2],   s[2*c][3]);
            pa[2] = pack2h(s[2*c+1][0], s[2*c+1][1]);
            pa[3] = pack2h(s[2*c+1][2], s[2*c+1][3]);

            uint32_t vf[4][4];
            const uint32_t rbase = (uint32_t)((16 * c + vrowb) * 128);
            #pragma unroll
            for (int jd = 0; jd < 4; jd++) {
                const int ch = 2 * jd + vchh;
                LDSM4T(vf[jd], bV + rbase + ((ch ^ sx) << 4));
            }
            #pragma unroll
            for (int jd = 0; jd < 4; jd++) {
                MMA_F16(o[2*jd],   pa, vf[jd]);
                MMA_F16(o[2*jd+1], pa, vf[jd] + 2);
            }
        }

        __syncthreads();
    }

    // ---- epilogue: normalize, single fp16 out for Wo GEMM ----
    const float i0 = 1.0f / l0, i1 = 1.0f / l1;
    const int qr = q0 + 16 * wid + (lane >> 2);
    const size_t ob = ((size_t)(b * SEQ + qr)) * EMB + h * DKH + 2 * (lane & 3);
    #pragma unroll
    for (int g = 0; g < 8; g++) {
        *(uint32_t*)(O + ob + 8 * g) = pack2h(o[g][0] * i0, o[g][1] * i0);
        *(uint32_t*)(O + ob + 8 * (size_t)EMB + 8 * g) = pack2h(o[g][2] * i1, o[g][3] * i1);
    }
}

// ---------------------------------------------------------------------------
extern "C" void kernel_launch(void* const* d_in, const int* in_sizes, int n_in,
                              void* d_out, int out_size)
{
    (void)in_sizes; (void)n_in; (void)out_size;
    const float*         query  = (const float*)d_in[0];
    const float*         key    = (const float*)d_in[1];
    const float*         value  = (const float*)d_in[2];
    const unsigned char* masked = (const unsigned char*)d_in[3];
    const float*         Wq     = (const float*)d_in[4];
    const float*         Wk     = (const float*)d_in[5];
    const float*         Wv     = (const float*)d_in[6];
    const float*         Wo     = (const float*)d_in[7];
    float*               out    = (float*)d_out;

    __half *gqh, *gkh, *gvh, *goh, *gxh, *gxl, *gwth;
    unsigned char *gm8;
    cudaGetSymbolAddress((void**)&gqh,  g_qh);
    cudaGetSymbolAddress((void**)&gkh,  g_kh);
    cudaGetSymbolAddress((void**)&gvh,  g_vh);
    cudaGetSymbolAddress((void**)&goh,  g_oh);
    cudaGetSymbolAddress((void**)&gxh,  g_xh);
    cudaGetSymbolAddress((void**)&gxl,  g_xl);
    cudaGetSymbolAddress((void**)&gwth, g_wth);
    cudaGetSymbolAddress((void**)&gm8,  g_m8);

    const size_t XN = (size_t)MROWS * EMB;
    const size_t WN = (size_t)EMB * EMB;

    cudaFuncSetAttribute(mha_mma_gemm3,
                         cudaFuncAttributeMaxDynamicSharedMemorySize, GSM_TOTAL);
    cudaFuncSetAttribute(mha_mma_gemm_f32,
                         cudaFuncAttributeMaxDynamicSharedMemorySize, GSM_TOTAL);
    cudaFuncSetAttribute(mha_attn_mma,
                         cudaFuncAttributeMaxDynamicSharedMemorySize, ASM_TOTAL);

    const int n4 = MROWS * EMB / 4;

    mha_detect_mask_kernel<<<1, 256>>>(masked);

    WsplitArgs wa;
    wa.W[0] = Wq; wa.W[1] = Wk; wa.W[2] = Wv; wa.W[3] = Wo;
    for (int z = 0; z < 4; z++) wa.th[z] = gwth + z * WN;
    dim3 w_grid(EMB / 32, EMB / 32, 4), w_blk(32, 8);
    mha_wsplit4_kernel<<<w_grid, w_blk>>>(wa);

    SplitArgs sa;
    sa.x[0] = (const float4*)query; sa.x[1] = (const float4*)key; sa.x[2] = (const float4*)value;
    for (int z = 0; z < 3; z++) {
        sa.hi[z] = (uint32_t*)(gxh + z * XN);
        sa.lo[z] = (uint32_t*)(gxl + z * XN);
    }
    dim3 s_grid((n4 + 255) / 256, 1, 3);
    mha_split3_kernel<<<s_grid, 256>>>(sa, n4);

    const int mn4 = BATCH * SEQ * SEQ / 4;
    mha_mask8_kernel<<<(mn4 + 255) / 256, 256>>>(masked, gm8, mn4);

    Gemm3Args ga;
    for (int z = 0; z < 3; z++) {
        ga.Ah[z] = gxh + z * XN;  ga.Al[z] = gxl + z * XN;
        ga.B[z]  = gwth + z * WN;
    }
    ga.C[0] = gqh; ga.C[1] = gkh; ga.C[2] = gvh;
    dim3 g3(EMB / 256, MROWS / 128, 3);      // (4, 32, 3)
    mha_mma_gemm3<<<g3, 256, GSM_TOTAL>>>(ga);

    dim3 attn_grid(SEQ / BR, BATCH * HEADS);  // (16, 32)
    mha_attn_mma<<<attn_grid, 256, ASM_TOTAL>>>(gqh, gkh, gvh, gm8, goh);

    dim3 g1(EMB / 256, MROWS / 128);          // (4, 32)
    mha_mma_gemm_f32<<<g1, 256, GSM_TOTAL>>>(goh, gwth + 3 * WN, out);
}

// round 13
// speedup vs baseline: 5.6347x; 1.1951x over previous
#include <cuda_runtime.h>
#include <cuda_fp16.h>
#include <cstdint>

#define BATCH 2
#define SEQ   2048
#define EMB   1024
#define HEADS 16
#define DKH   64
#define NEGV  (-1.0e9f)
#define SCALE 0.125f
#define MROWS (BATCH*SEQ)     // 4096

// ---------------------------------------------------------------------------
// Scratch — __device__ globals per allocation rules. All-fp16 scheme:
// inputs, weights, Q/K/V, P, attention output all single fp16 (fp32 accum).
// ---------------------------------------------------------------------------
__device__ __half g_qh [MROWS*EMB];
__device__ __half g_kh [MROWS*EMB];
__device__ __half g_vh [MROWS*EMB];
__device__ __half g_xh [3][MROWS*EMB];
__device__ __half g_oh [MROWS*EMB];
__device__ __half g_wth[4][EMB*EMB];
__device__ unsigned char g_m8 [BATCH*SEQ*SEQ];
__device__ int   g_mask_is_i32;

// ---------------------------------------------------------------------------
// PTX helpers
// ---------------------------------------------------------------------------
__device__ __forceinline__ uint32_t smem_u32(const void* p) {
    uint32_t a;
    asm("{ .reg .u64 t; cvta.to.shared.u64 t, %1; cvt.u32.u64 %0, t; }"
        : "=r"(a) : "l"(p));
    return a;
}

#define LDSM4(r, addr) \
    asm volatile("ldmatrix.sync.aligned.m8n8.x4.shared.b16 {%0,%1,%2,%3}, [%4];" \
        : "=r"((r)[0]), "=r"((r)[1]), "=r"((r)[2]), "=r"((r)[3]) : "r"(addr))
#define LDSM4T(r, addr) \
    asm volatile("ldmatrix.sync.aligned.m8n8.x4.trans.shared.b16 {%0,%1,%2,%3}, [%4];" \
        : "=r"((r)[0]), "=r"((r)[1]), "=r"((r)[2]), "=r"((r)[3]) : "r"(addr))

#define MMA_F16(d, a, b) \
    asm volatile("mma.sync.aligned.m16n8k16.row.col.f32.f16.f16.f32 " \
        "{%0,%1,%2,%3}, {%4,%5,%6,%7}, {%8,%9}, {%0,%1,%2,%3};" \
        : "+f"((d)[0]), "+f"((d)[1]), "+f"((d)[2]), "+f"((d)[3]) \
        : "r"((a)[0]), "r"((a)[1]), "r"((a)[2]), "r"((a)[3]), \
          "r"((b)[0]), "r"((b)[1]))

#define CP_ASYNC16(sa, gp) \
    asm volatile("{\n\t.reg .u64 gpt;\n\tcvta.to.global.u64 gpt, %1;\n\t" \
        "cp.async.cg.shared.global [%0], [gpt], 16;\n\t}" \
        :: "r"(sa), "l"(gp))
#define CP_COMMIT()  asm volatile("cp.async.commit_group;" ::: "memory")
#define CP_WAIT0()   asm volatile("cp.async.wait_group 0;" ::: "memory")
#define CP_WAIT1()   asm volatile("cp.async.wait_group 1;" ::: "memory")
#define CP_WAIT2()   asm volatile("cp.async.wait_group 2;" ::: "memory")

__device__ __forceinline__ uint32_t pack2h(float x, float y)
{
    __half2 H = __halves2half2(__float2half_rn(x), __float2half_rn(y));
    return *reinterpret_cast<uint32_t*>(&H);
}

// ---------------------------------------------------------------------------
// Prep kernels
// ---------------------------------------------------------------------------
__global__ void mha_detect_mask_kernel(const unsigned char* __restrict__ m)
{
    int s = 0;
    for (int i = threadIdx.x; i < 4096; i += 256)
        if ((i & 3) != 0) s |= m[i];
    int any = __syncthreads_or(s);
    if (threadIdx.x == 0)
        g_mask_is_i32 = (any == 0) ? 1 : 0;
}

__global__ __launch_bounds__(256)
void mha_mask8_kernel(const unsigned char* __restrict__ m,
                      unsigned char* __restrict__ o, int n4)
{
    int i = blockIdx.x * 256 + threadIdx.x;
    if (i >= n4) return;
    if (g_mask_is_i32) {
        int4 w = ((const int4*)m)[i];
        uchar4 u;
        u.x = (unsigned char)w.x; u.y = (unsigned char)w.y;
        u.z = (unsigned char)w.z; u.w = (unsigned char)w.w;
        ((uchar4*)o)[i] = u;
    } else {
        ((uchar4*)o)[i] = ((const uchar4*)m)[i];
    }
}

// fp32 -> fp16 convert, 3 tensors in one launch
struct ConvArgs {
    const float4* x[3];
    uint32_t* h[3];
};

__global__ __launch_bounds__(256)
void mha_conv3_kernel(ConvArgs p, int n4)
{
    int i = blockIdx.x * 256 + threadIdx.x;
    if (i >= n4) return;
    const int z = blockIdx.z;
    float4 v = p.x[z][i];
    p.h[z][2 * i + 0] = pack2h(v.x, v.y);
    p.h[z][2 * i + 1] = pack2h(v.z, v.w);
}

struct WsplitArgs {
    const float* W[4];
    __half* th[4];
};

__global__ __launch_bounds__(256)
void mha_wsplit4_kernel(WsplitArgs p)
{
    __shared__ float t[32][33];
    const int z  = blockIdx.z;
    const float* W = p.W[z];
    const int n  = blockIdx.x * 32 + threadIdx.x;
    const int k0 = blockIdx.y * 32;
    #pragma unroll
    for (int r = 0; r < 32; r += 8)
        t[threadIdx.y + r][threadIdx.x] = W[(size_t)(k0 + threadIdx.y + r) * EMB + n];
    __syncthreads();
    #pragma unroll
    for (int r = 0; r < 32; r += 8) {
        float v = t[threadIdx.x][threadIdx.y + r];
        int on = blockIdx.x * 32 + threadIdx.y + r;
        int ok = k0 + threadIdx.x;
        p.th[z][(size_t)on * EMB + ok] = __float2half_rn(v);
    }
}

// ---------------------------------------------------------------------------
// Plain fp16 GEMM: CTA 128x256, warp tile 64x64, KC=32, 3-stage cp.async.
// Stage: A(8K) B(16K) = 24KB; 3 stages = 72KB.
// ---------------------------------------------------------------------------
#define KC        32
#define A_TSB     8192
#define B_TSB     16384
#define STAGE_SB  (A_TSB + B_TSB)       // 24576
#define GSM_TOTAL (3 * STAGE_SB)        // 73728

#define GSWZ(r, ch) ((uint32_t)((r) * 64 + ((((ch) ^ (((r) >> 1) & 3))) << 4)))

__device__ __forceinline__ void cp_tile_a(const __half* __restrict__ g,
                                          int row0, int kb, uint32_t sdst, int tid)
{
    #pragma unroll
    for (int p = 0; p < 2; p++) {
        int f = tid + p * 256;
        int r = f >> 2, ch = f & 3;
        const __half* gp = g + (size_t)(row0 + r) * EMB + kb + ch * 8;
        CP_ASYNC16(sdst + GSWZ(r, ch), gp);
    }
}

__device__ __forceinline__ void cp_tile_b(const __half* __restrict__ g,
                                          int row0, int kb, uint32_t sdst, int tid)
{
    #pragma unroll
    for (int p = 0; p < 4; p++) {
        int f = tid + p * 256;
        int r = f >> 2, ch = f & 3;
        const __half* gp = g + (size_t)(row0 + r) * EMB + kb + ch * 8;
        CP_ASYNC16(sdst + GSWZ(r, ch), gp);
    }
}

__device__ __forceinline__ void gemm_stage_load(const __half* A, const __half* B,
                                                int m0, int n0, int kb,
                                                uint32_t buf, int tid)
{
    cp_tile_a(A, m0, kb, buf, tid);
    cp_tile_b(B, n0, kb, buf + A_TSB, tid);
    CP_COMMIT();
}

__device__ __forceinline__ void gemm_main(const __half* A, const __half* B,
                                          uint32_t sb, int m0, int n0,
                                          int tid, int lane, int wm, int wn,
                                          float acc[4][8][4])
{
    const int NS = EMB / KC;           // 32
    gemm_stage_load(A, B, m0, n0, 0, sb, tid);
    gemm_stage_load(A, B, m0, n0, KC, sb + STAGE_SB, tid);

    for (int s = 0; s < NS; s++) {
        if (s + 2 < NS)
            gemm_stage_load(A, B, m0, n0, (s + 2) * KC,
                            sb + ((s + 2) % 3) * STAGE_SB, tid);
        if (s + 2 < NS)      CP_WAIT2();
        else if (s + 1 < NS) CP_WAIT1();
        else                 CP_WAIT0();
        __syncthreads();

        const uint32_t abase = sb + (s % 3) * STAGE_SB;
        const uint32_t bbase = abase + A_TSB;

        #pragma unroll
        for (int ks = 0; ks < 2; ks++) {
            uint32_t ah[4][4];
            {
                const int ch = ks * 2 + (lane >> 4);
                #pragma unroll
                for (int mt = 0; mt < 4; mt++) {
                    const int row = wm * 64 + mt * 16 + (lane & 15);
                    LDSM4(ah[mt], abase + GSWZ(row, ch));
                }
            }
            #pragma unroll
            for (int ntp = 0; ntp < 4; ntp++) {
                const int row = wn * 64 + ntp * 16 + (lane & 7) + ((lane >> 4) << 3);
                const int ch  = ks * 2 + ((lane >> 3) & 1);
                uint32_t tb[4];
                LDSM4(tb, bbase + GSWZ(row, ch));
                const int n0t = 2 * ntp, n1t = 2 * ntp + 1;
                #pragma unroll
                for (int mt = 0; mt < 4; mt++) {
                    MMA_F16(acc[mt][n0t], ah[mt], tb);
                    MMA_F16(acc[mt][n1t], ah[mt], tb + 2);
                }
            }
        }
        __syncthreads();
    }
}

// merged Q/K/V projections: plain fp16 GEMM, fp16 output
struct Gemm3Args {
    const __half *A[3], *B[3];
    __half *C[3];
};

__global__ __launch_bounds__(256, 1)
void mha_mma_gemm3(Gemm3Args p)
{
    extern __shared__ char smem[];
    const uint32_t sb = smem_u32(smem);
    const int tid  = threadIdx.x;
    const int wid  = tid >> 5;
    const int lane = tid & 31;
    const int wm   = wid & 1;
    const int wn   = wid >> 1;
    const int m0   = blockIdx.y * 128;
    const int n0   = blockIdx.x * 256;
    const int z    = blockIdx.z;

    float acc[4][8][4];
    #pragma unroll
    for (int mt = 0; mt < 4; mt++)
        #pragma unroll
        for (int nt = 0; nt < 8; nt++)
            #pragma unroll
            for (int e = 0; e < 4; e++) acc[mt][nt][e] = 0.0f;

    gemm_main(p.A[z], p.B[z], sb, m0, n0, tid, lane, wm, wn, acc);

    __half* C = p.C[z];
    #pragma unroll
    for (int mt = 0; mt < 4; mt++) {
        const int r0 = m0 + wm * 64 + mt * 16 + (lane >> 2);
        #pragma unroll
        for (int nt = 0; nt < 8; nt++) {
            const int c0 = n0 + wn * 64 + nt * 8 + 2 * (lane & 3);
            *(uint32_t*)(C + (size_t)r0 * EMB + c0) =
                pack2h(acc[mt][nt][0], acc[mt][nt][1]);
            *(uint32_t*)(C + (size_t)(r0 + 8) * EMB + c0) =
                pack2h(acc[mt][nt][2], acc[mt][nt][3]);
        }
    }
}

// Wo projection: plain fp16 GEMM, fp32 output
__global__ __launch_bounds__(256, 1)
void mha_mma_gemm_f32(const __half* __restrict__ A,
                      const __half* __restrict__ B,
                      float* __restrict__ C)
{
    extern __shared__ char smem[];
    const uint32_t sb = smem_u32(smem);
    const int tid  = threadIdx.x;
    const int wid  = tid >> 5;
    const int lane = tid & 31;
    const int wm   = wid & 1;
    const int wn   = wid >> 1;
    const int m0   = blockIdx.y * 128;
    const int n0   = blockIdx.x * 256;

    float acc[4][8][4];
    #pragma unroll
    for (int mt = 0; mt < 4; mt++)
        #pragma unroll
        for (int nt = 0; nt < 8; nt++)
            #pragma unroll
            for (int e = 0; e < 4; e++) acc[mt][nt][e] = 0.0f;

    gemm_main(A, B, sb, m0, n0, tid, lane, wm, wn, acc);

    #pragma unroll
    for (int mt = 0; mt < 4; mt++) {
        const int r0 = m0 + wm * 64 + mt * 16 + (lane >> 2);
        #pragma unroll
        for (int nt = 0; nt < 8; nt++) {
            const int c0 = n0 + wn * 64 + nt * 8 + 2 * (lane & 3);
            *(float2*)(C + (size_t)r0 * EMB + c0)       = make_float2(acc[mt][nt][0], acc[mt][nt][1]);
            *(float2*)(C + (size_t)(r0 + 8) * EMB + c0) = make_float2(acc[mt][nt][2], acc[mt][nt][3]);
        }
    }
}

// ---------------------------------------------------------------------------
// Flash attention, single-fp16 Q/K/V/P.
// BR=128, BC=64, 2 CTAs/SM. smem: Q 16KB + 2 stages x (K 8K + V 8K) = 48KB.
// ---------------------------------------------------------------------------
#define BR  128
#define BC  64
#define NKT (SEQ / BC)        // 32
#define AQH 0
#define AST 16384
#define KVT 8192
#define ASTAGE (2 * KVT)      // 16384
#define ASM_TOTAL (AST + 2 * ASTAGE)   // 49152

__device__ __forceinline__ void att_cp_q(const __half* __restrict__ g,
                                         uint32_t sbase, int tid)
{
    #pragma unroll
    for (int p = 0; p < 4; p++) {
        int f = tid + p * 256;
        int r = f >> 3, ch = f & 7;
        const __half* gp = g + (size_t)r * EMB + ch * 8;
        uint32_t sa = sbase + r * 128 + ((ch ^ (r & 7)) << 4);
        CP_ASYNC16(sa, gp);
    }
}

__device__ __forceinline__ void att_cp_kv(const __half* __restrict__ g,
                                          uint32_t sbase, int tid)
{
    #pragma unroll
    for (int p = 0; p < 2; p++) {
        int f = tid + p * 256;
        int r = f >> 3, ch = f & 7;
        const __half* gp = g + (size_t)r * EMB + ch * 8;
        uint32_t sa = sbase + r * 128 + ((ch ^ (r & 7)) << 4);
        CP_ASYNC16(sa, gp);
    }
}

__global__ __launch_bounds__(256, 2)
void mha_attn_mma(const __half* __restrict__ Q,
                  const __half* __restrict__ K,  const __half* __restrict__ V,
                  const unsigned char* __restrict__ mask8,
                  __half* __restrict__ O)
{
    extern __shared__ char smem[];
    const uint32_t sb = smem_u32(smem);
    const int tid = threadIdx.x, wid = tid >> 5, lane = tid & 31;
    const int q0 = blockIdx.x * BR;
    const int b  = blockIdx.y >> 4, h = blockIdx.y & 15;

    const size_t qoff   = ((size_t)(b * SEQ + q0)) * EMB + h * DKH;
    const size_t kvbase = ((size_t)b * SEQ) * EMB + h * DKH;

    att_cp_q(Q + qoff, sb + AQH, tid);
    att_cp_kv(K + kvbase, sb + AST + 0 * KVT, tid);
    att_cp_kv(V + kvbase, sb + AST + 1 * KVT, tid);
    CP_COMMIT();
    CP_WAIT0();
    __syncthreads();

    uint32_t qf[4][4];
    {
        const int qrow = 16 * wid + (lane & 15);
        const uint32_t qb = sb + AQH + qrow * 128;
        const int q7 = qrow & 7;
        #pragma unroll
        for (int kc = 0; kc < 4; kc++) {
            const int ch = 2 * kc + (lane >> 4);
            LDSM4(qf[kc], qb + ((ch ^ q7) << 4));
        }
    }

    const int sx    = lane & 7;
    const int krow  = (lane & 7) + ((lane & 16) ? 8 : 0);
    const int kchh  = (lane >> 3) & 1;
    const int vrowb = (lane & 7) + ((lane & 8) ? 8 : 0);
    const int vchh  = (lane & 16) ? 1 : 0;

    float o[8][4];
    float s[8][4];
    #pragma unroll
    for (int g = 0; g < 8; g++)
        #pragma unroll
        for (int e = 0; e < 4; e++) o[g][e] = 0.0f;
    float m0 = __int_as_float(0xff800000);
    float m1 = __int_as_float(0xff800000);
    float l0 = 0.0f, l1 = 0.0f;

    const unsigned char* mb0 = mask8 +
        ((size_t)(b * SEQ + q0 + 16 * wid + (lane >> 2))) * SEQ + 2 * (lane & 3);
    const unsigned char* mb1 = mb0 + 8 * SEQ;

    for (int kt = 0; kt < NKT; kt++) {
        if (kt + 1 < NKT) {
            const size_t kv = kvbase + (size_t)(kt + 1) * BC * EMB;
            const uint32_t nb = sb + AST + ((kt + 1) & 1) * ASTAGE;
            att_cp_kv(K + kv, nb + 0 * KVT, tid);
            att_cp_kv(V + kv, nb + 1 * KVT, tid);
            CP_COMMIT();
            CP_WAIT1();
        } else {
            CP_WAIT0();
        }
        __syncthreads();

        const uint32_t bK = sb + AST + (kt & 1) * ASTAGE;
        const uint32_t bV = bK + KVT;

        #pragma unroll
        for (int g = 0; g < 8; g++)
            #pragma unroll
            for (int e = 0; e < 4; e++) s[g][e] = 0.0f;

        #pragma unroll
        for (int kc = 0; kc < 4; kc++) {
            #pragma unroll
            for (int jp = 0; jp < 2; jp++) {
                uint32_t kf0[4], kf1[4];
                const int ch = 2 * kc + kchh;
                const uint32_t pc = (uint32_t)((ch ^ sx) << 4);
                const uint32_t o0 = (uint32_t)((32 * jp + krow) * 128) + pc;
                const uint32_t o1 = o0 + 16 * 128;
                LDSM4(kf0, bK + o0);
                LDSM4(kf1, bK + o1);
                MMA_F16(s[4*jp+0], qf[kc], kf0);
                MMA_F16(s[4*jp+1], qf[kc], kf0 + 2);
                MMA_F16(s[4*jp+2], qf[kc], kf1);
                MMA_F16(s[4*jp+3], qf[kc], kf1 + 2);
            }
        }

        const unsigned char* mr0 = mb0 + (size_t)kt * BC;
        const unsigned char* mr1 = mb1 + (size_t)kt * BC;
        #pragma unroll
        for (int g = 0; g < 8; g++) {
            uchar2 u0 = *(const uchar2*)(mr0 + 8 * g);
            uchar2 u1 = *(const uchar2*)(mr1 + 8 * g);
            s[g][0] = u0.x ? NEGV : s[g][0] * SCALE;
            s[g][1] = u0.y ? NEGV : s[g][1] * SCALE;
            s[g][2] = u1.x ? NEGV : s[g][2] * SCALE;
            s[g][3] = u1.y ? NEGV : s[g][3] * SCALE;
        }

        float mx0 = NEGV * 2.0f, mx1 = NEGV * 2.0f;
        #pragma unroll
        for (int g = 0; g < 8; g++) {
            mx0 = fmaxf(mx0, fmaxf(s[g][0], s[g][1]));
            mx1 = fmaxf(mx1, fmaxf(s[g][2], s[g][3]));
        }
        mx0 = fmaxf(mx0, __shfl_xor_sync(0xffffffffu, mx0, 1));
        mx0 = fmaxf(mx0, __shfl_xor_sync(0xffffffffu, mx0, 2));
        mx1 = fmaxf(mx1, __shfl_xor_sync(0xffffffffu, mx1, 1));
        mx1 = fmaxf(mx1, __shfl_xor_sync(0xffffffffu, mx1, 2));
        const float mn0 = fmaxf(m0, mx0), mn1 = fmaxf(m1, mx1);
        const float a0 = __expf(m0 - mn0), a1 = __expf(m1 - mn1);
        float sum0 = 0.0f, sum1 = 0.0f;
        #pragma unroll
        for (int g = 0; g < 8; g++) {
            s[g][0] = __expf(s[g][0] - mn0);
            s[g][1] = __expf(s[g][1] - mn0);
            s[g][2] = __expf(s[g][2] - mn1);
            s[g][3] = __expf(s[g][3] - mn1);
            sum0 += s[g][0] + s[g][1];
            sum1 += s[g][2] + s[g][3];
        }
        sum0 += __shfl_xor_sync(0xffffffffu, sum0, 1);
        sum0 += __shfl_xor_sync(0xffffffffu, sum0, 2);
        sum1 += __shfl_xor_sync(0xffffffffu, sum1, 1);
        sum1 += __shfl_xor_sync(0xffffffffu, sum1, 2);
        l0 = l0 * a0 + sum0;  m0 = mn0;
        l1 = l1 * a1 + sum1;  m1 = mn1;
        #pragma unroll
        for (int g = 0; g < 8; g++) {
            o[g][0] *= a0; o[g][1] *= a0;
            o[g][2] *= a1; o[g][3] *= a1;
        }

        #pragma unroll
        for (int c = 0; c < 4; c++) {
            uint32_t pa[4];
            pa[0] = pack2h(s[2*c][0],   s[2*c][1]);
            pa[1] = pack2h(s[2*c][2],   s[2*c][3]);
            pa[2] = pack2h(s[2*c+1][0], s[2*c+1][1]);
            pa[3] = pack2h(s[2*c+1][2], s[2*c+1][3]);

            uint32_t vf[4][4];
            const uint32_t rbase = (uint32_t)((16 * c + vrowb) * 128);
            #pragma unroll
            for (int jd = 0; jd < 4; jd++) {
                const int ch = 2 * jd + vchh;
                LDSM4T(vf[jd], bV + rbase + ((ch ^ sx) << 4));
            }
            #pragma unroll
            for (int jd = 0; jd < 4; jd++) {
                MMA_F16(o[2*jd],   pa, vf[jd]);
                MMA_F16(o[2*jd+1], pa, vf[jd] + 2);
            }
        }

        __syncthreads();
    }

    const float i0 = 1.0f / l0, i1 = 1.0f / l1;
    const int qr = q0 + 16 * wid + (lane >> 2);
    const size_t ob = ((size_t)(b * SEQ + qr)) * EMB + h * DKH + 2 * (lane & 3);
    #pragma unroll
    for (int g = 0; g < 8; g++) {
        *(uint32_t*)(O + ob + 8 * g) = pack2h(o[g][0] * i0, o[g][1] * i0);
        *(uint32_t*)(O + ob + 8 * (size_t)EMB + 8 * g) = pack2h(o[g][2] * i1, o[g][3] * i1);
    }
}

// ---------------------------------------------------------------------------
extern "C" void kernel_launch(void* const* d_in, const int* in_sizes, int n_in,
                              void* d_out, int out_size)
{
    (void)in_sizes; (void)n_in; (void)out_size;
    const float*         query  = (const float*)d_in[0];
    const float*         key    = (const float*)d_in[1];
    const float*         value  = (const float*)d_in[2];
    const unsigned char* masked = (const unsigned char*)d_in[3];
    const float*         Wq     = (const float*)d_in[4];
    const float*         Wk     = (const float*)d_in[5];
    const float*         Wv     = (const float*)d_in[6];
    const float*         Wo     = (const float*)d_in[7];
    float*               out    = (float*)d_out;

    __half *gqh, *gkh, *gvh, *goh, *gxh, *gwth;
    unsigned char *gm8;
    cudaGetSymbolAddress((void**)&gqh,  g_qh);
    cudaGetSymbolAddress((void**)&gkh,  g_kh);
    cudaGetSymbolAddress((void**)&gvh,  g_vh);
    cudaGetSymbolAddress((void**)&goh,  g_oh);
    cudaGetSymbolAddress((void**)&gxh,  g_xh);
    cudaGetSymbolAddress((void**)&gwth, g_wth);
    cudaGetSymbolAddress((void**)&gm8,  g_m8);

    const size_t XN = (size_t)MROWS * EMB;
    const size_t WN = (size_t)EMB * EMB;

    cudaFuncSetAttribute(mha_mma_gemm3,
                         cudaFuncAttributeMaxDynamicSharedMemorySize, GSM_TOTAL);
    cudaFuncSetAttribute(mha_mma_gemm_f32,
                         cudaFuncAttributeMaxDynamicSharedMemorySize, GSM_TOTAL);
    cudaFuncSetAttribute(mha_attn_mma,
                         cudaFuncAttributeMaxDynamicSharedMemorySize, ASM_TOTAL);

    const int n4 = MROWS * EMB / 4;

    mha_detect_mask_kernel<<<1, 256>>>(masked);

    WsplitArgs wa;
    wa.W[0] = Wq; wa.W[1] = Wk; wa.W[2] = Wv; wa.W[3] = Wo;
    for (int z = 0; z < 4; z++) wa.th[z] = gwth + z * WN;
    dim3 w_grid(EMB / 32, EMB / 32, 4), w_blk(32, 8);
    mha_wsplit4_kernel<<<w_grid, w_blk>>>(wa);

    ConvArgs ca;
    ca.x[0] = (const float4*)query; ca.x[1] = (const float4*)key; ca.x[2] = (const float4*)value;
    for (int z = 0; z < 3; z++) ca.h[z] = (uint32_t*)(gxh + z * XN);
    dim3 c_grid((n4 + 255) / 256, 1, 3);
    mha_conv3_kernel<<<c_grid, 256>>>(ca, n4);

    const int mn4 = BATCH * SEQ * SEQ / 4;
    mha_mask8_kernel<<<(mn4 + 255) / 256, 256>>>(masked, gm8, mn4);

    Gemm3Args ga;
    for (int z = 0; z < 3; z++) {
        ga.A[z] = gxh + z * XN;
        ga.B[z] = gwth + z * WN;
    }
    ga.C[0] = gqh; ga.C[1] = gkh; ga.C[2] = gvh;
    dim3 g3(EMB / 256, MROWS / 128, 3);      // (4, 32, 3)
    mha_mma_gemm3<<<g3, 256, GSM_TOTAL>>>(ga);

    dim3 attn_grid(SEQ / BR, BATCH * HEADS);  // (16, 32)
    mha_attn_mma<<<attn_grid, 256, ASM_TOTAL>>>(gqh, gkh, gvh, gm8, goh);

    dim3 g1(EMB / 256, MROWS / 128);          // (4, 32)
    mha_mma_gemm_f32<<<g1, 256, GSM_TOTAL>>>(goh, gwth + 3 * WN, out);
}